// round 10
// baseline (speedup 1.0000x reference)
#include <cuda_runtime.h>
#include <math.h>

#define NN 50000
#define EE 400000
#define DMAX 256

// ---------------- scratch ----------------
__device__ float g_h[(size_t)NN * DMAX];
__device__ float g_x[(size_t)NN * DMAX];
__device__ float g_y[(size_t)NN * DMAX];
__device__ float g_s[NN * 4];
__device__ float g_d[NN * 4];
__device__ float g_rc[2 * 64];
__device__ int g_src[EE];
__device__ int g_dst[EE];
__device__ int g_ecol[EE];
__device__ int g_rowptr[NN + 1];
__device__ int g_deg[NN];
__device__ int g_cursor[NN];
__device__ int g_bsum[64];
__device__ int g_role[NN];
__device__ int g_is64;

// ---------------- helpers ----------------
__device__ __forceinline__ float warpSum(float v) {
    #pragma unroll
    for (int o = 16; o > 0; o >>= 1) v += __shfl_xor_sync(0xffffffffu, v, o);
    return v;
}
__device__ __forceinline__ int warpSumI(int v) {
    #pragma unroll
    for (int o = 16; o > 0; o >>= 1) v += __shfl_xor_sync(0xffffffffu, v, o);
    return v;
}
__device__ __forceinline__ int warpInclScan(int v, int lane) {
    #pragma unroll
    for (int o = 1; o < 32; o <<= 1) {
        int t = __shfl_up_sync(0xffffffffu, v, o);
        if (lane >= o) v += t;
    }
    return v;
}
__device__ __forceinline__ float leaky(float v) { return fmaxf(v, 0.2f * v); }
__device__ __forceinline__ float4 f4fma(float4 a, float s, float4 c) {
    c.x += a.x * s; c.y += a.y * s; c.z += a.z * s; c.w += a.w * s; return c;
}
__device__ __forceinline__ float4 f4scale(float4 a, float s) {
    return make_float4(a.x * s, a.y * s, a.z * s, a.w * s);
}
__device__ __forceinline__ float4 f4add(float4 a, float4 b) {
    return make_float4(a.x + b.x, a.y + b.y, a.z + b.z, a.w + b.w);
}

// ---------------- dtype detect + prep ----------------
__global__ void detect_kernel(const unsigned int* __restrict__ w, int* flag) {
    if (threadIdx.x == 0 && blockIdx.x == 0) {
        int is64 = 1;
        for (int i = 0; i < 64; i++)
            if (w[2 * i + 1] != 0u) { is64 = 0; break; }
        *flag = is64;
    }
}

__global__ void prep_kernel(const void* __restrict__ ei, const void* __restrict__ rid,
                            int* __restrict__ src, int* __restrict__ dst,
                            int* __restrict__ deg, int* __restrict__ role,
                            const int* __restrict__ flag, int E, int n) {
    int i = blockIdx.x * blockDim.x + threadIdx.x;
    int is64 = *flag;
    if (i < E) {
        int s, d;
        if (is64) {
            const long long* p = (const long long*)ei;
            s = (int)p[i];
            d = (int)p[(size_t)E + i];
        } else {
            const int* p = (const int*)ei;
            s = p[i];
            d = p[E + i];
        }
        src[i] = s;
        dst[i] = d;
        atomicAdd(&deg[d], 1);
    }
    if (i < n) {
        if (is64) role[i] = (int)((const long long*)rid)[i];
        else      role[i] = ((const int*)rid)[i];
    }
}

// ---------------- 2-phase scan ----------------
__global__ void scan_reduce_kernel(const int* __restrict__ deg, int* __restrict__ bsum, int n) {
    __shared__ int sw[32];
    int tid = threadIdx.x, lane = tid & 31, w = tid >> 5;
    int i = blockIdx.x * 1024 + tid;
    int v = (i < n) ? deg[i] : 0;
    v = warpSumI(v);
    if (lane == 0) sw[w] = v;
    __syncthreads();
    if (w == 0) {
        int t = sw[lane];
        t = warpSumI(t);
        if (lane == 0) bsum[blockIdx.x] = t;
    }
}

__global__ void scan_final_kernel(const int* __restrict__ deg, const int* __restrict__ bsum,
                                  int* __restrict__ rowptr, int* __restrict__ cursor, int n) {
    __shared__ int sw[32];
    __shared__ int partial[2];
    int tid = threadIdx.x, lane = tid & 31, w = tid >> 5;
    int bid = blockIdx.x;
    if (tid < 64) {
        int v = (tid < bid) ? bsum[tid] : 0;
        v = warpSumI(v);
        if ((tid & 31) == 0) partial[tid >> 5] = v;
    }
    int i = bid * 1024 + tid;
    int v = (i < n) ? deg[i] : 0;
    int iv = warpInclScan(v, lane);
    if (lane == 31) sw[w] = iv;
    __syncthreads();
    int base = partial[0] + partial[1];
    if (w == 0) {
        int t = sw[lane];
        t = warpInclScan(t, lane);
        sw[lane] = t;
    }
    __syncthreads();
    int offs = ((w > 0) ? sw[w - 1] : 0) + base;
    int incl = iv + offs;
    if (i < n) {
        rowptr[i + 1] = incl;
        cursor[i] = incl - v;
    }
    if (i == 0) rowptr[0] = 0;
}

__global__ void scatter_kernel(const int* __restrict__ src, const int* __restrict__ dst,
                               int* __restrict__ cursor, int* __restrict__ ecol, int E) {
    int i = blockIdx.x * blockDim.x + threadIdx.x;
    if (i >= E) return;
    int pos = atomicAdd(&cursor[dst[i]], 1);
    ecol[pos] = src[i];
}

// ---------------- role contribution precompute: rc[r][j] over K=64 tail of p1w -------
__global__ void role_prep_kernel(const float* __restrict__ rt, const float* __restrict__ p1w,
                                 const float* __restrict__ p1b, float* __restrict__ rc) {
    int tid = threadIdx.x;      // 128 threads
    int r = tid >> 6, j = tid & 63;
    float acc = p1b[j];
    #pragma unroll 8
    for (int k = 0; k < 64; k++)
        acc += rt[r * 64 + k] * p1w[j * 128 + 64 + k];
    rc[r * 64 + j] = acc;
}

// ---------------- pipelined GEMM 128x128 (8x8/thread), Nc=256, fused scores ----------
#define QBM 128
#define QBK 16
__global__ void __launch_bounds__(256, 2) gemm_nt128(
        const float* __restrict__ A, const float* __restrict__ B,
        float* __restrict__ C, int M, int Nc, int K,
        const float* __restrict__ as_, const float* __restrict__ ad_,
        float* __restrict__ s_, float* __restrict__ d_, int H) {
    __shared__ float As[2][QBK][QBM + 4];
    __shared__ float Bs[2][QBK][QBM + 4];
    int tid = threadIdx.x;
    int lane = tid & 31;
    int brow = blockIdx.y * QBM, bcol = blockIdx.x * 128;
    int tr = tid >> 4, tc = tid & 15;
    float acc[8][8];
    #pragma unroll
    for (int i = 0; i < 8; i++)
        #pragma unroll
        for (int j = 0; j < 8; j++) acc[i][j] = 0.f;

    int lrow[2], lkq[2];
    #pragma unroll
    for (int t = 0; t < 2; t++) { int li = tid + t * 256; lrow[t] = li >> 2; lkq[t] = (li & 3) * 4; }
    float4 aReg[2], bReg[2];
    const int nch = K / QBK;

    #pragma unroll
    for (int t = 0; t < 2; t++) {
        int gm = brow + lrow[t];
        aReg[t] = (gm < M) ? *(const float4*)&A[(size_t)gm * K + lkq[t]]
                           : make_float4(0.f, 0.f, 0.f, 0.f);
        int gn = bcol + lrow[t];
        bReg[t] = (gn < Nc) ? *(const float4*)&B[(size_t)gn * K + lkq[t]]
                            : make_float4(0.f, 0.f, 0.f, 0.f);
    }
    #pragma unroll
    for (int t = 0; t < 2; t++) {
        As[0][lkq[t] + 0][lrow[t]] = aReg[t].x; As[0][lkq[t] + 1][lrow[t]] = aReg[t].y;
        As[0][lkq[t] + 2][lrow[t]] = aReg[t].z; As[0][lkq[t] + 3][lrow[t]] = aReg[t].w;
        Bs[0][lkq[t] + 0][lrow[t]] = bReg[t].x; Bs[0][lkq[t] + 1][lrow[t]] = bReg[t].y;
        Bs[0][lkq[t] + 2][lrow[t]] = bReg[t].z; Bs[0][lkq[t] + 3][lrow[t]] = bReg[t].w;
    }
    __syncthreads();

    for (int c = 0; c < nch; c++) {
        int buf = c & 1;
        if (c + 1 < nch) {
            int k0 = (c + 1) * QBK;
            #pragma unroll
            for (int t = 0; t < 2; t++) {
                int gm = brow + lrow[t];
                aReg[t] = (gm < M) ? *(const float4*)&A[(size_t)gm * K + k0 + lkq[t]]
                                   : make_float4(0.f, 0.f, 0.f, 0.f);
                int gn = bcol + lrow[t];
                bReg[t] = (gn < Nc) ? *(const float4*)&B[(size_t)gn * K + k0 + lkq[t]]
                                    : make_float4(0.f, 0.f, 0.f, 0.f);
            }
        }
        #pragma unroll
        for (int kk = 0; kk < QBK; kk++) {
            float a[8], b[8];
            *(float4*)&a[0] = *(float4*)&As[buf][kk][tr * 8];
            *(float4*)&a[4] = *(float4*)&As[buf][kk][tr * 8 + 4];
            *(float4*)&b[0] = *(float4*)&Bs[buf][kk][tc * 4];
            *(float4*)&b[4] = *(float4*)&Bs[buf][kk][64 + tc * 4];
            #pragma unroll
            for (int i = 0; i < 8; i++)
                #pragma unroll
                for (int j = 0; j < 8; j++) acc[i][j] += a[i] * b[j];
        }
        if (c + 1 < nch) {
            int nb = buf ^ 1;
            #pragma unroll
            for (int t = 0; t < 2; t++) {
                As[nb][lkq[t] + 0][lrow[t]] = aReg[t].x; As[nb][lkq[t] + 1][lrow[t]] = aReg[t].y;
                As[nb][lkq[t] + 2][lrow[t]] = aReg[t].z; As[nb][lkq[t] + 3][lrow[t]] = aReg[t].w;
                Bs[nb][lkq[t] + 0][lrow[t]] = bReg[t].x; Bs[nb][lkq[t] + 1][lrow[t]] = bReg[t].y;
                Bs[nb][lkq[t] + 2][lrow[t]] = bReg[t].z; Bs[nb][lkq[t] + 3][lrow[t]] = bReg[t].w;
            }
        }
        __syncthreads();
    }

    #pragma unroll
    for (int i = 0; i < 8; i++) {
        int gm = brow + tr * 8 + i;
        if (gm >= M) continue;
        *(float4*)&C[(size_t)gm * Nc + bcol + tc * 4] =
            make_float4(acc[i][0], acc[i][1], acc[i][2], acc[i][3]);
        *(float4*)&C[(size_t)gm * Nc + bcol + 64 + tc * 4] =
            make_float4(acc[i][4], acc[i][5], acc[i][6], acc[i][7]);
    }

    int h0 = blockIdx.x * 2, h1 = h0 + 1;
    float as0[4], ad0[4], as1[4], ad1[4];
    #pragma unroll
    for (int j = 0; j < 4; j++) {
        as0[j] = as_[h0 * 64 + tc * 4 + j];
        ad0[j] = ad_[h0 * 64 + tc * 4 + j];
        as1[j] = as_[h1 * 64 + tc * 4 + j];
        ad1[j] = ad_[h1 * 64 + tc * 4 + j];
    }
    #pragma unroll
    for (int i = 0; i < 8; i++) {
        float s0 = 0.f, e0 = 0.f, s1 = 0.f, e1 = 0.f;
        #pragma unroll
        for (int j = 0; j < 4; j++) {
            s0 += acc[i][j] * as0[j];
            e0 += acc[i][j] * ad0[j];
            s1 += acc[i][4 + j] * as1[j];
            e1 += acc[i][4 + j] * ad1[j];
        }
        #pragma unroll
        for (int o = 8; o >= 1; o >>= 1) {
            s0 += __shfl_xor_sync(0xffffffffu, s0, o);
            e0 += __shfl_xor_sync(0xffffffffu, e0, o);
            s1 += __shfl_xor_sync(0xffffffffu, s1, o);
            e1 += __shfl_xor_sync(0xffffffffu, e1, o);
        }
        int gm = brow + tr * 8 + i;
        if ((lane & 15) == 0 && gm < M) {
            s_[(size_t)gm * H + h0] = s0;
            d_[(size_t)gm * H + h0] = e0;
            s_[(size_t)gm * H + h1] = s1;
            d_[(size_t)gm * H + h1] = e1;
        }
    }
}

// ---------------- pipelined GEMM 128x64 (8x8/thread, 128 threads), Nc=64, H=1 ---------
__global__ void __launch_bounds__(128) gemm_nt64(
        const float* __restrict__ A, const float* __restrict__ B,
        float* __restrict__ C, int M, int K,
        const float* __restrict__ as_, const float* __restrict__ ad_,
        float* __restrict__ s_, float* __restrict__ d_) {
    __shared__ float As[2][16][132];
    __shared__ float Bs[2][16][68];
    int tid = threadIdx.x;
    int lane = tid & 31;
    int brow = blockIdx.x * 128;
    int tr = tid >> 3, tc = tid & 7;
    float acc[8][8];
    #pragma unroll
    for (int i = 0; i < 8; i++)
        #pragma unroll
        for (int j = 0; j < 8; j++) acc[i][j] = 0.f;

    int lrowA[4], lkqA[4];
    #pragma unroll
    for (int t = 0; t < 4; t++) { int li = tid + t * 128; lrowA[t] = li >> 2; lkqA[t] = (li & 3) * 4; }
    int lrowB[2], lkqB[2];
    #pragma unroll
    for (int t = 0; t < 2; t++) { int li = tid + t * 128; lrowB[t] = li >> 2; lkqB[t] = (li & 3) * 4; }
    float4 aReg[4], bReg[2];
    const int nch = K / 16;

    #pragma unroll
    for (int t = 0; t < 4; t++) {
        int gm = brow + lrowA[t];
        aReg[t] = (gm < M) ? *(const float4*)&A[(size_t)gm * K + lkqA[t]]
                           : make_float4(0.f, 0.f, 0.f, 0.f);
    }
    #pragma unroll
    for (int t = 0; t < 2; t++)
        bReg[t] = *(const float4*)&B[(size_t)lrowB[t] * K + lkqB[t]];
    #pragma unroll
    for (int t = 0; t < 4; t++) {
        As[0][lkqA[t] + 0][lrowA[t]] = aReg[t].x; As[0][lkqA[t] + 1][lrowA[t]] = aReg[t].y;
        As[0][lkqA[t] + 2][lrowA[t]] = aReg[t].z; As[0][lkqA[t] + 3][lrowA[t]] = aReg[t].w;
    }
    #pragma unroll
    for (int t = 0; t < 2; t++) {
        Bs[0][lkqB[t] + 0][lrowB[t]] = bReg[t].x; Bs[0][lkqB[t] + 1][lrowB[t]] = bReg[t].y;
        Bs[0][lkqB[t] + 2][lrowB[t]] = bReg[t].z; Bs[0][lkqB[t] + 3][lrowB[t]] = bReg[t].w;
    }
    __syncthreads();

    for (int c = 0; c < nch; c++) {
        int buf = c & 1;
        if (c + 1 < nch) {
            int k0 = (c + 1) * 16;
            #pragma unroll
            for (int t = 0; t < 4; t++) {
                int gm = brow + lrowA[t];
                aReg[t] = (gm < M) ? *(const float4*)&A[(size_t)gm * K + k0 + lkqA[t]]
                                   : make_float4(0.f, 0.f, 0.f, 0.f);
            }
            #pragma unroll
            for (int t = 0; t < 2; t++)
                bReg[t] = *(const float4*)&B[(size_t)lrowB[t] * K + k0 + lkqB[t]];
        }
        #pragma unroll
        for (int kk = 0; kk < 16; kk++) {
            float a[8], b[8];
            *(float4*)&a[0] = *(float4*)&As[buf][kk][tr * 8];
            *(float4*)&a[4] = *(float4*)&As[buf][kk][tr * 8 + 4];
            *(float4*)&b[0] = *(float4*)&Bs[buf][kk][tc * 8];
            *(float4*)&b[4] = *(float4*)&Bs[buf][kk][tc * 8 + 4];
            #pragma unroll
            for (int i = 0; i < 8; i++)
                #pragma unroll
                for (int j = 0; j < 8; j++) acc[i][j] += a[i] * b[j];
        }
        if (c + 1 < nch) {
            int nb = buf ^ 1;
            #pragma unroll
            for (int t = 0; t < 4; t++) {
                As[nb][lkqA[t] + 0][lrowA[t]] = aReg[t].x; As[nb][lkqA[t] + 1][lrowA[t]] = aReg[t].y;
                As[nb][lkqA[t] + 2][lrowA[t]] = aReg[t].z; As[nb][lkqA[t] + 3][lrowA[t]] = aReg[t].w;
            }
            #pragma unroll
            for (int t = 0; t < 2; t++) {
                Bs[nb][lkqB[t] + 0][lrowB[t]] = bReg[t].x; Bs[nb][lkqB[t] + 1][lrowB[t]] = bReg[t].y;
                Bs[nb][lkqB[t] + 2][lrowB[t]] = bReg[t].z; Bs[nb][lkqB[t] + 3][lrowB[t]] = bReg[t].w;
            }
        }
        __syncthreads();
    }

    #pragma unroll
    for (int i = 0; i < 8; i++) {
        int gm = brow + tr * 8 + i;
        if (gm >= M) continue;
        *(float4*)&C[(size_t)gm * 64 + tc * 8] =
            make_float4(acc[i][0], acc[i][1], acc[i][2], acc[i][3]);
        *(float4*)&C[(size_t)gm * 64 + tc * 8 + 4] =
            make_float4(acc[i][4], acc[i][5], acc[i][6], acc[i][7]);
    }

    // fused score epilogue, H=1: thread covers cols tc*8..tc*8+7
    float asv[8], adv[8];
    #pragma unroll
    for (int j = 0; j < 8; j++) {
        asv[j] = as_[tc * 8 + j];
        adv[j] = ad_[tc * 8 + j];
    }
    #pragma unroll
    for (int i = 0; i < 8; i++) {
        float ss = 0.f, dd = 0.f;
        #pragma unroll
        for (int j = 0; j < 8; j++) {
            ss += acc[i][j] * asv[j];
            dd += acc[i][j] * adv[j];
        }
        #pragma unroll
        for (int o = 4; o >= 1; o >>= 1) {
            ss += __shfl_xor_sync(0xffffffffu, ss, o);
            dd += __shfl_xor_sync(0xffffffffu, dd, o);
        }
        int gm = brow + tr * 8 + i;
        if ((lane & 7) == 0 && gm < M) {
            s_[gm] = ss;
            d_[gm] = dd;
        }
    }
}

// ---------------- fused GAT layer, H=4: online softmax + prefetch-4 aggregate ---------
__global__ void gat_fused4(const int* __restrict__ rowptr, const int* __restrict__ ecol,
                           const float* __restrict__ s_, const float* __restrict__ d_,
                           const float* __restrict__ h, const float* __restrict__ bias,
                           const float* __restrict__ lw, const float* __restrict__ lb,
                           float* __restrict__ outp, int n, int do_elu) {
    int warp = (blockIdx.x * blockDim.x + threadIdx.x) >> 5;
    int lane = threadIdx.x & 31;
    if (warp >= n) return;
    int node = warp;
    int start = rowptr[node], end = rowptr[node + 1];

    float4 dv4 = ((const float4*)d_)[node];
    float dsel[4] = {dv4.x, dv4.y, dv4.z, dv4.w};
    float4 sv4 = ((const float4*)s_)[node];
    float selfv[4] = {leaky(sv4.x + dsel[0]), leaky(sv4.y + dsel[1]),
                      leaky(sv4.z + dsel[2]), leaky(sv4.w + dsel[3])};

    float m[4], s[4];
    #pragma unroll
    for (int q = 0; q < 4; q++) {
        m[q] = (lane == 0) ? selfv[q] : -3e38f;
        s[q] = (lane == 0) ? 1.f : 0.f;
    }
    for (int e = start + lane; e < end; e += 32) {
        int src = ecol[e];
        float4 sv = ((const float4*)s_)[src];
        float v[4] = {leaky(sv.x + dsel[0]), leaky(sv.y + dsel[1]),
                      leaky(sv.z + dsel[2]), leaky(sv.w + dsel[3])};
        #pragma unroll
        for (int q = 0; q < 4; q++) {
            float nm = fmaxf(m[q], v[q]);
            s[q] = s[q] * expf(m[q] - nm) + expf(v[q] - nm);
            m[q] = nm;
        }
    }
    #pragma unroll
    for (int o = 16; o > 0; o >>= 1) {
        #pragma unroll
        for (int q = 0; q < 4; q++) {
            float om = __shfl_xor_sync(0xffffffffu, m[q], o);
            float os = __shfl_xor_sync(0xffffffffu, s[q], o);
            float nm = fmaxf(m[q], om);
            s[q] = s[q] * expf(m[q] - nm) + os * expf(om - nm);
            m[q] = nm;
        }
    }
    float inv[4], aself[4];
    #pragma unroll
    for (int q = 0; q < 4; q++) {
        inv[q] = 1.f / (s[q] + 1e-16f);
        aself[q] = expf(selfv[q] - m[q]) * inv[q];
    }

    int hl = lane & 3;
    float d_hl = (hl == 0) ? dsel[0] : (hl == 1) ? dsel[1] : (hl == 2) ? dsel[2] : dsel[3];
    float m_hl = (hl == 0) ? m[0]    : (hl == 1) ? m[1]    : (hl == 2) ? m[2]    : m[3];
    float i_hl = (hl == 0) ? inv[0]  : (hl == 1) ? inv[1]  : (hl == 2) ? inv[2]  : inv[3];
    int hA = lane >> 4;
    float asA = hA ? aself[1] : aself[0];
    float asB = hA ? aself[3] : aself[2];

    const float4* hps4 = (const float4*)(h + (size_t)node * 256);
    float4 acc0 = f4scale(hps4[lane], asA);
    float4 acc1 = f4scale(hps4[lane + 32], asB);

    for (int e0 = start; e0 < end; e0 += 8) {
        int me = e0 + (lane >> 2);
        float alpha = 0.f; int msrc = 0;
        if (me < end) {
            msrc = ecol[me];
            float v = leaky(s_[(size_t)msrc * 4 + hl] + d_hl);
            alpha = expf(v - m_hl) * i_hl;
        }
        int cnt = end - e0; if (cnt > 8) cnt = 8;
        for (int j0 = 0; j0 < cnt; j0 += 4) {
            int jn = cnt - j0; if (jn > 4) jn = 4;
            float4 pa[4], pb[4];
            float a0[4], a1[4];
            #pragma unroll
            for (int j = 0; j < 4; j++) {
                int src = __shfl_sync(0xffffffffu, msrc, (j0 + j) * 4);
                a0[j] = __shfl_sync(0xffffffffu, alpha, (j0 + j) * 4 + hA);
                a1[j] = __shfl_sync(0xffffffffu, alpha, (j0 + j) * 4 + 2 + hA);
                if (j < jn) {
                    const float4* hp4 = (const float4*)(h + (size_t)src * 256);
                    pa[j] = hp4[lane];
                    pb[j] = hp4[lane + 32];
                }
            }
            #pragma unroll
            for (int j = 0; j < 4; j++) {
                if (j < jn) {
                    acc0 = f4fma(pa[j], a0[j], acc0);
                    acc1 = f4fma(pb[j], a1[j], acc1);
                }
            }
        }
    }

    const float4* b4 = (const float4*)bias;
    const float4* lw4 = (const float4*)lw;
    const float4* lb4 = (const float4*)lb;
    float4 v0 = f4add(acc0, b4[lane]);
    float4 v1 = f4add(acc1, b4[lane + 32]);
    if (do_elu) {
        v0.x = v0.x > 0.f ? v0.x : expf(v0.x) - 1.f;
        v0.y = v0.y > 0.f ? v0.y : expf(v0.y) - 1.f;
        v0.z = v0.z > 0.f ? v0.z : expf(v0.z) - 1.f;
        v0.w = v0.w > 0.f ? v0.w : expf(v0.w) - 1.f;
        v1.x = v1.x > 0.f ? v1.x : expf(v1.x) - 1.f;
        v1.y = v1.y > 0.f ? v1.y : expf(v1.y) - 1.f;
        v1.z = v1.z > 0.f ? v1.z : expf(v1.z) - 1.f;
        v1.w = v1.w > 0.f ? v1.w : expf(v1.w) - 1.f;
    }
    float ssum = v0.x + v0.y + v0.z + v0.w + v1.x + v1.y + v1.z + v1.w;
    ssum = warpSum(ssum);
    float mu = ssum * (1.f / 256.f);
    float t, vs = 0.f;
    t = v0.x - mu; vs += t * t; t = v0.y - mu; vs += t * t;
    t = v0.z - mu; vs += t * t; t = v0.w - mu; vs += t * t;
    t = v1.x - mu; vs += t * t; t = v1.y - mu; vs += t * t;
    t = v1.z - mu; vs += t * t; t = v1.w - mu; vs += t * t;
    vs = warpSum(vs);
    float rs = rsqrtf(vs * (1.f / 256.f) + 1e-5f);
    float4 w0 = lw4[lane], w1 = lw4[lane + 32];
    float4 c0 = lb4[lane], c1 = lb4[lane + 32];
    float4* out4 = (float4*)(outp + (size_t)node * 256);
    out4[lane] = make_float4((v0.x - mu) * rs * w0.x + c0.x, (v0.y - mu) * rs * w0.y + c0.y,
                             (v0.z - mu) * rs * w0.z + c0.z, (v0.w - mu) * rs * w0.w + c0.w);
    out4[lane + 32] = make_float4((v1.x - mu) * rs * w1.x + c1.x, (v1.y - mu) * rs * w1.y + c1.y,
                                  (v1.z - mu) * rs * w1.z + c1.z, (v1.w - mu) * rs * w1.w + c1.w);
}

// ---------------- fused GAT layer, H=1 (D=64) ----------
__global__ void gat_fused1(const int* __restrict__ rowptr, const int* __restrict__ ecol,
                           const float* __restrict__ s_, const float* __restrict__ d_,
                           const float* __restrict__ h, const float* __restrict__ bias,
                           const float* __restrict__ lw, const float* __restrict__ lb,
                           float* __restrict__ outp, int n, int do_elu) {
    int warp = (blockIdx.x * blockDim.x + threadIdx.x) >> 5;
    int lane = threadIdx.x & 31;
    if (warp >= n) return;
    int node = warp;
    int start = rowptr[node], end = rowptr[node + 1];

    float dsel = d_[node];
    float selfv = leaky(s_[node] + dsel);
    float m = (lane == 0) ? selfv : -3e38f;
    float s = (lane == 0) ? 1.f : 0.f;
    for (int e = start + lane; e < end; e += 32) {
        float v = leaky(s_[ecol[e]] + dsel);
        float nm = fmaxf(m, v);
        s = s * expf(m - nm) + expf(v - nm);
        m = nm;
    }
    #pragma unroll
    for (int o = 16; o > 0; o >>= 1) {
        float om = __shfl_xor_sync(0xffffffffu, m, o);
        float os = __shfl_xor_sync(0xffffffffu, s, o);
        float nm = fmaxf(m, om);
        s = s * expf(m - nm) + os * expf(om - nm);
        m = nm;
    }
    float inv = 1.f / (s + 1e-16f);
    float aself = expf(selfv - m) * inv;

    int half = lane >> 4, f = lane & 15;
    const float4* hps4 = (const float4*)(h + (size_t)node * 64);
    float4 acc = (half == 0) ? f4scale(hps4[f], aself) : make_float4(0.f, 0.f, 0.f, 0.f);

    for (int e0 = start; e0 < end; e0 += 8) {
        int me = e0 + lane;
        float alpha = 0.f; int msrc = 0;
        if (lane < 8 && me < end) {
            msrc = ecol[me];
            alpha = expf(leaky(s_[msrc] + dsel) - m) * inv;
        }
        int cnt = end - e0; if (cnt > 8) cnt = 8;
        for (int j = 0; j < cnt; j += 2) {
            int eidx = j + half;
            int src = __shfl_sync(0xffffffffu, msrc, eidx);
            float al = __shfl_sync(0xffffffffu, alpha, eidx);
            if (eidx < cnt) {
                const float4* hp4 = (const float4*)(h + (size_t)src * 64);
                acc = f4fma(hp4[f], al, acc);
            }
        }
    }
    acc.x += __shfl_xor_sync(0xffffffffu, acc.x, 16);
    acc.y += __shfl_xor_sync(0xffffffffu, acc.y, 16);
    acc.z += __shfl_xor_sync(0xffffffffu, acc.z, 16);
    acc.w += __shfl_xor_sync(0xffffffffu, acc.w, 16);

    const float4* b4 = (const float4*)bias;
    const float4* lw4 = (const float4*)lw;
    const float4* lb4 = (const float4*)lb;
    float4 v = f4add(acc, b4[f]);
    if (do_elu) {
        v.x = v.x > 0.f ? v.x : expf(v.x) - 1.f;
        v.y = v.y > 0.f ? v.y : expf(v.y) - 1.f;
        v.z = v.z > 0.f ? v.z : expf(v.z) - 1.f;
        v.w = v.w > 0.f ? v.w : expf(v.w) - 1.f;
    }
    float ssum = warpSum(v.x + v.y + v.z + v.w);
    float mu = ssum * (1.f / 128.f);
    float t, vs = 0.f;
    t = v.x - mu; vs += t * t; t = v.y - mu; vs += t * t;
    t = v.z - mu; vs += t * t; t = v.w - mu; vs += t * t;
    vs = warpSum(vs);
    float rs = rsqrtf(vs * (1.f / 128.f) + 1e-5f);
    if (half == 0) {
        float4 w = lw4[f], c = lb4[f];
        float4* out4 = (float4*)(outp + (size_t)node * 64);
        out4[f] = make_float4((v.x - mu) * rs * w.x + c.x, (v.y - mu) * rs * w.y + c.y,
                              (v.z - mu) * rs * w.z + c.z, (v.w - mu) * rs * w.w + c.w);
    }
}

// ---------------- final MLP head (stage-1 K halved via role precompute) ----------------
__global__ void head_kernel(const float* __restrict__ h3, const int* __restrict__ role,
                            const float* __restrict__ rc, const float* __restrict__ p1w,
                            const float* __restrict__ p2w, const float* __restrict__ p2b,
                            float* __restrict__ z, int n) {
    extern __shared__ float sm[];
    float* sp1 = sm;                  // 64*64 transposed (K<64 part of p1w)
    float* sp2 = sp1 + 64 * 64;       // 64*64 transposed
    float* sz  = sp2 + 64 * 64;       // 4 groups * 64
    float* sz1 = sz + 4 * 64;         // 4 groups * 64
    int tid = threadIdx.x;
    for (int i = tid; i < 64 * 64; i += 256) {
        int j = i >> 6, k = i & 63;
        sp1[k * 64 + j] = p1w[j * 128 + k];
        sp2[k * 64 + j] = p2w[i];
    }
    __syncthreads();
    int g = tid >> 6, j = tid & 63;
    float b2v = p2b[j];
    for (int it = 0; it < 16; it++) {
        int node = blockIdx.x * 64 + it * 4 + g;
        bool valid = node < n;
        float rcv = 0.f;
        if (valid) {
            sz[g * 64 + j] = h3[(size_t)node * 64 + j];
            rcv = rc[role[node] * 64 + j];
        }
        __syncthreads();
        float acc = rcv;
        #pragma unroll 8
        for (int k = 0; k < 64; k++) acc += sp1[k * 64 + j] * sz[g * 64 + k];
        sz1[g * 64 + j] = fmaxf(acc, 0.f);
        __syncthreads();
        float acc2 = b2v;
        #pragma unroll 8
        for (int k = 0; k < 64; k++) acc2 += sp2[k * 64 + j] * sz1[g * 64 + k];
        if (valid) z[(size_t)node * 64 + j] = acc2;
    }
}

// ---------------- host orchestration ----------------
extern "C" void kernel_launch(void* const* d_in, const int* in_sizes, int n_in,
                              void* d_out, int out_size) {
    const float* x   = (const float*)d_in[0];
    const void*  ei  = d_in[1];
    const void*  rid = d_in[2];
    const float* W1  = (const float*)d_in[3];
    const float* a1s = (const float*)d_in[4];
    const float* a1d = (const float*)d_in[5];
    const float* b1  = (const float*)d_in[6];
    const float* W2  = (const float*)d_in[7];
    const float* a2s = (const float*)d_in[8];
    const float* a2d = (const float*)d_in[9];
    const float* b2  = (const float*)d_in[10];
    const float* W3  = (const float*)d_in[11];
    const float* a3s = (const float*)d_in[12];
    const float* a3d = (const float*)d_in[13];
    const float* b3  = (const float*)d_in[14];
    const float* ln1w = (const float*)d_in[15];
    const float* ln1b = (const float*)d_in[16];
    const float* ln2w = (const float*)d_in[17];
    const float* ln2b = (const float*)d_in[18];
    const float* ln3w = (const float*)d_in[19];
    const float* ln3b = (const float*)d_in[20];
    const float* rt   = (const float*)d_in[21];
    const float* p1w  = (const float*)d_in[22];
    const float* p1b  = (const float*)d_in[23];
    const float* p2w  = (const float*)d_in[24];
    const float* p2b  = (const float*)d_in[25];
    float* z = (float*)d_out;

    float *hbuf, *xbuf, *ybuf, *sp, *dp, *rcp;
    int *srcp, *dstp, *ecolp, *rowp, *degp, *curp, *bsump, *rolep, *flagp;
    cudaGetSymbolAddress((void**)&hbuf, g_h);
    cudaGetSymbolAddress((void**)&xbuf, g_x);
    cudaGetSymbolAddress((void**)&ybuf, g_y);
    cudaGetSymbolAddress((void**)&sp, g_s);
    cudaGetSymbolAddress((void**)&dp, g_d);
    cudaGetSymbolAddress((void**)&rcp, g_rc);
    cudaGetSymbolAddress((void**)&srcp, g_src);
    cudaGetSymbolAddress((void**)&dstp, g_dst);
    cudaGetSymbolAddress((void**)&ecolp, g_ecol);
    cudaGetSymbolAddress((void**)&rowp, g_rowptr);
    cudaGetSymbolAddress((void**)&degp, g_deg);
    cudaGetSymbolAddress((void**)&curp, g_cursor);
    cudaGetSymbolAddress((void**)&bsump, g_bsum);
    cudaGetSymbolAddress((void**)&rolep, g_role);
    cudaGetSymbolAddress((void**)&flagp, g_is64);

    const int n = NN, E = EE;
    const int nb = (n + 1023) / 1024;

    dim3 gq(256 / 128, (n + QBM - 1) / QBM);
    int g3blocks = (n + 127) / 128;
    int fusedBlocks = (n * 32 + 255) / 256;

    detect_kernel<<<1, 32>>>((const unsigned int*)ei, flagp);
    cudaMemsetAsync(degp, 0, n * sizeof(int));
    prep_kernel<<<(E + 255) / 256, 256>>>(ei, rid, srcp, dstp, degp, rolep, flagp, E, n);
    scan_reduce_kernel<<<nb, 1024>>>(degp, bsump, n);
    // gemm1 stays in profile slot 5
    gemm_nt128<<<gq, 256>>>(x, W1, hbuf, n, 256, 64, a1s, a1d, sp, dp, 4);
    role_prep_kernel<<<1, 128>>>(rt, p1w, p1b, rcp);
    scan_final_kernel<<<nb, 1024>>>(degp, bsump, rowp, curp, n);
    scatter_kernel<<<(E + 255) / 256, 256>>>(srcp, dstp, curp, ecolp, E);

    // layer 1 gather
    gat_fused4<<<fusedBlocks, 256>>>(rowp, ecolp, sp, dp, hbuf, b1, ln1w, ln1b, xbuf, n, 1);

    // layer 2
    gemm_nt128<<<gq, 256>>>(xbuf, W2, hbuf, n, 256, 256, a2s, a2d, sp, dp, 4);
    gat_fused4<<<fusedBlocks, 256>>>(rowp, ecolp, sp, dp, hbuf, b2, ln2w, ln2b, xbuf, n, 1);

    // layer 3
    gemm_nt64<<<g3blocks, 128>>>(xbuf, W3, hbuf, n, 256, a3s, a3d, sp, dp);
    gat_fused1<<<fusedBlocks, 256>>>(rowp, ecolp, sp, dp, hbuf, b3, ln3w, ln3b, ybuf, n, 0);

    // final MLP head
    size_t smem = (64 * 64 + 64 * 64 + 4 * 64 + 4 * 64) * sizeof(float);
    cudaFuncSetAttribute(head_kernel, cudaFuncAttributeMaxDynamicSharedMemorySize, (int)smem);
    head_kernel<<<(n + 63) / 64, 256, smem>>>(ybuf, rolep, rcp, p1w, p2w, p2b, z, n);
}

// round 11
// speedup vs baseline: 1.0274x; 1.0274x over previous
#include <cuda_runtime.h>
#include <math.h>

#define NN 50000
#define EE 400000
#define DMAX 256

// ---------------- scratch ----------------
__device__ float g_h[(size_t)NN * DMAX];
__device__ float g_x[(size_t)NN * DMAX];
__device__ float g_y[(size_t)NN * DMAX];
__device__ float g_s[NN * 4];
__device__ float g_d[NN * 4];
__device__ float g_rc[2 * 64];
__device__ int g_src[EE];
__device__ int g_dst[EE];
__device__ int g_ecol[EE];
__device__ int g_rowptr[NN + 1];
__device__ int g_deg[NN];
__device__ int g_cursor[NN];
__device__ int g_bsum[64];
__device__ int g_role[NN];
__device__ int g_is64;

// ---------------- helpers ----------------
__device__ __forceinline__ float warpSum(float v) {
    #pragma unroll
    for (int o = 16; o > 0; o >>= 1) v += __shfl_xor_sync(0xffffffffu, v, o);
    return v;
}
__device__ __forceinline__ int warpSumI(int v) {
    #pragma unroll
    for (int o = 16; o > 0; o >>= 1) v += __shfl_xor_sync(0xffffffffu, v, o);
    return v;
}
__device__ __forceinline__ int warpInclScan(int v, int lane) {
    #pragma unroll
    for (int o = 1; o < 32; o <<= 1) {
        int t = __shfl_up_sync(0xffffffffu, v, o);
        if (lane >= o) v += t;
    }
    return v;
}
__device__ __forceinline__ float leaky(float v) { return fmaxf(v, 0.2f * v); }
__device__ __forceinline__ float4 f4fma(float4 a, float s, float4 c) {
    c.x += a.x * s; c.y += a.y * s; c.z += a.z * s; c.w += a.w * s; return c;
}
__device__ __forceinline__ float4 f4scale(float4 a, float s) {
    return make_float4(a.x * s, a.y * s, a.z * s, a.w * s);
}
__device__ __forceinline__ float4 f4add(float4 a, float4 b) {
    return make_float4(a.x + b.x, a.y + b.y, a.z + b.z, a.w + b.w);
}

// packed f32x2 ops (Blackwell)
#define PACK2(d, x, y) asm("mov.b64 %0, {%1, %2};" : "=l"(d) : "f"(x), "f"(y))
#define DUP2(d, x)     asm("mov.b64 %0, {%1, %1};" : "=l"(d) : "f"(x))
#define FMA2(c, a, b)  asm("fma.rn.f32x2 %0, %1, %2, %0;" : "+l"(c) : "l"(a), "l"(b))
#define UNPACK2(x, y, d) asm("mov.b64 {%0, %1}, %2;" : "=f"(x), "=f"(y) : "l"(d))

// ---------------- dtype detect + prep ----------------
__global__ void detect_kernel(const unsigned int* __restrict__ w, int* flag) {
    if (threadIdx.x == 0 && blockIdx.x == 0) {
        int is64 = 1;
        for (int i = 0; i < 64; i++)
            if (w[2 * i + 1] != 0u) { is64 = 0; break; }
        *flag = is64;
    }
}

__global__ void prep_kernel(const void* __restrict__ ei, const void* __restrict__ rid,
                            int* __restrict__ src, int* __restrict__ dst,
                            int* __restrict__ deg, int* __restrict__ role,
                            const int* __restrict__ flag, int E, int n) {
    int i = blockIdx.x * blockDim.x + threadIdx.x;
    int is64 = *flag;
    if (i < E) {
        int s, d;
        if (is64) {
            const long long* p = (const long long*)ei;
            s = (int)p[i];
            d = (int)p[(size_t)E + i];
        } else {
            const int* p = (const int*)ei;
            s = p[i];
            d = p[E + i];
        }
        src[i] = s;
        dst[i] = d;
        atomicAdd(&deg[d], 1);
    }
    if (i < n) {
        if (is64) role[i] = (int)((const long long*)rid)[i];
        else      role[i] = ((const int*)rid)[i];
    }
}

// ---------------- 2-phase scan ----------------
__global__ void scan_reduce_kernel(const int* __restrict__ deg, int* __restrict__ bsum, int n) {
    __shared__ int sw[32];
    int tid = threadIdx.x, lane = tid & 31, w = tid >> 5;
    int i = blockIdx.x * 1024 + tid;
    int v = (i < n) ? deg[i] : 0;
    v = warpSumI(v);
    if (lane == 0) sw[w] = v;
    __syncthreads();
    if (w == 0) {
        int t = sw[lane];
        t = warpSumI(t);
        if (lane == 0) bsum[blockIdx.x] = t;
    }
}

__global__ void scan_final_kernel(const int* __restrict__ deg, const int* __restrict__ bsum,
                                  int* __restrict__ rowptr, int* __restrict__ cursor, int n) {
    __shared__ int sw[32];
    __shared__ int partial[2];
    int tid = threadIdx.x, lane = tid & 31, w = tid >> 5;
    int bid = blockIdx.x;
    if (tid < 64) {
        int v = (tid < bid) ? bsum[tid] : 0;
        v = warpSumI(v);
        if ((tid & 31) == 0) partial[tid >> 5] = v;
    }
    int i = bid * 1024 + tid;
    int v = (i < n) ? deg[i] : 0;
    int iv = warpInclScan(v, lane);
    if (lane == 31) sw[w] = iv;
    __syncthreads();
    int base = partial[0] + partial[1];
    if (w == 0) {
        int t = sw[lane];
        t = warpInclScan(t, lane);
        sw[lane] = t;
    }
    __syncthreads();
    int offs = ((w > 0) ? sw[w - 1] : 0) + base;
    int incl = iv + offs;
    if (i < n) {
        rowptr[i + 1] = incl;
        cursor[i] = incl - v;
    }
    if (i == 0) rowptr[0] = 0;
}

__global__ void scatter_kernel(const int* __restrict__ src, const int* __restrict__ dst,
                               int* __restrict__ cursor, int* __restrict__ ecol, int E) {
    int i = blockIdx.x * blockDim.x + threadIdx.x;
    if (i >= E) return;
    int pos = atomicAdd(&cursor[dst[i]], 1);
    ecol[pos] = src[i];
}

// ---------------- role contribution precompute ----------------
__global__ void role_prep_kernel(const float* __restrict__ rt, const float* __restrict__ p1w,
                                 const float* __restrict__ p1b, float* __restrict__ rc) {
    int tid = threadIdx.x;      // 128 threads
    int r = tid >> 6, j = tid & 63;
    float acc = p1b[j];
    #pragma unroll 8
    for (int k = 0; k < 64; k++)
        acc += rt[r * 64 + k] * p1w[j * 128 + 64 + k];
    rc[r * 64 + j] = acc;
}

// ---------------- FFMA2 GEMM 128x128 (8x8/thread), Nc=256, fused scores ----------
#define QBM 128
#define QBK 16
__global__ void __launch_bounds__(256, 2) gemm_nt128(
        const float* __restrict__ A, const float* __restrict__ B,
        float* __restrict__ C, int M, int Nc, int K,
        const float* __restrict__ as_, const float* __restrict__ ad_,
        float* __restrict__ s_, float* __restrict__ d_, int H) {
    __shared__ float As[2][QBK][QBM + 4];
    __shared__ float Bs[2][QBK][QBM + 4];
    int tid = threadIdx.x;
    int lane = tid & 31;
    int brow = blockIdx.y * QBM, bcol = blockIdx.x * 128;
    int tr = tid >> 4, tc = tid & 15;
    unsigned long long accP[4][8];   // rows paired (2p, 2p+1) x 8 cols
    #pragma unroll
    for (int p = 0; p < 4; p++)
        #pragma unroll
        for (int j = 0; j < 8; j++) accP[p][j] = 0ull;

    int lrow[2], lkq[2];
    #pragma unroll
    for (int t = 0; t < 2; t++) { int li = tid + t * 256; lrow[t] = li >> 2; lkq[t] = (li & 3) * 4; }
    float4 aReg[2], bReg[2];
    const int nch = K / QBK;

    #pragma unroll
    for (int t = 0; t < 2; t++) {
        int gm = brow + lrow[t];
        aReg[t] = (gm < M) ? *(const float4*)&A[(size_t)gm * K + lkq[t]]
                           : make_float4(0.f, 0.f, 0.f, 0.f);
        int gn = bcol + lrow[t];
        bReg[t] = (gn < Nc) ? *(const float4*)&B[(size_t)gn * K + lkq[t]]
                            : make_float4(0.f, 0.f, 0.f, 0.f);
    }
    #pragma unroll
    for (int t = 0; t < 2; t++) {
        As[0][lkq[t] + 0][lrow[t]] = aReg[t].x; As[0][lkq[t] + 1][lrow[t]] = aReg[t].y;
        As[0][lkq[t] + 2][lrow[t]] = aReg[t].z; As[0][lkq[t] + 3][lrow[t]] = aReg[t].w;
        Bs[0][lkq[t] + 0][lrow[t]] = bReg[t].x; Bs[0][lkq[t] + 1][lrow[t]] = bReg[t].y;
        Bs[0][lkq[t] + 2][lrow[t]] = bReg[t].z; Bs[0][lkq[t] + 3][lrow[t]] = bReg[t].w;
    }
    __syncthreads();

    for (int c = 0; c < nch; c++) {
        int buf = c & 1;
        if (c + 1 < nch) {
            int k0 = (c + 1) * QBK;
            #pragma unroll
            for (int t = 0; t < 2; t++) {
                int gm = brow + lrow[t];
                aReg[t] = (gm < M) ? *(const float4*)&A[(size_t)gm * K + k0 + lkq[t]]
                                   : make_float4(0.f, 0.f, 0.f, 0.f);
                int gn = bcol + lrow[t];
                bReg[t] = (gn < Nc) ? *(const float4*)&B[(size_t)gn * K + k0 + lkq[t]]
                                    : make_float4(0.f, 0.f, 0.f, 0.f);
            }
        }
        #pragma unroll
        for (int kk = 0; kk < QBK; kk++) {
            float4 va0 = *(float4*)&As[buf][kk][tr * 8];
            float4 va1 = *(float4*)&As[buf][kk][tr * 8 + 4];
            float4 vb0 = *(float4*)&Bs[buf][kk][tc * 4];
            float4 vb1 = *(float4*)&Bs[buf][kk][64 + tc * 4];
            unsigned long long a2[4], bd[8];
            PACK2(a2[0], va0.x, va0.y); PACK2(a2[1], va0.z, va0.w);
            PACK2(a2[2], va1.x, va1.y); PACK2(a2[3], va1.z, va1.w);
            DUP2(bd[0], vb0.x); DUP2(bd[1], vb0.y); DUP2(bd[2], vb0.z); DUP2(bd[3], vb0.w);
            DUP2(bd[4], vb1.x); DUP2(bd[5], vb1.y); DUP2(bd[6], vb1.z); DUP2(bd[7], vb1.w);
            #pragma unroll
            for (int p = 0; p < 4; p++)
                #pragma unroll
                for (int j = 0; j < 8; j++) FMA2(accP[p][j], a2[p], bd[j]);
        }
        if (c + 1 < nch) {
            int nb = buf ^ 1;
            #pragma unroll
            for (int t = 0; t < 2; t++) {
                As[nb][lkq[t] + 0][lrow[t]] = aReg[t].x; As[nb][lkq[t] + 1][lrow[t]] = aReg[t].y;
                As[nb][lkq[t] + 2][lrow[t]] = aReg[t].z; As[nb][lkq[t] + 3][lrow[t]] = aReg[t].w;
                Bs[nb][lkq[t] + 0][lrow[t]] = bReg[t].x; Bs[nb][lkq[t] + 1][lrow[t]] = bReg[t].y;
                Bs[nb][lkq[t] + 2][lrow[t]] = bReg[t].z; Bs[nb][lkq[t] + 3][lrow[t]] = bReg[t].w;
            }
        }
        __syncthreads();
    }

    // unpack accumulators
    float acc[8][8];
    #pragma unroll
    for (int p = 0; p < 4; p++)
        #pragma unroll
        for (int j = 0; j < 8; j++) UNPACK2(acc[2 * p][j], acc[2 * p + 1][j], accP[p][j]);

    #pragma unroll
    for (int i = 0; i < 8; i++) {
        int gm = brow + tr * 8 + i;
        if (gm >= M) continue;
        *(float4*)&C[(size_t)gm * Nc + bcol + tc * 4] =
            make_float4(acc[i][0], acc[i][1], acc[i][2], acc[i][3]);
        *(float4*)&C[(size_t)gm * Nc + bcol + 64 + tc * 4] =
            make_float4(acc[i][4], acc[i][5], acc[i][6], acc[i][7]);
    }

    int h0 = blockIdx.x * 2, h1 = h0 + 1;
    float as0[4], ad0[4], as1[4], ad1[4];
    #pragma unroll
    for (int j = 0; j < 4; j++) {
        as0[j] = as_[h0 * 64 + tc * 4 + j];
        ad0[j] = ad_[h0 * 64 + tc * 4 + j];
        as1[j] = as_[h1 * 64 + tc * 4 + j];
        ad1[j] = ad_[h1 * 64 + tc * 4 + j];
    }
    #pragma unroll
    for (int i = 0; i < 8; i++) {
        float s0 = 0.f, e0 = 0.f, s1 = 0.f, e1 = 0.f;
        #pragma unroll
        for (int j = 0; j < 4; j++) {
            s0 += acc[i][j] * as0[j];
            e0 += acc[i][j] * ad0[j];
            s1 += acc[i][4 + j] * as1[j];
            e1 += acc[i][4 + j] * ad1[j];
        }
        #pragma unroll
        for (int o = 8; o >= 1; o >>= 1) {
            s0 += __shfl_xor_sync(0xffffffffu, s0, o);
            e0 += __shfl_xor_sync(0xffffffffu, e0, o);
            s1 += __shfl_xor_sync(0xffffffffu, s1, o);
            e1 += __shfl_xor_sync(0xffffffffu, e1, o);
        }
        int gm = brow + tr * 8 + i;
        if ((lane & 15) == 0 && gm < M) {
            s_[(size_t)gm * H + h0] = s0;
            d_[(size_t)gm * H + h0] = e0;
            s_[(size_t)gm * H + h1] = s1;
            d_[(size_t)gm * H + h1] = e1;
        }
    }
}

// ---------------- FFMA2 GEMM 128x64 (8x8/thread, 128 threads), Nc=64, H=1 ---------
__global__ void __launch_bounds__(128) gemm_nt64(
        const float* __restrict__ A, const float* __restrict__ B,
        float* __restrict__ C, int M, int K,
        const float* __restrict__ as_, const float* __restrict__ ad_,
        float* __restrict__ s_, float* __restrict__ d_) {
    __shared__ float As[2][16][132];
    __shared__ float Bs[2][16][68];
    int tid = threadIdx.x;
    int lane = tid & 31;
    int brow = blockIdx.x * 128;
    int tr = tid >> 3, tc = tid & 7;
    unsigned long long accP[4][8];
    #pragma unroll
    for (int p = 0; p < 4; p++)
        #pragma unroll
        for (int j = 0; j < 8; j++) accP[p][j] = 0ull;

    int lrowA[4], lkqA[4];
    #pragma unroll
    for (int t = 0; t < 4; t++) { int li = tid + t * 128; lrowA[t] = li >> 2; lkqA[t] = (li & 3) * 4; }
    int lrowB[2], lkqB[2];
    #pragma unroll
    for (int t = 0; t < 2; t++) { int li = tid + t * 128; lrowB[t] = li >> 2; lkqB[t] = (li & 3) * 4; }
    float4 aReg[4], bReg[2];
    const int nch = K / 16;

    #pragma unroll
    for (int t = 0; t < 4; t++) {
        int gm = brow + lrowA[t];
        aReg[t] = (gm < M) ? *(const float4*)&A[(size_t)gm * K + lkqA[t]]
                           : make_float4(0.f, 0.f, 0.f, 0.f);
    }
    #pragma unroll
    for (int t = 0; t < 2; t++)
        bReg[t] = *(const float4*)&B[(size_t)lrowB[t] * K + lkqB[t]];
    #pragma unroll
    for (int t = 0; t < 4; t++) {
        As[0][lkqA[t] + 0][lrowA[t]] = aReg[t].x; As[0][lkqA[t] + 1][lrowA[t]] = aReg[t].y;
        As[0][lkqA[t] + 2][lrowA[t]] = aReg[t].z; As[0][lkqA[t] + 3][lrowA[t]] = aReg[t].w;
    }
    #pragma unroll
    for (int t = 0; t < 2; t++) {
        Bs[0][lkqB[t] + 0][lrowB[t]] = bReg[t].x; Bs[0][lkqB[t] + 1][lrowB[t]] = bReg[t].y;
        Bs[0][lkqB[t] + 2][lrowB[t]] = bReg[t].z; Bs[0][lkqB[t] + 3][lrowB[t]] = bReg[t].w;
    }
    __syncthreads();

    for (int c = 0; c < nch; c++) {
        int buf = c & 1;
        if (c + 1 < nch) {
            int k0 = (c + 1) * 16;
            #pragma unroll
            for (int t = 0; t < 4; t++) {
                int gm = brow + lrowA[t];
                aReg[t] = (gm < M) ? *(const float4*)&A[(size_t)gm * K + k0 + lkqA[t]]
                                   : make_float4(0.f, 0.f, 0.f, 0.f);
            }
            #pragma unroll
            for (int t = 0; t < 2; t++)
                bReg[t] = *(const float4*)&B[(size_t)lrowB[t] * K + k0 + lkqB[t]];
        }
        #pragma unroll
        for (int kk = 0; kk < 16; kk++) {
            float4 va0 = *(float4*)&As[buf][kk][tr * 8];
            float4 va1 = *(float4*)&As[buf][kk][tr * 8 + 4];
            float4 vb0 = *(float4*)&Bs[buf][kk][tc * 8];
            float4 vb1 = *(float4*)&Bs[buf][kk][tc * 8 + 4];
            unsigned long long a2[4], bd[8];
            PACK2(a2[0], va0.x, va0.y); PACK2(a2[1], va0.z, va0.w);
            PACK2(a2[2], va1.x, va1.y); PACK2(a2[3], va1.z, va1.w);
            DUP2(bd[0], vb0.x); DUP2(bd[1], vb0.y); DUP2(bd[2], vb0.z); DUP2(bd[3], vb0.w);
            DUP2(bd[4], vb1.x); DUP2(bd[5], vb1.y); DUP2(bd[6], vb1.z); DUP2(bd[7], vb1.w);
            #pragma unroll
            for (int p = 0; p < 4; p++)
                #pragma unroll
                for (int j = 0; j < 8; j++) FMA2(accP[p][j], a2[p], bd[j]);
        }
        if (c + 1 < nch) {
            int nb = buf ^ 1;
            #pragma unroll
            for (int t = 0; t < 4; t++) {
                As[nb][lkqA[t] + 0][lrowA[t]] = aReg[t].x; As[nb][lkqA[t] + 1][lrowA[t]] = aReg[t].y;
                As[nb][lkqA[t] + 2][lrowA[t]] = aReg[t].z; As[nb][lkqA[t] + 3][lrowA[t]] = aReg[t].w;
            }
            #pragma unroll
            for (int t = 0; t < 2; t++) {
                Bs[nb][lkqB[t] + 0][lrowB[t]] = bReg[t].x; Bs[nb][lkqB[t] + 1][lrowB[t]] = bReg[t].y;
                Bs[nb][lkqB[t] + 2][lrowB[t]] = bReg[t].z; Bs[nb][lkqB[t] + 3][lrowB[t]] = bReg[t].w;
            }
        }
        __syncthreads();
    }

    float acc[8][8];
    #pragma unroll
    for (int p = 0; p < 4; p++)
        #pragma unroll
        for (int j = 0; j < 8; j++) UNPACK2(acc[2 * p][j], acc[2 * p + 1][j], accP[p][j]);

    #pragma unroll
    for (int i = 0; i < 8; i++) {
        int gm = brow + tr * 8 + i;
        if (gm >= M) continue;
        *(float4*)&C[(size_t)gm * 64 + tc * 8] =
            make_float4(acc[i][0], acc[i][1], acc[i][2], acc[i][3]);
        *(float4*)&C[(size_t)gm * 64 + tc * 8 + 4] =
            make_float4(acc[i][4], acc[i][5], acc[i][6], acc[i][7]);
    }

    float asv[8], adv[8];
    #pragma unroll
    for (int j = 0; j < 8; j++) {
        asv[j] = as_[tc * 8 + j];
        adv[j] = ad_[tc * 8 + j];
    }
    #pragma unroll
    for (int i = 0; i < 8; i++) {
        float ss = 0.f, dd = 0.f;
        #pragma unroll
        for (int j = 0; j < 8; j++) {
            ss += acc[i][j] * asv[j];
            dd += acc[i][j] * adv[j];
        }
        #pragma unroll
        for (int o = 4; o >= 1; o >>= 1) {
            ss += __shfl_xor_sync(0xffffffffu, ss, o);
            dd += __shfl_xor_sync(0xffffffffu, dd, o);
        }
        int gm = brow + tr * 8 + i;
        if ((lane & 7) == 0 && gm < M) {
            s_[gm] = ss;
            d_[gm] = dd;
        }
    }
}

// ---------------- fused GAT layer, H=4 ----------
__global__ void gat_fused4(const int* __restrict__ rowptr, const int* __restrict__ ecol,
                           const float* __restrict__ s_, const float* __restrict__ d_,
                           const float* __restrict__ h, const float* __restrict__ bias,
                           const float* __restrict__ lw, const float* __restrict__ lb,
                           float* __restrict__ outp, int n, int do_elu) {
    int warp = (blockIdx.x * blockDim.x + threadIdx.x) >> 5;
    int lane = threadIdx.x & 31;
    if (warp >= n) return;
    int node = warp;
    int start = rowptr[node], end = rowptr[node + 1];

    float4 dv4 = ((const float4*)d_)[node];
    float dsel[4] = {dv4.x, dv4.y, dv4.z, dv4.w};
    float4 sv4 = ((const float4*)s_)[node];
    float selfv[4] = {leaky(sv4.x + dsel[0]), leaky(sv4.y + dsel[1]),
                      leaky(sv4.z + dsel[2]), leaky(sv4.w + dsel[3])};

    float m[4], s[4];
    #pragma unroll
    for (int q = 0; q < 4; q++) {
        m[q] = (lane == 0) ? selfv[q] : -3e38f;
        s[q] = (lane == 0) ? 1.f : 0.f;
    }
    for (int e = start + lane; e < end; e += 32) {
        int src = ecol[e];
        float4 sv = ((const float4*)s_)[src];
        float v[4] = {leaky(sv.x + dsel[0]), leaky(sv.y + dsel[1]),
                      leaky(sv.z + dsel[2]), leaky(sv.w + dsel[3])};
        #pragma unroll
        for (int q = 0; q < 4; q++) {
            float nm = fmaxf(m[q], v[q]);
            s[q] = s[q] * expf(m[q] - nm) + expf(v[q] - nm);
            m[q] = nm;
        }
    }
    #pragma unroll
    for (int o = 16; o > 0; o >>= 1) {
        #pragma unroll
        for (int q = 0; q < 4; q++) {
            float om = __shfl_xor_sync(0xffffffffu, m[q], o);
            float os = __shfl_xor_sync(0xffffffffu, s[q], o);
            float nm = fmaxf(m[q], om);
            s[q] = s[q] * expf(m[q] - nm) + os * expf(om - nm);
            m[q] = nm;
        }
    }
    float inv[4], aself[4];
    #pragma unroll
    for (int q = 0; q < 4; q++) {
        inv[q] = 1.f / (s[q] + 1e-16f);
        aself[q] = expf(selfv[q] - m[q]) * inv[q];
    }

    int hl = lane & 3;
    float d_hl = (hl == 0) ? dsel[0] : (hl == 1) ? dsel[1] : (hl == 2) ? dsel[2] : dsel[3];
    float m_hl = (hl == 0) ? m[0]    : (hl == 1) ? m[1]    : (hl == 2) ? m[2]    : m[3];
    float i_hl = (hl == 0) ? inv[0]  : (hl == 1) ? inv[1]  : (hl == 2) ? inv[2]  : inv[3];
    int hA = lane >> 4;
    float asA = hA ? aself[1] : aself[0];
    float asB = hA ? aself[3] : aself[2];

    const float4* hps4 = (const float4*)(h + (size_t)node * 256);
    float4 acc0 = f4scale(hps4[lane], asA);
    float4 acc1 = f4scale(hps4[lane + 32], asB);

    for (int e0 = start; e0 < end; e0 += 8) {
        int me = e0 + (lane >> 2);
        float alpha = 0.f; int msrc = 0;
        if (me < end) {
            msrc = ecol[me];
            float v = leaky(s_[(size_t)msrc * 4 + hl] + d_hl);
            alpha = expf(v - m_hl) * i_hl;
        }
        int cnt = end - e0; if (cnt > 8) cnt = 8;
        for (int j0 = 0; j0 < cnt; j0 += 4) {
            int jn = cnt - j0; if (jn > 4) jn = 4;
            float4 pa[4], pb[4];
            float a0[4], a1[4];
            #pragma unroll
            for (int j = 0; j < 4; j++) {
                int src = __shfl_sync(0xffffffffu, msrc, (j0 + j) * 4);
                a0[j] = __shfl_sync(0xffffffffu, alpha, (j0 + j) * 4 + hA);
                a1[j] = __shfl_sync(0xffffffffu, alpha, (j0 + j) * 4 + 2 + hA);
                if (j < jn) {
                    const float4* hp4 = (const float4*)(h + (size_t)src * 256);
                    pa[j] = hp4[lane];
                    pb[j] = hp4[lane + 32];
                }
            }
            #pragma unroll
            for (int j = 0; j < 4; j++) {
                if (j < jn) {
                    acc0 = f4fma(pa[j], a0[j], acc0);
                    acc1 = f4fma(pb[j], a1[j], acc1);
                }
            }
        }
    }

    const float4* b4 = (const float4*)bias;
    const float4* lw4 = (const float4*)lw;
    const float4* lb4 = (const float4*)lb;
    float4 v0 = f4add(acc0, b4[lane]);
    float4 v1 = f4add(acc1, b4[lane + 32]);
    if (do_elu) {
        v0.x = v0.x > 0.f ? v0.x : expf(v0.x) - 1.f;
        v0.y = v0.y > 0.f ? v0.y : expf(v0.y) - 1.f;
        v0.z = v0.z > 0.f ? v0.z : expf(v0.z) - 1.f;
        v0.w = v0.w > 0.f ? v0.w : expf(v0.w) - 1.f;
        v1.x = v1.x > 0.f ? v1.x : expf(v1.x) - 1.f;
        v1.y = v1.y > 0.f ? v1.y : expf(v1.y) - 1.f;
        v1.z = v1.z > 0.f ? v1.z : expf(v1.z) - 1.f;
        v1.w = v1.w > 0.f ? v1.w : expf(v1.w) - 1.f;
    }
    float ssum = v0.x + v0.y + v0.z + v0.w + v1.x + v1.y + v1.z + v1.w;
    ssum = warpSum(ssum);
    float mu = ssum * (1.f / 256.f);
    float t, vs = 0.f;
    t = v0.x - mu; vs += t * t; t = v0.y - mu; vs += t * t;
    t = v0.z - mu; vs += t * t; t = v0.w - mu; vs += t * t;
    t = v1.x - mu; vs += t * t; t = v1.y - mu; vs += t * t;
    t = v1.z - mu; vs += t * t; t = v1.w - mu; vs += t * t;
    vs = warpSum(vs);
    float rs = rsqrtf(vs * (1.f / 256.f) + 1e-5f);
    float4 w0 = lw4[lane], w1 = lw4[lane + 32];
    float4 c0 = lb4[lane], c1 = lb4[lane + 32];
    float4* out4 = (float4*)(outp + (size_t)node * 256);
    out4[lane] = make_float4((v0.x - mu) * rs * w0.x + c0.x, (v0.y - mu) * rs * w0.y + c0.y,
                             (v0.z - mu) * rs * w0.z + c0.z, (v0.w - mu) * rs * w0.w + c0.w);
    out4[lane + 32] = make_float4((v1.x - mu) * rs * w1.x + c1.x, (v1.y - mu) * rs * w1.y + c1.y,
                                  (v1.z - mu) * rs * w1.z + c1.z, (v1.w - mu) * rs * w1.w + c1.w);
}

// ---------------- fused GAT layer, H=1 (D=64) ----------
__global__ void gat_fused1(const int* __restrict__ rowptr, const int* __restrict__ ecol,
                           const float* __restrict__ s_, const float* __restrict__ d_,
                           const float* __restrict__ h, const float* __restrict__ bias,
                           const float* __restrict__ lw, const float* __restrict__ lb,
                           float* __restrict__ outp, int n, int do_elu) {
    int warp = (blockIdx.x * blockDim.x + threadIdx.x) >> 5;
    int lane = threadIdx.x & 31;
    if (warp >= n) return;
    int node = warp;
    int start = rowptr[node], end = rowptr[node + 1];

    float dsel = d_[node];
    float selfv = leaky(s_[node] + dsel);
    float m = (lane == 0) ? selfv : -3e38f;
    float s = (lane == 0) ? 1.f : 0.f;
    for (int e = start + lane; e < end; e += 32) {
        float v = leaky(s_[ecol[e]] + dsel);
        float nm = fmaxf(m, v);
        s = s * expf(m - nm) + expf(v - nm);
        m = nm;
    }
    #pragma unroll
    for (int o = 16; o > 0; o >>= 1) {
        float om = __shfl_xor_sync(0xffffffffu, m, o);
        float os = __shfl_xor_sync(0xffffffffu, s, o);
        float nm = fmaxf(m, om);
        s = s * expf(m - nm) + os * expf(om - nm);
        m = nm;
    }
    float inv = 1.f / (s + 1e-16f);
    float aself = expf(selfv - m) * inv;

    int half = lane >> 4, f = lane & 15;
    const float4* hps4 = (const float4*)(h + (size_t)node * 64);
    float4 acc = (half == 0) ? f4scale(hps4[f], aself) : make_float4(0.f, 0.f, 0.f, 0.f);

    for (int e0 = start; e0 < end; e0 += 8) {
        int me = e0 + lane;
        float alpha = 0.f; int msrc = 0;
        if (lane < 8 && me < end) {
            msrc = ecol[me];
            alpha = expf(leaky(s_[msrc] + dsel) - m) * inv;
        }
        int cnt = end - e0; if (cnt > 8) cnt = 8;
        for (int j = 0; j < cnt; j += 2) {
            int eidx = j + half;
            int src = __shfl_sync(0xffffffffu, msrc, eidx);
            float al = __shfl_sync(0xffffffffu, alpha, eidx);
            if (eidx < cnt) {
                const float4* hp4 = (const float4*)(h + (size_t)src * 64);
                acc = f4fma(hp4[f], al, acc);
            }
        }
    }
    acc.x += __shfl_xor_sync(0xffffffffu, acc.x, 16);
    acc.y += __shfl_xor_sync(0xffffffffu, acc.y, 16);
    acc.z += __shfl_xor_sync(0xffffffffu, acc.z, 16);
    acc.w += __shfl_xor_sync(0xffffffffu, acc.w, 16);

    const float4* b4 = (const float4*)bias;
    const float4* lw4 = (const float4*)lw;
    const float4* lb4 = (const float4*)lb;
    float4 v = f4add(acc, b4[f]);
    if (do_elu) {
        v.x = v.x > 0.f ? v.x : expf(v.x) - 1.f;
        v.y = v.y > 0.f ? v.y : expf(v.y) - 1.f;
        v.z = v.z > 0.f ? v.z : expf(v.z) - 1.f;
        v.w = v.w > 0.f ? v.w : expf(v.w) - 1.f;
    }
    float ssum = warpSum(v.x + v.y + v.z + v.w);
    float mu = ssum * (1.f / 128.f);
    float t, vs = 0.f;
    t = v.x - mu; vs += t * t; t = v.y - mu; vs += t * t;
    t = v.z - mu; vs += t * t; t = v.w - mu; vs += t * t;
    vs = warpSum(vs);
    float rs = rsqrtf(vs * (1.f / 128.f) + 1e-5f);
    if (half == 0) {
        float4 w = lw4[f], c = lb4[f];
        float4* out4 = (float4*)(outp + (size_t)node * 64);
        out4[f] = make_float4((v.x - mu) * rs * w.x + c.x, (v.y - mu) * rs * w.y + c.y,
                              (v.z - mu) * rs * w.z + c.z, (v.w - mu) * rs * w.w + c.w);
    }
}

// ---------------- final MLP head ----------------
__global__ void head_kernel(const float* __restrict__ h3, const int* __restrict__ role,
                            const float* __restrict__ rc, const float* __restrict__ p1w,
                            const float* __restrict__ p2w, const float* __restrict__ p2b,
                            float* __restrict__ z, int n) {
    extern __shared__ float sm[];
    float* sp1 = sm;
    float* sp2 = sp1 + 64 * 64;
    float* sz  = sp2 + 64 * 64;
    float* sz1 = sz + 4 * 64;
    int tid = threadIdx.x;
    for (int i = tid; i < 64 * 64; i += 256) {
        int j = i >> 6, k = i & 63;
        sp1[k * 64 + j] = p1w[j * 128 + k];
        sp2[k * 64 + j] = p2w[i];
    }
    __syncthreads();
    int g = tid >> 6, j = tid & 63;
    float b2v = p2b[j];
    for (int it = 0; it < 16; it++) {
        int node = blockIdx.x * 64 + it * 4 + g;
        bool valid = node < n;
        float rcv = 0.f;
        if (valid) {
            sz[g * 64 + j] = h3[(size_t)node * 64 + j];
            rcv = rc[role[node] * 64 + j];
        }
        __syncthreads();
        float acc = rcv;
        #pragma unroll 8
        for (int k = 0; k < 64; k++) acc += sp1[k * 64 + j] * sz[g * 64 + k];
        sz1[g * 64 + j] = fmaxf(acc, 0.f);
        __syncthreads();
        float acc2 = b2v;
        #pragma unroll 8
        for (int k = 0; k < 64; k++) acc2 += sp2[k * 64 + j] * sz1[g * 64 + k];
        if (valid) z[(size_t)node * 64 + j] = acc2;
    }
}

// ---------------- host orchestration ----------------
extern "C" void kernel_launch(void* const* d_in, const int* in_sizes, int n_in,
                              void* d_out, int out_size) {
    const float* x   = (const float*)d_in[0];
    const void*  ei  = d_in[1];
    const void*  rid = d_in[2];
    const float* W1  = (const float*)d_in[3];
    const float* a1s = (const float*)d_in[4];
    const float* a1d = (const float*)d_in[5];
    const float* b1  = (const float*)d_in[6];
    const float* W2  = (const float*)d_in[7];
    const float* a2s = (const float*)d_in[8];
    const float* a2d = (const float*)d_in[9];
    const float* b2  = (const float*)d_in[10];
    const float* W3  = (const float*)d_in[11];
    const float* a3s = (const float*)d_in[12];
    const float* a3d = (const float*)d_in[13];
    const float* b3  = (const float*)d_in[14];
    const float* ln1w = (const float*)d_in[15];
    const float* ln1b = (const float*)d_in[16];
    const float* ln2w = (const float*)d_in[17];
    const float* ln2b = (const float*)d_in[18];
    const float* ln3w = (const float*)d_in[19];
    const float* ln3b = (const float*)d_in[20];
    const float* rt   = (const float*)d_in[21];
    const float* p1w  = (const float*)d_in[22];
    const float* p1b  = (const float*)d_in[23];
    const float* p2w  = (const float*)d_in[24];
    const float* p2b  = (const float*)d_in[25];
    float* z = (float*)d_out;

    float *hbuf, *xbuf, *ybuf, *sp, *dp, *rcp;
    int *srcp, *dstp, *ecolp, *rowp, *degp, *curp, *bsump, *rolep, *flagp;
    cudaGetSymbolAddress((void**)&hbuf, g_h);
    cudaGetSymbolAddress((void**)&xbuf, g_x);
    cudaGetSymbolAddress((void**)&ybuf, g_y);
    cudaGetSymbolAddress((void**)&sp, g_s);
    cudaGetSymbolAddress((void**)&dp, g_d);
    cudaGetSymbolAddress((void**)&rcp, g_rc);
    cudaGetSymbolAddress((void**)&srcp, g_src);
    cudaGetSymbolAddress((void**)&dstp, g_dst);
    cudaGetSymbolAddress((void**)&ecolp, g_ecol);
    cudaGetSymbolAddress((void**)&rowp, g_rowptr);
    cudaGetSymbolAddress((void**)&degp, g_deg);
    cudaGetSymbolAddress((void**)&curp, g_cursor);
    cudaGetSymbolAddress((void**)&bsump, g_bsum);
    cudaGetSymbolAddress((void**)&rolep, g_role);
    cudaGetSymbolAddress((void**)&flagp, g_is64);

    const int n = NN, E = EE;
    const int nb = (n + 1023) / 1024;

    dim3 gq(256 / 128, (n + QBM - 1) / QBM);
    int g3blocks = (n + 127) / 128;
    int fusedBlocks = (n * 32 + 255) / 256;

    detect_kernel<<<1, 32>>>((const unsigned int*)ei, flagp);
    cudaMemsetAsync(degp, 0, n * sizeof(int));
    prep_kernel<<<(E + 255) / 256, 256>>>(ei, rid, srcp, dstp, degp, rolep, flagp, E, n);
    scan_reduce_kernel<<<nb, 1024>>>(degp, bsump, n);
    gemm_nt128<<<gq, 256>>>(x, W1, hbuf, n, 256, 64, a1s, a1d, sp, dp, 4);
    role_prep_kernel<<<1, 128>>>(rt, p1w, p1b, rcp);
    scan_final_kernel<<<nb, 1024>>>(degp, bsump, rowp, curp, n);
    scatter_kernel<<<(E + 255) / 256, 256>>>(srcp, dstp, curp, ecolp, E);

    // layer 1 gather
    gat_fused4<<<fusedBlocks, 256>>>(rowp, ecolp, sp, dp, hbuf, b1, ln1w, ln1b, xbuf, n, 1);

    // layer 2
    gemm_nt128<<<gq, 256>>>(xbuf, W2, hbuf, n, 256, 256, a2s, a2d, sp, dp, 4);
    gat_fused4<<<fusedBlocks, 256>>>(rowp, ecolp, sp, dp, hbuf, b2, ln2w, ln2b, xbuf, n, 1);

    // layer 3
    gemm_nt64<<<g3blocks, 128>>>(xbuf, W3, hbuf, n, 256, a3s, a3d, sp, dp);
    gat_fused1<<<fusedBlocks, 256>>>(rowp, ecolp, sp, dp, hbuf, b3, ln3w, ln3b, ybuf, n, 0);

    // final MLP head
    size_t smem = (64 * 64 + 64 * 64 + 4 * 64 + 4 * 64) * sizeof(float);
    cudaFuncSetAttribute(head_kernel, cudaFuncAttributeMaxDynamicSharedMemorySize, (int)smem);
    head_kernel<<<(n + 63) / 64, 256, smem>>>(ybuf, rolep, rcp, p1w, p2w, p2b, z, n);
}

// round 12
// speedup vs baseline: 1.0884x; 1.0594x over previous
#include <cuda_runtime.h>
#include <cuda_bf16.h>
#include <math.h>

#define NN 50000
#define EE 400000
#define DMAX 256

// ---------------- scratch ----------------
__device__ float g_h[(size_t)NN * DMAX];
__device__ float g_x[(size_t)NN * DMAX];
__device__ float g_y[(size_t)NN * DMAX];
__device__ float g_s[NN * 4];
__device__ float g_d[NN * 4];
__device__ float g_rc[2 * 64];
__device__ unsigned g_xhi[(size_t)NN * 128];
__device__ unsigned g_xlo[(size_t)NN * 128];
__device__ unsigned g_whi[256 * 128];
__device__ unsigned g_wlo[256 * 128];
__device__ int g_src[EE];
__device__ int g_dst[EE];
__device__ int g_ecol[EE];
__device__ int g_rowptr[NN + 1];
__device__ int g_deg[NN];
__device__ int g_cursor[NN];
__device__ int g_bsum[64];
__device__ int g_role[NN];
__device__ int g_is64;

// ---------------- helpers ----------------
__device__ __forceinline__ float warpSum(float v) {
    #pragma unroll
    for (int o = 16; o > 0; o >>= 1) v += __shfl_xor_sync(0xffffffffu, v, o);
    return v;
}
__device__ __forceinline__ int warpSumI(int v) {
    #pragma unroll
    for (int o = 16; o > 0; o >>= 1) v += __shfl_xor_sync(0xffffffffu, v, o);
    return v;
}
__device__ __forceinline__ int warpInclScan(int v, int lane) {
    #pragma unroll
    for (int o = 1; o < 32; o <<= 1) {
        int t = __shfl_up_sync(0xffffffffu, v, o);
        if (lane >= o) v += t;
    }
    return v;
}
__device__ __forceinline__ float leaky(float v) { return fmaxf(v, 0.2f * v); }
__device__ __forceinline__ float4 f4fma(float4 a, float s, float4 c) {
    c.x += a.x * s; c.y += a.y * s; c.z += a.z * s; c.w += a.w * s; return c;
}
__device__ __forceinline__ float4 f4scale(float4 a, float s) {
    return make_float4(a.x * s, a.y * s, a.z * s, a.w * s);
}
__device__ __forceinline__ float4 f4add(float4 a, float4 b) {
    return make_float4(a.x + b.x, a.y + b.y, a.z + b.z, a.w + b.w);
}

// packed f32x2 ops (for FFMA2 gemm_nt64)
#define PACK2(d, x, y) asm("mov.b64 %0, {%1, %2};" : "=l"(d) : "f"(x), "f"(y))
#define DUP2(d, x)     asm("mov.b64 %0, {%1, %1};" : "=l"(d) : "f"(x))
#define FMA2(c, a, b)  asm("fma.rn.f32x2 %0, %1, %2, %0;" : "+l"(c) : "l"(a), "l"(b))
#define UNPACK2(x, y, d) asm("mov.b64 {%0, %1}, %2;" : "=f"(x), "=f"(y) : "l"(d))

// bf16 helpers: word packs (elem k -> low 16, elem k+1 -> high 16)
__device__ __forceinline__ unsigned packbf(float lo_elem, float hi_elem) {
    unsigned r;
    asm("cvt.rn.bf16x2.f32 %0, %1, %2;" : "=r"(r) : "f"(hi_elem), "f"(lo_elem));
    return r;
}
__device__ __forceinline__ float bfr(float f) {
    return __bfloat162float(__float2bfloat16(f));
}

#define MMA_BF16(c, a, b)                                                        \
    asm volatile("mma.sync.aligned.m16n8k16.row.col.f32.bf16.bf16.f32 "          \
                 "{%0,%1,%2,%3}, {%4,%5,%6,%7}, {%8,%9}, {%0,%1,%2,%3};"         \
                 : "+f"((c)[0]), "+f"((c)[1]), "+f"((c)[2]), "+f"((c)[3])        \
                 : "r"((a)[0]), "r"((a)[1]), "r"((a)[2]), "r"((a)[3]),           \
                   "r"((b)[0]), "r"((b)[1]))

// ---------------- bf16 hi/lo split (linear, words = elems/2) ----------------
__global__ void split_kernel(const float* __restrict__ in, unsigned* __restrict__ hi,
                             unsigned* __restrict__ lo, int n4) {
    int i = blockIdx.x * blockDim.x + threadIdx.x;
    if (i >= n4) return;
    float4 v = ((const float4*)in)[i];
    float h0 = bfr(v.x), h1 = bfr(v.y), h2 = bfr(v.z), h3 = bfr(v.w);
    uint2 hw = make_uint2(packbf(v.x, v.y), packbf(v.z, v.w));
    uint2 lw = make_uint2(packbf(v.x - h0, v.y - h1), packbf(v.z - h2, v.w - h3));
    ((uint2*)hi)[i] = hw;
    ((uint2*)lo)[i] = lw;
}

// ---------------- dtype detect + prep ----------------
__global__ void detect_kernel(const unsigned int* __restrict__ w, int* flag) {
    if (threadIdx.x == 0 && blockIdx.x == 0) {
        int is64 = 1;
        for (int i = 0; i < 64; i++)
            if (w[2 * i + 1] != 0u) { is64 = 0; break; }
        *flag = is64;
    }
}

__global__ void prep_kernel(const void* __restrict__ ei, const void* __restrict__ rid,
                            int* __restrict__ src, int* __restrict__ dst,
                            int* __restrict__ deg, int* __restrict__ role,
                            const int* __restrict__ flag, int E, int n) {
    int i = blockIdx.x * blockDim.x + threadIdx.x;
    int is64 = *flag;
    if (i < E) {
        int s, d;
        if (is64) {
            const long long* p = (const long long*)ei;
            s = (int)p[i];
            d = (int)p[(size_t)E + i];
        } else {
            const int* p = (const int*)ei;
            s = p[i];
            d = p[E + i];
        }
        src[i] = s;
        dst[i] = d;
        atomicAdd(&deg[d], 1);
    }
    if (i < n) {
        if (is64) role[i] = (int)((const long long*)rid)[i];
        else      role[i] = ((const int*)rid)[i];
    }
}

// ---------------- 2-phase scan ----------------
__global__ void scan_reduce_kernel(const int* __restrict__ deg, int* __restrict__ bsum, int n) {
    __shared__ int sw[32];
    int tid = threadIdx.x, lane = tid & 31, w = tid >> 5;
    int i = blockIdx.x * 1024 + tid;
    int v = (i < n) ? deg[i] : 0;
    v = warpSumI(v);
    if (lane == 0) sw[w] = v;
    __syncthreads();
    if (w == 0) {
        int t = sw[lane];
        t = warpSumI(t);
        if (lane == 0) bsum[blockIdx.x] = t;
    }
}

__global__ void scan_final_kernel(const int* __restrict__ deg, const int* __restrict__ bsum,
                                  int* __restrict__ rowptr, int* __restrict__ cursor, int n) {
    __shared__ int sw[32];
    __shared__ int partial[2];
    int tid = threadIdx.x, lane = tid & 31, w = tid >> 5;
    int bid = blockIdx.x;
    if (tid < 64) {
        int v = (tid < bid) ? bsum[tid] : 0;
        v = warpSumI(v);
        if ((tid & 31) == 0) partial[tid >> 5] = v;
    }
    int i = bid * 1024 + tid;
    int v = (i < n) ? deg[i] : 0;
    int iv = warpInclScan(v, lane);
    if (lane == 31) sw[w] = iv;
    __syncthreads();
    int base = partial[0] + partial[1];
    if (w == 0) {
        int t = sw[lane];
        t = warpInclScan(t, lane);
        sw[lane] = t;
    }
    __syncthreads();
    int offs = ((w > 0) ? sw[w - 1] : 0) + base;
    int incl = iv + offs;
    if (i < n) {
        rowptr[i + 1] = incl;
        cursor[i] = incl - v;
    }
    if (i == 0) rowptr[0] = 0;
}

__global__ void scatter_kernel(const int* __restrict__ src, const int* __restrict__ dst,
                               int* __restrict__ cursor, int* __restrict__ ecol, int E) {
    int i = blockIdx.x * blockDim.x + threadIdx.x;
    if (i >= E) return;
    int pos = atomicAdd(&cursor[dst[i]], 1);
    ecol[pos] = src[i];
}

// ---------------- role contribution precompute ----------------
__global__ void role_prep_kernel(const float* __restrict__ rt, const float* __restrict__ p1w,
                                 const float* __restrict__ p1b, float* __restrict__ rc) {
    int tid = threadIdx.x;
    int r = tid >> 6, j = tid & 63;
    float acc = p1b[j];
    #pragma unroll 8
    for (int k = 0; k < 64; k++)
        acc += rt[r * 64 + k] * p1w[j * 128 + 64 + k];
    rc[r * 64 + j] = acc;
}

// ---------------- BF16x3 tensor-core GEMM 128x128, Nc=256, fused scores ----------------
// A hi/lo, B hi/lo: packed words [row][KW] (word = bf16 pair of k=2w, 2w+1).
// 8 warps: wm=warp&3 (32 rows), wn=warp>>2 (64 cols). smem [kw][row] stride 136.
#define SBF 136
__global__ void __launch_bounds__(256) gemm_bf16(
        const unsigned* __restrict__ Ahi, const unsigned* __restrict__ Alo,
        const unsigned* __restrict__ Bhi, const unsigned* __restrict__ Blo,
        float* __restrict__ C, int M, int KW,
        const float* __restrict__ as_, const float* __restrict__ ad_,
        float* __restrict__ s_, float* __restrict__ d_, int H) {
    __shared__ unsigned AhiS[16 * SBF];
    __shared__ unsigned AloS[16 * SBF];
    __shared__ unsigned BhiS[16 * SBF];
    __shared__ unsigned BloS[16 * SBF];
    int tid = threadIdx.x, lane = tid & 31, warp = tid >> 5;
    int wm = warp & 3, wn = warp >> 2;
    int brow = blockIdx.y * 128, bcol = blockIdx.x * 128;
    float c[2][8][4];
    #pragma unroll
    for (int mt = 0; mt < 2; mt++)
        #pragma unroll
        for (int nt = 0; nt < 8; nt++)
            #pragma unroll
            for (int r = 0; r < 4; r++) c[mt][nt][r] = 0.f;

    int lrow = tid >> 1;
    int lkw = (tid & 1) * 8;
    int grow = brow + lrow;
    bool aok = grow < M;
    int gbrow = bcol + lrow;         // B "row" = output column; always < 256
    const int nch = KW >> 4;
    const uint4 z4 = make_uint4(0u, 0u, 0u, 0u);

    uint4 va0, va1, wa0, wa1, vb0, vb1, wb0, wb1;
    {
        int kw0 = lkw;
        va0 = aok ? *(const uint4*)&Ahi[(size_t)grow * KW + kw0] : z4;
        va1 = aok ? *(const uint4*)&Ahi[(size_t)grow * KW + kw0 + 4] : z4;
        wa0 = aok ? *(const uint4*)&Alo[(size_t)grow * KW + kw0] : z4;
        wa1 = aok ? *(const uint4*)&Alo[(size_t)grow * KW + kw0 + 4] : z4;
        vb0 = *(const uint4*)&Bhi[(size_t)gbrow * KW + kw0];
        vb1 = *(const uint4*)&Bhi[(size_t)gbrow * KW + kw0 + 4];
        wb0 = *(const uint4*)&Blo[(size_t)gbrow * KW + kw0];
        wb1 = *(const uint4*)&Blo[(size_t)gbrow * KW + kw0 + 4];
    }

    for (int ch = 0; ch < nch; ch++) {
        __syncthreads();   // smem reads of previous chunk done
        AhiS[(lkw + 0) * SBF + lrow] = va0.x; AhiS[(lkw + 1) * SBF + lrow] = va0.y;
        AhiS[(lkw + 2) * SBF + lrow] = va0.z; AhiS[(lkw + 3) * SBF + lrow] = va0.w;
        AhiS[(lkw + 4) * SBF + lrow] = va1.x; AhiS[(lkw + 5) * SBF + lrow] = va1.y;
        AhiS[(lkw + 6) * SBF + lrow] = va1.z; AhiS[(lkw + 7) * SBF + lrow] = va1.w;
        AloS[(lkw + 0) * SBF + lrow] = wa0.x; AloS[(lkw + 1) * SBF + lrow] = wa0.y;
        AloS[(lkw + 2) * SBF + lrow] = wa0.z; AloS[(lkw + 3) * SBF + lrow] = wa0.w;
        AloS[(lkw + 4) * SBF + lrow] = wa1.x; AloS[(lkw + 5) * SBF + lrow] = wa1.y;
        AloS[(lkw + 6) * SBF + lrow] = wa1.z; AloS[(lkw + 7) * SBF + lrow] = wa1.w;
        BhiS[(lkw + 0) * SBF + lrow] = vb0.x; BhiS[(lkw + 1) * SBF + lrow] = vb0.y;
        BhiS[(lkw + 2) * SBF + lrow] = vb0.z; BhiS[(lkw + 3) * SBF + lrow] = vb0.w;
        BhiS[(lkw + 4) * SBF + lrow] = vb1.x; BhiS[(lkw + 5) * SBF + lrow] = vb1.y;
        BhiS[(lkw + 6) * SBF + lrow] = vb1.z; BhiS[(lkw + 7) * SBF + lrow] = vb1.w;
        BloS[(lkw + 0) * SBF + lrow] = wb0.x; BloS[(lkw + 1) * SBF + lrow] = wb0.y;
        BloS[(lkw + 2) * SBF + lrow] = wb0.z; BloS[(lkw + 3) * SBF + lrow] = wb0.w;
        BloS[(lkw + 4) * SBF + lrow] = wb1.x; BloS[(lkw + 5) * SBF + lrow] = wb1.y;
        BloS[(lkw + 6) * SBF + lrow] = wb1.z; BloS[(lkw + 7) * SBF + lrow] = wb1.w;
        __syncthreads();

        if (ch + 1 < nch) {          // prefetch next chunk; overlaps with mma below
            int kw0 = (ch + 1) * 16 + lkw;
            va0 = aok ? *(const uint4*)&Ahi[(size_t)grow * KW + kw0] : z4;
            va1 = aok ? *(const uint4*)&Ahi[(size_t)grow * KW + kw0 + 4] : z4;
            wa0 = aok ? *(const uint4*)&Alo[(size_t)grow * KW + kw0] : z4;
            wa1 = aok ? *(const uint4*)&Alo[(size_t)grow * KW + kw0 + 4] : z4;
            vb0 = *(const uint4*)&Bhi[(size_t)gbrow * KW + kw0];
            vb1 = *(const uint4*)&Bhi[(size_t)gbrow * KW + kw0 + 4];
            wb0 = *(const uint4*)&Blo[(size_t)gbrow * KW + kw0];
            wb1 = *(const uint4*)&Blo[(size_t)gbrow * KW + kw0 + 4];
        }

        #pragma unroll
        for (int kg = 0; kg < 2; kg++) {
            int kc = kg * 8 + (lane & 3);
            unsigned ah[2][4], al[2][4];
            #pragma unroll
            for (int mt = 0; mt < 2; mt++) {
                int r = wm * 32 + mt * 16 + (lane >> 2);
                ah[mt][0] = AhiS[kc * SBF + r];
                ah[mt][1] = AhiS[kc * SBF + r + 8];
                ah[mt][2] = AhiS[(kc + 4) * SBF + r];
                ah[mt][3] = AhiS[(kc + 4) * SBF + r + 8];
                al[mt][0] = AloS[kc * SBF + r];
                al[mt][1] = AloS[kc * SBF + r + 8];
                al[mt][2] = AloS[(kc + 4) * SBF + r];
                al[mt][3] = AloS[(kc + 4) * SBF + r + 8];
            }
            #pragma unroll
            for (int nt = 0; nt < 8; nt++) {
                int nc = wn * 64 + nt * 8 + (lane >> 2);
                unsigned bh[2], bl[2];
                bh[0] = BhiS[kc * SBF + nc];
                bh[1] = BhiS[(kc + 4) * SBF + nc];
                bl[0] = BloS[kc * SBF + nc];
                bl[1] = BloS[(kc + 4) * SBF + nc];
                MMA_BF16(c[0][nt], ah[0], bh);
                MMA_BF16(c[1][nt], ah[1], bh);
                MMA_BF16(c[0][nt], ah[0], bl);
                MMA_BF16(c[1][nt], ah[1], bl);
                MMA_BF16(c[0][nt], al[0], bh);
                MMA_BF16(c[1][nt], al[1], bh);
            }
        }
    }

    // store C
    #pragma unroll
    for (int mt = 0; mt < 2; mt++) {
        #pragma unroll
        for (int nt = 0; nt < 8; nt++) {
            int row = brow + wm * 32 + mt * 16 + (lane >> 2);
            int col = bcol + wn * 64 + nt * 8 + 2 * (lane & 3);
            if (row < M)
                *(float2*)&C[(size_t)row * 256 + col] = make_float2(c[mt][nt][0], c[mt][nt][1]);
            if (row + 8 < M)
                *(float2*)&C[(size_t)(row + 8) * 256 + col] = make_float2(c[mt][nt][2], c[mt][nt][3]);
        }
    }

    // fused score epilogue: this warp's 64 cols = head (bx*2 + wn)
    int head = blockIdx.x * 2 + wn;
    float asv[8][2], adv[8][2];
    #pragma unroll
    for (int nt = 0; nt < 8; nt++) {
        int cc = nt * 8 + 2 * (lane & 3);
        asv[nt][0] = as_[head * 64 + cc];
        asv[nt][1] = as_[head * 64 + cc + 1];
        adv[nt][0] = ad_[head * 64 + cc];
        adv[nt][1] = ad_[head * 64 + cc + 1];
    }
    #pragma unroll
    for (int mt = 0; mt < 2; mt++) {
        #pragma unroll
        for (int p = 0; p < 2; p++) {
            float ss = 0.f, dd = 0.f;
            #pragma unroll
            for (int nt = 0; nt < 8; nt++) {
                ss += c[mt][nt][p * 2] * asv[nt][0] + c[mt][nt][p * 2 + 1] * asv[nt][1];
                dd += c[mt][nt][p * 2] * adv[nt][0] + c[mt][nt][p * 2 + 1] * adv[nt][1];
            }
            ss += __shfl_xor_sync(0xffffffffu, ss, 1);
            ss += __shfl_xor_sync(0xffffffffu, ss, 2);
            dd += __shfl_xor_sync(0xffffffffu, dd, 1);
            dd += __shfl_xor_sync(0xffffffffu, dd, 2);
            int row = brow + wm * 32 + mt * 16 + (lane >> 2) + p * 8;
            if ((lane & 3) == 0 && row < M) {
                s_[(size_t)row * H + head] = ss;
                d_[(size_t)row * H + head] = dd;
            }
        }
    }
}

// ---------------- FFMA2 GEMM 128x64 (layer 3), Nc=64, H=1 ----------------
__global__ void __launch_bounds__(128) gemm_nt64(
        const float* __restrict__ A, const float* __restrict__ B,
        float* __restrict__ C, int M, int K,
        const float* __restrict__ as_, const float* __restrict__ ad_,
        float* __restrict__ s_, float* __restrict__ d_) {
    __shared__ float As[2][16][132];
    __shared__ float Bs[2][16][68];
    int tid = threadIdx.x;
    int lane = tid & 31;
    int brow = blockIdx.x * 128;
    int tr = tid >> 3, tc = tid & 7;
    unsigned long long accP[4][8];
    #pragma unroll
    for (int p = 0; p < 4; p++)
        #pragma unroll
        for (int j = 0; j < 8; j++) accP[p][j] = 0ull;

    int lrowA[4], lkqA[4];
    #pragma unroll
    for (int t = 0; t < 4; t++) { int li = tid + t * 128; lrowA[t] = li >> 2; lkqA[t] = (li & 3) * 4; }
    int lrowB[2], lkqB[2];
    #pragma unroll
    for (int t = 0; t < 2; t++) { int li = tid + t * 128; lrowB[t] = li >> 2; lkqB[t] = (li & 3) * 4; }
    float4 aReg[4], bReg[2];
    const int nch = K / 16;

    #pragma unroll
    for (int t = 0; t < 4; t++) {
        int gm = brow + lrowA[t];
        aReg[t] = (gm < M) ? *(const float4*)&A[(size_t)gm * K + lkqA[t]]
                           : make_float4(0.f, 0.f, 0.f, 0.f);
    }
    #pragma unroll
    for (int t = 0; t < 2; t++)
        bReg[t] = *(const float4*)&B[(size_t)lrowB[t] * K + lkqB[t]];
    #pragma unroll
    for (int t = 0; t < 4; t++) {
        As[0][lkqA[t] + 0][lrowA[t]] = aReg[t].x; As[0][lkqA[t] + 1][lrowA[t]] = aReg[t].y;
        As[0][lkqA[t] + 2][lrowA[t]] = aReg[t].z; As[0][lkqA[t] + 3][lrowA[t]] = aReg[t].w;
    }
    #pragma unroll
    for (int t = 0; t < 2; t++) {
        Bs[0][lkqB[t] + 0][lrowB[t]] = bReg[t].x; Bs[0][lkqB[t] + 1][lrowB[t]] = bReg[t].y;
        Bs[0][lkqB[t] + 2][lrowB[t]] = bReg[t].z; Bs[0][lkqB[t] + 3][lrowB[t]] = bReg[t].w;
    }
    __syncthreads();

    for (int c = 0; c < nch; c++) {
        int buf = c & 1;
        if (c + 1 < nch) {
            int k0 = (c + 1) * 16;
            #pragma unroll
            for (int t = 0; t < 4; t++) {
                int gm = brow + lrowA[t];
                aReg[t] = (gm < M) ? *(const float4*)&A[(size_t)gm * K + k0 + lkqA[t]]
                                   : make_float4(0.f, 0.f, 0.f, 0.f);
            }
            #pragma unroll
            for (int t = 0; t < 2; t++)
                bReg[t] = *(const float4*)&B[(size_t)lrowB[t] * K + k0 + lkqB[t]];
        }
        #pragma unroll
        for (int kk = 0; kk < 16; kk++) {
            float4 va0 = *(float4*)&As[buf][kk][tr * 8];
            float4 va1 = *(float4*)&As[buf][kk][tr * 8 + 4];
            float4 vb0 = *(float4*)&Bs[buf][kk][tc * 8];
            float4 vb1 = *(float4*)&Bs[buf][kk][tc * 8 + 4];
            unsigned long long a2[4], bd[8];
            PACK2(a2[0], va0.x, va0.y); PACK2(a2[1], va0.z, va0.w);
            PACK2(a2[2], va1.x, va1.y); PACK2(a2[3], va1.z, va1.w);
            DUP2(bd[0], vb0.x); DUP2(bd[1], vb0.y); DUP2(bd[2], vb0.z); DUP2(bd[3], vb0.w);
            DUP2(bd[4], vb1.x); DUP2(bd[5], vb1.y); DUP2(bd[6], vb1.z); DUP2(bd[7], vb1.w);
            #pragma unroll
            for (int p = 0; p < 4; p++)
                #pragma unroll
                for (int j = 0; j < 8; j++) FMA2(accP[p][j], a2[p], bd[j]);
        }
        if (c + 1 < nch) {
            int nb = buf ^ 1;
            #pragma unroll
            for (int t = 0; t < 4; t++) {
                As[nb][lkqA[t] + 0][lrowA[t]] = aReg[t].x; As[nb][lkqA[t] + 1][lrowA[t]] = aReg[t].y;
                As[nb][lkqA[t] + 2][lrowA[t]] = aReg[t].z; As[nb][lkqA[t] + 3][lrowA[t]] = aReg[t].w;
            }
            #pragma unroll
            for (int t = 0; t < 2; t++) {
                Bs[nb][lkqB[t] + 0][lrowB[t]] = bReg[t].x; Bs[nb][lkqB[t] + 1][lrowB[t]] = bReg[t].y;
                Bs[nb][lkqB[t] + 2][lrowB[t]] = bReg[t].z; Bs[nb][lkqB[t] + 3][lrowB[t]] = bReg[t].w;
            }
        }
        __syncthreads();
    }

    float acc[8][8];
    #pragma unroll
    for (int p = 0; p < 4; p++)
        #pragma unroll
        for (int j = 0; j < 8; j++) UNPACK2(acc[2 * p][j], acc[2 * p + 1][j], accP[p][j]);

    #pragma unroll
    for (int i = 0; i < 8; i++) {
        int gm = brow + tr * 8 + i;
        if (gm >= M) continue;
        *(float4*)&C[(size_t)gm * 64 + tc * 8] =
            make_float4(acc[i][0], acc[i][1], acc[i][2], acc[i][3]);
        *(float4*)&C[(size_t)gm * 64 + tc * 8 + 4] =
            make_float4(acc[i][4], acc[i][5], acc[i][6], acc[i][7]);
    }

    float asv[8], adv[8];
    #pragma unroll
    for (int j = 0; j < 8; j++) {
        asv[j] = as_[tc * 8 + j];
        adv[j] = ad_[tc * 8 + j];
    }
    #pragma unroll
    for (int i = 0; i < 8; i++) {
        float ss = 0.f, dd = 0.f;
        #pragma unroll
        for (int j = 0; j < 8; j++) {
            ss += acc[i][j] * asv[j];
            dd += acc[i][j] * adv[j];
        }
        #pragma unroll
        for (int o = 4; o >= 1; o >>= 1) {
            ss += __shfl_xor_sync(0xffffffffu, ss, o);
            dd += __shfl_xor_sync(0xffffffffu, dd, o);
        }
        int gm = brow + tr * 8 + i;
        if ((lane & 7) == 0 && gm < M) {
            s_[gm] = ss;
            d_[gm] = dd;
        }
    }
}

// ---------------- fused GAT layer, H=4 (optional bf16-split output) ----------
__global__ void gat_fused4(const int* __restrict__ rowptr, const int* __restrict__ ecol,
                           const float* __restrict__ s_, const float* __restrict__ d_,
                           const float* __restrict__ h, const float* __restrict__ bias,
                           const float* __restrict__ lw, const float* __restrict__ lb,
                           float* __restrict__ outp, unsigned* __restrict__ xhi,
                           unsigned* __restrict__ xlo, int n, int do_elu, int splitOut) {
    int warp = (blockIdx.x * blockDim.x + threadIdx.x) >> 5;
    int lane = threadIdx.x & 31;
    if (warp >= n) return;
    int node = warp;
    int start = rowptr[node], end = rowptr[node + 1];

    float4 dv4 = ((const float4*)d_)[node];
    float dsel[4] = {dv4.x, dv4.y, dv4.z, dv4.w};
    float4 sv4 = ((const float4*)s_)[node];
    float selfv[4] = {leaky(sv4.x + dsel[0]), leaky(sv4.y + dsel[1]),
                      leaky(sv4.z + dsel[2]), leaky(sv4.w + dsel[3])};

    float m[4], s[4];
    #pragma unroll
    for (int q = 0; q < 4; q++) {
        m[q] = (lane == 0) ? selfv[q] : -3e38f;
        s[q] = (lane == 0) ? 1.f : 0.f;
    }
    for (int e = start + lane; e < end; e += 32) {
        int src = ecol[e];
        float4 sv = ((const float4*)s_)[src];
        float v[4] = {leaky(sv.x + dsel[0]), leaky(sv.y + dsel[1]),
                      leaky(sv.z + dsel[2]), leaky(sv.w + dsel[3])};
        #pragma unroll
        for (int q = 0; q < 4; q++) {
            float nm = fmaxf(m[q], v[q]);
            s[q] = s[q] * expf(m[q] - nm) + expf(v[q] - nm);
            m[q] = nm;
        }
    }
    #pragma unroll
    for (int o = 16; o > 0; o >>= 1) {
        #pragma unroll
        for (int q = 0; q < 4; q++) {
            float om = __shfl_xor_sync(0xffffffffu, m[q], o);
            float os = __shfl_xor_sync(0xffffffffu, s[q], o);
            float nm = fmaxf(m[q], om);
            s[q] = s[q] * expf(m[q] - nm) + os * expf(om - nm);
            m[q] = nm;
        }
    }
    float inv[4], aself[4];
    #pragma unroll
    for (int q = 0; q < 4; q++) {
        inv[q] = 1.f / (s[q] + 1e-16f);
        aself[q] = expf(selfv[q] - m[q]) * inv[q];
    }

    int hl = lane & 3;
    float d_hl = (hl == 0) ? dsel[0] : (hl == 1) ? dsel[1] : (hl == 2) ? dsel[2] : dsel[3];
    float m_hl = (hl == 0) ? m[0]    : (hl == 1) ? m[1]    : (hl == 2) ? m[2]    : m[3];
    float i_hl = (hl == 0) ? inv[0]  : (hl == 1) ? inv[1]  : (hl == 2) ? inv[2]  : inv[3];
    int hA = lane >> 4;
    float asA = hA ? aself[1] : aself[0];
    float asB = hA ? aself[3] : aself[2];

    const float4* hps4 = (const float4*)(h + (size_t)node * 256);
    float4 acc0 = f4scale(hps4[lane], asA);
    float4 acc1 = f4scale(hps4[lane + 32], asB);

    for (int e0 = start; e0 < end; e0 += 8) {
        int me = e0 + (lane >> 2);
        float alpha = 0.f; int msrc = 0;
        if (me < end) {
            msrc = ecol[me];
            float v = leaky(s_[(size_t)msrc * 4 + hl] + d_hl);
            alpha = expf(v - m_hl) * i_hl;
        }
        int cnt = end - e0; if (cnt > 8) cnt = 8;
        for (int j0 = 0; j0 < cnt; j0 += 4) {
            int jn = cnt - j0; if (jn > 4) jn = 4;
            float4 pa[4], pb[4];
            float a0[4], a1[4];
            #pragma unroll
            for (int j = 0; j < 4; j++) {
                int src = __shfl_sync(0xffffffffu, msrc, (j0 + j) * 4);
                a0[j] = __shfl_sync(0xffffffffu, alpha, (j0 + j) * 4 + hA);
                a1[j] = __shfl_sync(0xffffffffu, alpha, (j0 + j) * 4 + 2 + hA);
                if (j < jn) {
                    const float4* hp4 = (const float4*)(h + (size_t)src * 256);
                    pa[j] = hp4[lane];
                    pb[j] = hp4[lane + 32];
                }
            }
            #pragma unroll
            for (int j = 0; j < 4; j++) {
                if (j < jn) {
                    acc0 = f4fma(pa[j], a0[j], acc0);
                    acc1 = f4fma(pb[j], a1[j], acc1);
                }
            }
        }
    }

    const float4* b4 = (const float4*)bias;
    const float4* lw4 = (const float4*)lw;
    const float4* lb4 = (const float4*)lb;
    float4 v0 = f4add(acc0, b4[lane]);
    float4 v1 = f4add(acc1, b4[lane + 32]);
    if (do_elu) {
        v0.x = v0.x > 0.f ? v0.x : expf(v0.x) - 1.f;
        v0.y = v0.y > 0.f ? v0.y : expf(v0.y) - 1.f;
        v0.z = v0.z > 0.f ? v0.z : expf(v0.z) - 1.f;
        v0.w = v0.w > 0.f ? v0.w : expf(v0.w) - 1.f;
        v1.x = v1.x > 0.f ? v1.x : expf(v1.x) - 1.f;
        v1.y = v1.y > 0.f ? v1.y : expf(v1.y) - 1.f;
        v1.z = v1.z > 0.f ? v1.z : expf(v1.z) - 1.f;
        v1.w = v1.w > 0.f ? v1.w : expf(v1.w) - 1.f;
    }
    float ssum = v0.x + v0.y + v0.z + v0.w + v1.x + v1.y + v1.z + v1.w;
    ssum = warpSum(ssum);
    float mu = ssum * (1.f / 256.f);
    float t, vs = 0.f;
    t = v0.x - mu; vs += t * t; t = v0.y - mu; vs += t * t;
    t = v0.z - mu; vs += t * t; t = v0.w - mu; vs += t * t;
    t = v1.x - mu; vs += t * t; t = v1.y - mu; vs += t * t;
    t = v1.z - mu; vs += t * t; t = v1.w - mu; vs += t * t;
    vs = warpSum(vs);
    float rs = rsqrtf(vs * (1.f / 256.f) + 1e-5f);
    float4 w0 = lw4[lane], w1 = lw4[lane + 32];
    float4 c0 = lb4[lane], c1 = lb4[lane + 32];
    float4 o0 = make_float4((v0.x - mu) * rs * w0.x + c0.x, (v0.y - mu) * rs * w0.y + c0.y,
                            (v0.z - mu) * rs * w0.z + c0.z, (v0.w - mu) * rs * w0.w + c0.w);
    float4 o1 = make_float4((v1.x - mu) * rs * w1.x + c1.x, (v1.y - mu) * rs * w1.y + c1.y,
                            (v1.z - mu) * rs * w1.z + c1.z, (v1.w - mu) * rs * w1.w + c1.w);
    float4* out4 = (float4*)(outp + (size_t)node * 256);
    out4[lane] = o0;
    out4[lane + 32] = o1;

    if (splitOut) {
        unsigned* xh = xhi + (size_t)node * 128;
        unsigned* xl = xlo + (size_t)node * 128;
        *(uint2*)&xh[lane * 2] = make_uint2(packbf(o0.x, o0.y), packbf(o0.z, o0.w));
        *(uint2*)&xh[64 + lane * 2] = make_uint2(packbf(o1.x, o1.y), packbf(o1.z, o1.w));
        *(uint2*)&xl[lane * 2] = make_uint2(
            packbf(o0.x - bfr(o0.x), o0.y - bfr(o0.y)),
            packbf(o0.z - bfr(o0.z), o0.w - bfr(o0.w)));
        *(uint2*)&xl[64 + lane * 2] = make_uint2(
            packbf(o1.x - bfr(o1.x), o1.y - bfr(o1.y)),
            packbf(o1.z - bfr(o1.z), o1.w - bfr(o1.w)));
    }
}

// ---------------- fused GAT layer, H=1 (D=64) ----------
__global__ void gat_fused1(const int* __restrict__ rowptr, const int* __restrict__ ecol,
                           const float* __restrict__ s_, const float* __restrict__ d_,
                           const float* __restrict__ h, const float* __restrict__ bias,
                           const float* __restrict__ lw, const float* __restrict__ lb,
                           float* __restrict__ outp, int n, int do_elu) {
    int warp = (blockIdx.x * blockDim.x + threadIdx.x) >> 5;
    int lane = threadIdx.x & 31;
    if (warp >= n) return;
    int node = warp;
    int start = rowptr[node], end = rowptr[node + 1];

    float dsel = d_[node];
    float selfv = leaky(s_[node] + dsel);
    float m = (lane == 0) ? selfv : -3e38f;
    float s = (lane == 0) ? 1.f : 0.f;
    for (int e = start + lane; e < end; e += 32) {
        float v = leaky(s_[ecol[e]] + dsel);
        float nm = fmaxf(m, v);
        s = s * expf(m - nm) + expf(v - nm);
        m = nm;
    }
    #pragma unroll
    for (int o = 16; o > 0; o >>= 1) {
        float om = __shfl_xor_sync(0xffffffffu, m, o);
        float os = __shfl_xor_sync(0xffffffffu, s, o);
        float nm = fmaxf(m, om);
        s = s * expf(m - nm) + os * expf(om - nm);
        m = nm;
    }
    float inv = 1.f / (s + 1e-16f);
    float aself = expf(selfv - m) * inv;

    int half = lane >> 4, f = lane & 15;
    const float4* hps4 = (const float4*)(h + (size_t)node * 64);
    float4 acc = (half == 0) ? f4scale(hps4[f], aself) : make_float4(0.f, 0.f, 0.f, 0.f);

    for (int e0 = start; e0 < end; e0 += 8) {
        int me = e0 + lane;
        float alpha = 0.f; int msrc = 0;
        if (lane < 8 && me < end) {
            msrc = ecol[me];
            alpha = expf(leaky(s_[msrc] + dsel) - m) * inv;
        }
        int cnt = end - e0; if (cnt > 8) cnt = 8;
        for (int j = 0; j < cnt; j += 2) {
            int eidx = j + half;
            int src = __shfl_sync(0xffffffffu, msrc, eidx);
            float al = __shfl_sync(0xffffffffu, alpha, eidx);
            if (eidx < cnt) {
                const float4* hp4 = (const float4*)(h + (size_t)src * 64);
                acc = f4fma(hp4[f], al, acc);
            }
        }
    }
    acc.x += __shfl_xor_sync(0xffffffffu, acc.x, 16);
    acc.y += __shfl_xor_sync(0xffffffffu, acc.y, 16);
    acc.z += __shfl_xor_sync(0xffffffffu, acc.z, 16);
    acc.w += __shfl_xor_sync(0xffffffffu, acc.w, 16);

    const float4* b4 = (const float4*)bias;
    const float4* lw4 = (const float4*)lw;
    const float4* lb4 = (const float4*)lb;
    float4 v = f4add(acc, b4[f]);
    if (do_elu) {
        v.x = v.x > 0.f ? v.x : expf(v.x) - 1.f;
        v.y = v.y > 0.f ? v.y : expf(v.y) - 1.f;
        v.z = v.z > 0.f ? v.z : expf(v.z) - 1.f;
        v.w = v.w > 0.f ? v.w : expf(v.w) - 1.f;
    }
    float ssum = warpSum(v.x + v.y + v.z + v.w);
    float mu = ssum * (1.f / 128.f);
    float t, vs = 0.f;
    t = v.x - mu; vs += t * t; t = v.y - mu; vs += t * t;
    t = v.z - mu; vs += t * t; t = v.w - mu; vs += t * t;
    vs = warpSum(vs);
    float rs = rsqrtf(vs * (1.f / 128.f) + 1e-5f);
    if (half == 0) {
        float4 w = lw4[f], c = lb4[f];
        float4* out4 = (float4*)(outp + (size_t)node * 64);
        out4[f] = make_float4((v.x - mu) * rs * w.x + c.x, (v.y - mu) * rs * w.y + c.y,
                              (v.z - mu) * rs * w.z + c.z, (v.w - mu) * rs * w.w + c.w);
    }
}

// ---------------- final MLP head ----------------
__global__ void head_kernel(const float* __restrict__ h3, const int* __restrict__ role,
                            const float* __restrict__ rc, const float* __restrict__ p1w,
                            const float* __restrict__ p2w, const float* __restrict__ p2b,
                            float* __restrict__ z, int n) {
    extern __shared__ float sm[];
    float* sp1 = sm;
    float* sp2 = sp1 + 64 * 64;
    float* sz  = sp2 + 64 * 64;
    float* sz1 = sz + 4 * 64;
    int tid = threadIdx.x;
    for (int i = tid; i < 64 * 64; i += 256) {
        int j = i >> 6, k = i & 63;
        sp1[k * 64 + j] = p1w[j * 128 + k];
        sp2[k * 64 + j] = p2w[i];
    }
    __syncthreads();
    int g = tid >> 6, j = tid & 63;
    float b2v = p2b[j];
    for (int it = 0; it < 16; it++) {
        int node = blockIdx.x * 64 + it * 4 + g;
        bool valid = node < n;
        float rcv = 0.f;
        if (valid) {
            sz[g * 64 + j] = h3[(size_t)node * 64 + j];
            rcv = rc[role[node] * 64 + j];
        }
        __syncthreads();
        float acc = rcv;
        #pragma unroll 8
        for (int k = 0; k < 64; k++) acc += sp1[k * 64 + j] * sz[g * 64 + k];
        sz1[g * 64 + j] = fmaxf(acc, 0.f);
        __syncthreads();
        float acc2 = b2v;
        #pragma unroll 8
        for (int k = 0; k < 64; k++) acc2 += sp2[k * 64 + j] * sz1[g * 64 + k];
        if (valid) z[(size_t)node * 64 + j] = acc2;
    }
}

// ---------------- host orchestration ----------------
extern "C" void kernel_launch(void* const* d_in, const int* in_sizes, int n_in,
                              void* d_out, int out_size) {
    const float* x   = (const float*)d_in[0];
    const void*  ei  = d_in[1];
    const void*  rid = d_in[2];
    const float* W1  = (const float*)d_in[3];
    const float* a1s = (const float*)d_in[4];
    const float* a1d = (const float*)d_in[5];
    const float* b1  = (const float*)d_in[6];
    const float* W2  = (const float*)d_in[7];
    const float* a2s = (const float*)d_in[8];
    const float* a2d = (const float*)d_in[9];
    const float* b2  = (const float*)d_in[10];
    const float* W3  = (const float*)d_in[11];
    const float* a3s = (const float*)d_in[12];
    const float* a3d = (const float*)d_in[13];
    const float* b3  = (const float*)d_in[14];
    const float* ln1w = (const float*)d_in[15];
    const float* ln1b = (const float*)d_in[16];
    const float* ln2w = (const float*)d_in[17];
    const float* ln2b = (const float*)d_in[18];
    const float* ln3w = (const float*)d_in[19];
    const float* ln3b = (const float*)d_in[20];
    const float* rt   = (const float*)d_in[21];
    const float* p1w  = (const float*)d_in[22];
    const float* p1b  = (const float*)d_in[23];
    const float* p2w  = (const float*)d_in[24];
    const float* p2b  = (const float*)d_in[25];
    float* z = (float*)d_out;

    float *hbuf, *xbuf, *ybuf, *sp, *dp, *rcp;
    unsigned *xhip, *xlop, *whip, *wlop;
    int *srcp, *dstp, *ecolp, *rowp, *degp, *curp, *bsump, *rolep, *flagp;
    cudaGetSymbolAddress((void**)&hbuf, g_h);
    cudaGetSymbolAddress((void**)&xbuf, g_x);
    cudaGetSymbolAddress((void**)&ybuf, g_y);
    cudaGetSymbolAddress((void**)&sp, g_s);
    cudaGetSymbolAddress((void**)&dp, g_d);
    cudaGetSymbolAddress((void**)&rcp, g_rc);
    cudaGetSymbolAddress((void**)&xhip, g_xhi);
    cudaGetSymbolAddress((void**)&xlop, g_xlo);
    cudaGetSymbolAddress((void**)&whip, g_whi);
    cudaGetSymbolAddress((void**)&wlop, g_wlo);
    cudaGetSymbolAddress((void**)&srcp, g_src);
    cudaGetSymbolAddress((void**)&dstp, g_dst);
    cudaGetSymbolAddress((void**)&ecolp, g_ecol);
    cudaGetSymbolAddress((void**)&rowp, g_rowptr);
    cudaGetSymbolAddress((void**)&degp, g_deg);
    cudaGetSymbolAddress((void**)&curp, g_cursor);
    cudaGetSymbolAddress((void**)&bsump, g_bsum);
    cudaGetSymbolAddress((void**)&rolep, g_role);
    cudaGetSymbolAddress((void**)&flagp, g_is64);

    const int n = NN, E = EE;
    const int nb = (n + 1023) / 1024;

    dim3 gg(2, (n + 127) / 128);           // bf16 GEMM: 2 col-blocks x 391 row-blocks
    int g3blocks = (n + 127) / 128;
    int fusedBlocks = (n * 32 + 255) / 256;

    // conversions first (no deps) so gemm1 stays in the ncu capture slot
    split_kernel<<<(n * 64 / 4 + 255) / 256, 256>>>(x, xhip, xlop, n * 64 / 4);   // x: KW=32
    split_kernel<<<16, 256>>>(W1, whip, wlop, 256 * 64 / 4);                       // W1: KW=32
    detect_kernel<<<1, 32>>>((const unsigned int*)ei, flagp);
    cudaMemsetAsync(degp, 0, n * sizeof(int));
    gemm_bf16<<<gg, 256>>>(xhip, xlop, whip, wlop, hbuf, n, 32, a1s, a1d, sp, dp, 4);
    prep_kernel<<<(E + 255) / 256, 256>>>(ei, rid, srcp, dstp, degp, rolep, flagp, E, n);
    scan_reduce_kernel<<<nb, 1024>>>(degp, bsump, n);
    scan_final_kernel<<<nb, 1024>>>(degp, bsump, rowp, curp, n);
    scatter_kernel<<<(E + 255) / 256, 256>>>(srcp, dstp, curp, ecolp, E);
    role_prep_kernel<<<1, 128>>>(rt, p1w, p1b, rcp);

    // layer 1 gather (also emits bf16-split output for layer-2 GEMM A)
    gat_fused4<<<fusedBlocks, 256>>>(rowp, ecolp, sp, dp, hbuf, b1, ln1w, ln1b,
                                     xbuf, xhip, xlop, n, 1, 1);

    // layer 2
    split_kernel<<<64, 256>>>(W2, whip, wlop, 256 * 256 / 4);                      // W2: KW=128
    gemm_bf16<<<gg, 256>>>(xhip, xlop, whip, wlop, hbuf, n, 128, a2s, a2d, sp, dp, 4);
    gat_fused4<<<fusedBlocks, 256>>>(rowp, ecolp, sp, dp, hbuf, b2, ln2w, ln2b,
                                     xbuf, xhip, xlop, n, 1, 0);

    // layer 3 (fp32 FFMA2 path)
    gemm_nt64<<<g3blocks, 128>>>(xbuf, W3, hbuf, n, 256, a3s, a3d, sp, dp);
    gat_fused1<<<fusedBlocks, 256>>>(rowp, ecolp, sp, dp, hbuf, b3, ln3w, ln3b, ybuf, n, 0);

    // final MLP head
    size_t smem = (64 * 64 + 64 * 64 + 4 * 64 + 4 * 64) * sizeof(float);
    cudaFuncSetAttribute(head_kernel, cudaFuncAttributeMaxDynamicSharedMemorySize, (int)smem);
    head_kernel<<<(n + 63) / 64, 256, smem>>>(ybuf, rolep, rcp, p1w, p2w, p2b, z, n);
}

// round 13
// speedup vs baseline: 1.1593x; 1.0651x over previous
#include <cuda_runtime.h>
#include <cuda_bf16.h>
#include <math.h>

#define NN 50000
#define EE 400000
#define DMAX 256

// ---------------- scratch ----------------
__device__ float g_h[(size_t)NN * DMAX];
__device__ float g_x[(size_t)NN * DMAX];
__device__ float g_y[(size_t)NN * DMAX];
__device__ float g_s[NN * 4];
__device__ float g_d[NN * 4];
__device__ float g_rc[2 * 64];
__device__ unsigned g_xhi[(size_t)NN * 128];
__device__ unsigned g_xlo[(size_t)NN * 128];
__device__ unsigned g_whi[256 * 128];
__device__ unsigned g_wlo[256 * 128];
__device__ int g_src[EE];
__device__ int g_dst[EE];
__device__ int g_ecol[EE];
__device__ int g_rowptr[NN + 1];
__device__ int g_deg[NN];
__device__ int g_cursor[NN];
__device__ int g_bsum[64];
__device__ int g_role[NN];
__device__ int g_is64;

// ---------------- helpers ----------------
__device__ __forceinline__ float warpSum(float v) {
    #pragma unroll
    for (int o = 16; o > 0; o >>= 1) v += __shfl_xor_sync(0xffffffffu, v, o);
    return v;
}
__device__ __forceinline__ int warpSumI(int v) {
    #pragma unroll
    for (int o = 16; o > 0; o >>= 1) v += __shfl_xor_sync(0xffffffffu, v, o);
    return v;
}
__device__ __forceinline__ int warpInclScan(int v, int lane) {
    #pragma unroll
    for (int o = 1; o < 32; o <<= 1) {
        int t = __shfl_up_sync(0xffffffffu, v, o);
        if (lane >= o) v += t;
    }
    return v;
}
__device__ __forceinline__ float leaky(float v) { return fmaxf(v, 0.2f * v); }
__device__ __forceinline__ float4 f4fma(float4 a, float s, float4 c) {
    c.x += a.x * s; c.y += a.y * s; c.z += a.z * s; c.w += a.w * s; return c;
}
__device__ __forceinline__ float4 f4scale(float4 a, float s) {
    return make_float4(a.x * s, a.y * s, a.z * s, a.w * s);
}
__device__ __forceinline__ float4 f4add(float4 a, float4 b) {
    return make_float4(a.x + b.x, a.y + b.y, a.z + b.z, a.w + b.w);
}

// packed f32x2 ops (for FFMA2 gemm_nt64)
#define PACK2(d, x, y) asm("mov.b64 %0, {%1, %2};" : "=l"(d) : "f"(x), "f"(y))
#define DUP2(d, x)     asm("mov.b64 %0, {%1, %1};" : "=l"(d) : "f"(x))
#define FMA2(c, a, b)  asm("fma.rn.f32x2 %0, %1, %2, %0;" : "+l"(c) : "l"(a), "l"(b))
#define UNPACK2(x, y, d) asm("mov.b64 {%0, %1}, %2;" : "=f"(x), "=f"(y) : "l"(d))

// bf16 helpers
__device__ __forceinline__ unsigned packbf(float lo_elem, float hi_elem) {
    unsigned r;
    asm("cvt.rn.bf16x2.f32 %0, %1, %2;" : "=r"(r) : "f"(hi_elem), "f"(lo_elem));
    return r;
}
__device__ __forceinline__ float bfr(float f) {
    return __bfloat162float(__float2bfloat16(f));
}

#define MMA_BF16(c, a, b)                                                        \
    asm volatile("mma.sync.aligned.m16n8k16.row.col.f32.bf16.bf16.f32 "          \
                 "{%0,%1,%2,%3}, {%4,%5,%6,%7}, {%8,%9}, {%0,%1,%2,%3};"         \
                 : "+f"((c)[0]), "+f"((c)[1]), "+f"((c)[2]), "+f"((c)[3])        \
                 : "r"((a)[0]), "r"((a)[1]), "r"((a)[2]), "r"((a)[3]),           \
                   "r"((b)[0]), "r"((b)[1]))

__device__ __forceinline__ void cpasync16(unsigned dst, const void* src, bool valid) {
    int sz = valid ? 16 : 0;
    asm volatile("cp.async.cg.shared.global [%0], [%1], 16, %2;"
                 :: "r"(dst), "l"(src), "r"(sz));
}
#define CP_COMMIT() asm volatile("cp.async.commit_group;")

// ---------------- bf16 hi/lo split ----------------
__global__ void split_kernel(const float* __restrict__ in, unsigned* __restrict__ hi,
                             unsigned* __restrict__ lo, int n4) {
    int i = blockIdx.x * blockDim.x + threadIdx.x;
    if (i >= n4) return;
    float4 v = ((const float4*)in)[i];
    float h0 = bfr(v.x), h1 = bfr(v.y), h2 = bfr(v.z), h3 = bfr(v.w);
    uint2 hw = make_uint2(packbf(v.x, v.y), packbf(v.z, v.w));
    uint2 lw = make_uint2(packbf(v.x - h0, v.y - h1), packbf(v.z - h2, v.w - h3));
    ((uint2*)hi)[i] = hw;
    ((uint2*)lo)[i] = lw;
}

// ---------------- dtype detect + prep ----------------
__global__ void detect_kernel(const unsigned int* __restrict__ w, int* flag) {
    if (threadIdx.x == 0 && blockIdx.x == 0) {
        int is64 = 1;
        for (int i = 0; i < 64; i++)
            if (w[2 * i + 1] != 0u) { is64 = 0; break; }
        *flag = is64;
    }
}

__global__ void prep_kernel(const void* __restrict__ ei, const void* __restrict__ rid,
                            int* __restrict__ src, int* __restrict__ dst,
                            int* __restrict__ deg, int* __restrict__ role,
                            const int* __restrict__ flag, int E, int n) {
    int i = blockIdx.x * blockDim.x + threadIdx.x;
    int is64 = *flag;
    if (i < E) {
        int s, d;
        if (is64) {
            const long long* p = (const long long*)ei;
            s = (int)p[i];
            d = (int)p[(size_t)E + i];
        } else {
            const int* p = (const int*)ei;
            s = p[i];
            d = p[E + i];
        }
        src[i] = s;
        dst[i] = d;
        atomicAdd(&deg[d], 1);
    }
    if (i < n) {
        if (is64) role[i] = (int)((const long long*)rid)[i];
        else      role[i] = ((const int*)rid)[i];
    }
}

// ---------------- 2-phase scan ----------------
__global__ void scan_reduce_kernel(const int* __restrict__ deg, int* __restrict__ bsum, int n) {
    __shared__ int sw[32];
    int tid = threadIdx.x, lane = tid & 31, w = tid >> 5;
    int i = blockIdx.x * 1024 + tid;
    int v = (i < n) ? deg[i] : 0;
    v = warpSumI(v);
    if (lane == 0) sw[w] = v;
    __syncthreads();
    if (w == 0) {
        int t = sw[lane];
        t = warpSumI(t);
        if (lane == 0) bsum[blockIdx.x] = t;
    }
}

__global__ void scan_final_kernel(const int* __restrict__ deg, const int* __restrict__ bsum,
                                  int* __restrict__ rowptr, int* __restrict__ cursor, int n) {
    __shared__ int sw[32];
    __shared__ int partial[2];
    int tid = threadIdx.x, lane = tid & 31, w = tid >> 5;
    int bid = blockIdx.x;
    if (tid < 64) {
        int v = (tid < bid) ? bsum[tid] : 0;
        v = warpSumI(v);
        if ((tid & 31) == 0) partial[tid >> 5] = v;
    }
    int i = bid * 1024 + tid;
    int v = (i < n) ? deg[i] : 0;
    int iv = warpInclScan(v, lane);
    if (lane == 31) sw[w] = iv;
    __syncthreads();
    int base = partial[0] + partial[1];
    if (w == 0) {
        int t = sw[lane];
        t = warpInclScan(t, lane);
        sw[lane] = t;
    }
    __syncthreads();
    int offs = ((w > 0) ? sw[w - 1] : 0) + base;
    int incl = iv + offs;
    if (i < n) {
        rowptr[i + 1] = incl;
        cursor[i] = incl - v;
    }
    if (i == 0) rowptr[0] = 0;
}

__global__ void scatter_kernel(const int* __restrict__ src, const int* __restrict__ dst,
                               int* __restrict__ cursor, int* __restrict__ ecol, int E) {
    int i = blockIdx.x * blockDim.x + threadIdx.x;
    if (i >= E) return;
    int pos = atomicAdd(&cursor[dst[i]], 1);
    ecol[pos] = src[i];
}

// ---------------- role contribution precompute ----------------
__global__ void role_prep_kernel(const float* __restrict__ rt, const float* __restrict__ p1w,
                                 const float* __restrict__ p1b, float* __restrict__ rc) {
    int tid = threadIdx.x;
    int r = tid >> 6, j = tid & 63;
    float acc = p1b[j];
    #pragma unroll 8
    for (int k = 0; k < 64; k++)
        acc += rt[r * 64 + k] * p1w[j * 128 + 64 + k];
    rc[r * 64 + j] = acc;
}

// ---------------- BF16x3 tensor-core GEMM, cp.async double-buffered -------------------
// smem per buffer: 4 matrices x 128 rows x 20 words (row-major, stride 20 conflict-free)
#define CROW 20
#define CMAT (128 * CROW)
#define CBUF (4 * CMAT)
#define GEMM_BF16_SMEM (2 * CBUF * 4)
__global__ void __launch_bounds__(256, 2) gemm_bf16(
        const unsigned* __restrict__ Ahi, const unsigned* __restrict__ Alo,
        const unsigned* __restrict__ Bhi, const unsigned* __restrict__ Blo,
        float* __restrict__ C, int M, int KW,
        const float* __restrict__ as_, const float* __restrict__ ad_,
        float* __restrict__ s_, float* __restrict__ d_, int H) {
    extern __shared__ unsigned smemU[];
    unsigned sbase;
    asm("{ .reg .u64 t; cvta.to.shared.u64 t, %1; cvt.u32.u64 %0, t; }"
        : "=r"(sbase) : "l"(smemU));
    int tid = threadIdx.x, lane = tid & 31, warp = tid >> 5;
    int wm = warp & 3, wn = warp >> 2;
    int brow = blockIdx.y * 128, bcol = blockIdx.x * 128;
    float c[2][8][4];
    #pragma unroll
    for (int mt = 0; mt < 2; mt++)
        #pragma unroll
        for (int nt = 0; nt < 8; nt++)
            #pragma unroll
            for (int r = 0; r < 4; r++) c[mt][nt][r] = 0.f;

    const int nch = KW >> 4;

    // chunk copy: 2048 16B segments over 256 threads = 8 each
    auto issue = [&](int ch, int b) {
        #pragma unroll
        for (int t = 0; t < 8; t++) {
            int segid = tid + t * 256;
            int mtx = segid >> 9;             // compile-time per t after unroll
            int row = (segid >> 2) & 127;
            int seg = segid & 3;
            const unsigned* gp;
            bool valid = true;
            int grow;
            if (mtx == 0)      { gp = Ahi; grow = brow + row; valid = grow < M; }
            else if (mtx == 1) { gp = Alo; grow = brow + row; valid = grow < M; }
            else if (mtx == 2) { gp = Bhi; grow = bcol + row; }
            else               { gp = Blo; grow = bcol + row; }
            unsigned dst = sbase + (unsigned)(((b * 4 + mtx) * CMAT) + row * CROW + seg * 4) * 4u;
            cpasync16(dst, gp + (size_t)grow * KW + ch * 16 + seg * 4, valid);
        }
        CP_COMMIT();
    };

    issue(0, 0);

    for (int ch = 0; ch < nch; ch++) {
        int b = ch & 1;
        if (ch + 1 < nch) {
            issue(ch + 1, b ^ 1);
            asm volatile("cp.async.wait_group 1;");
        } else {
            asm volatile("cp.async.wait_group 0;");
        }
        __syncthreads();
        const unsigned* AhiS = smemU + (b * 4 + 0) * CMAT;
        const unsigned* AloS = smemU + (b * 4 + 1) * CMAT;
        const unsigned* BhiS = smemU + (b * 4 + 2) * CMAT;
        const unsigned* BloS = smemU + (b * 4 + 3) * CMAT;

        #pragma unroll
        for (int kg = 0; kg < 2; kg++) {
            int kc = kg * 8 + (lane & 3);
            unsigned ah[2][4], al[2][4];
            #pragma unroll
            for (int mt = 0; mt < 2; mt++) {
                int r = wm * 32 + mt * 16 + (lane >> 2);
                ah[mt][0] = AhiS[r * CROW + kc];
                ah[mt][1] = AhiS[(r + 8) * CROW + kc];
                ah[mt][2] = AhiS[r * CROW + kc + 4];
                ah[mt][3] = AhiS[(r + 8) * CROW + kc + 4];
                al[mt][0] = AloS[r * CROW + kc];
                al[mt][1] = AloS[(r + 8) * CROW + kc];
                al[mt][2] = AloS[r * CROW + kc + 4];
                al[mt][3] = AloS[(r + 8) * CROW + kc + 4];
            }
            #pragma unroll
            for (int nt = 0; nt < 8; nt++) {
                int nc = wn * 64 + nt * 8 + (lane >> 2);
                unsigned bh[2], bl[2];
                bh[0] = BhiS[nc * CROW + kc];
                bh[1] = BhiS[nc * CROW + kc + 4];
                bl[0] = BloS[nc * CROW + kc];
                bl[1] = BloS[nc * CROW + kc + 4];
                MMA_BF16(c[0][nt], ah[0], bh);
                MMA_BF16(c[1][nt], ah[1], bh);
                MMA_BF16(c[0][nt], ah[0], bl);
                MMA_BF16(c[1][nt], ah[1], bl);
                MMA_BF16(c[0][nt], al[0], bh);
                MMA_BF16(c[1][nt], al[1], bh);
            }
        }
        __syncthreads();
    }

    // store C
    #pragma unroll
    for (int mt = 0; mt < 2; mt++) {
        #pragma unroll
        for (int nt = 0; nt < 8; nt++) {
            int row = brow + wm * 32 + mt * 16 + (lane >> 2);
            int col = bcol + wn * 64 + nt * 8 + 2 * (lane & 3);
            if (row < M)
                *(float2*)&C[(size_t)row * 256 + col] = make_float2(c[mt][nt][0], c[mt][nt][1]);
            if (row + 8 < M)
                *(float2*)&C[(size_t)(row + 8) * 256 + col] = make_float2(c[mt][nt][2], c[mt][nt][3]);
        }
    }

    // fused score epilogue: this warp's 64 cols = head (bx*2 + wn); scalars loaded inline
    int head = blockIdx.x * 2 + wn;
    #pragma unroll
    for (int mt = 0; mt < 2; mt++) {
        #pragma unroll
        for (int p = 0; p < 2; p++) {
            float ss = 0.f, dd = 0.f;
            #pragma unroll
            for (int nt = 0; nt < 8; nt++) {
                int cc = nt * 8 + 2 * (lane & 3);
                float c0 = c[mt][nt][p * 2], c1 = c[mt][nt][p * 2 + 1];
                ss += c0 * as_[head * 64 + cc] + c1 * as_[head * 64 + cc + 1];
                dd += c0 * ad_[head * 64 + cc] + c1 * ad_[head * 64 + cc + 1];
            }
            ss += __shfl_xor_sync(0xffffffffu, ss, 1);
            ss += __shfl_xor_sync(0xffffffffu, ss, 2);
            dd += __shfl_xor_sync(0xffffffffu, dd, 1);
            dd += __shfl_xor_sync(0xffffffffu, dd, 2);
            int row = brow + wm * 32 + mt * 16 + (lane >> 2) + p * 8;
            if ((lane & 3) == 0 && row < M) {
                s_[(size_t)row * H + head] = ss;
                d_[(size_t)row * H + head] = dd;
            }
        }
    }
}

// ---------------- FFMA2 GEMM 128x64 (layer 3), Nc=64, H=1 ----------------
__global__ void __launch_bounds__(128) gemm_nt64(
        const float* __restrict__ A, const float* __restrict__ B,
        float* __restrict__ C, int M, int K,
        const float* __restrict__ as_, const float* __restrict__ ad_,
        float* __restrict__ s_, float* __restrict__ d_) {
    __shared__ float As[2][16][132];
    __shared__ float Bs[2][16][68];
    int tid = threadIdx.x;
    int lane = tid & 31;
    int brow = blockIdx.x * 128;
    int tr = tid >> 3, tc = tid & 7;
    unsigned long long accP[4][8];
    #pragma unroll
    for (int p = 0; p < 4; p++)
        #pragma unroll
        for (int j = 0; j < 8; j++) accP[p][j] = 0ull;

    int lrowA[4], lkqA[4];
    #pragma unroll
    for (int t = 0; t < 4; t++) { int li = tid + t * 128; lrowA[t] = li >> 2; lkqA[t] = (li & 3) * 4; }
    int lrowB[2], lkqB[2];
    #pragma unroll
    for (int t = 0; t < 2; t++) { int li = tid + t * 128; lrowB[t] = li >> 2; lkqB[t] = (li & 3) * 4; }
    float4 aReg[4], bReg[2];
    const int nch = K / 16;

    #pragma unroll
    for (int t = 0; t < 4; t++) {
        int gm = brow + lrowA[t];
        aReg[t] = (gm < M) ? *(const float4*)&A[(size_t)gm * K + lkqA[t]]
                           : make_float4(0.f, 0.f, 0.f, 0.f);
    }
    #pragma unroll
    for (int t = 0; t < 2; t++)
        bReg[t] = *(const float4*)&B[(size_t)lrowB[t] * K + lkqB[t]];
    #pragma unroll
    for (int t = 0; t < 4; t++) {
        As[0][lkqA[t] + 0][lrowA[t]] = aReg[t].x; As[0][lkqA[t] + 1][lrowA[t]] = aReg[t].y;
        As[0][lkqA[t] + 2][lrowA[t]] = aReg[t].z; As[0][lkqA[t] + 3][lrowA[t]] = aReg[t].w;
    }
    #pragma unroll
    for (int t = 0; t < 2; t++) {
        Bs[0][lkqB[t] + 0][lrowB[t]] = bReg[t].x; Bs[0][lkqB[t] + 1][lrowB[t]] = bReg[t].y;
        Bs[0][lkqB[t] + 2][lrowB[t]] = bReg[t].z; Bs[0][lkqB[t] + 3][lrowB[t]] = bReg[t].w;
    }
    __syncthreads();

    for (int c = 0; c < nch; c++) {
        int buf = c & 1;
        if (c + 1 < nch) {
            int k0 = (c + 1) * 16;
            #pragma unroll
            for (int t = 0; t < 4; t++) {
                int gm = brow + lrowA[t];
                aReg[t] = (gm < M) ? *(const float4*)&A[(size_t)gm * K + k0 + lkqA[t]]
                                   : make_float4(0.f, 0.f, 0.f, 0.f);
            }
            #pragma unroll
            for (int t = 0; t < 2; t++)
                bReg[t] = *(const float4*)&B[(size_t)lrowB[t] * K + k0 + lkqB[t]];
        }
        #pragma unroll
        for (int kk = 0; kk < 16; kk++) {
            float4 va0 = *(float4*)&As[buf][kk][tr * 8];
            float4 va1 = *(float4*)&As[buf][kk][tr * 8 + 4];
            float4 vb0 = *(float4*)&Bs[buf][kk][tc * 8];
            float4 vb1 = *(float4*)&Bs[buf][kk][tc * 8 + 4];
            unsigned long long a2[4], bd[8];
            PACK2(a2[0], va0.x, va0.y); PACK2(a2[1], va0.z, va0.w);
            PACK2(a2[2], va1.x, va1.y); PACK2(a2[3], va1.z, va1.w);
            DUP2(bd[0], vb0.x); DUP2(bd[1], vb0.y); DUP2(bd[2], vb0.z); DUP2(bd[3], vb0.w);
            DUP2(bd[4], vb1.x); DUP2(bd[5], vb1.y); DUP2(bd[6], vb1.z); DUP2(bd[7], vb1.w);
            #pragma unroll
            for (int p = 0; p < 4; p++)
                #pragma unroll
                for (int j = 0; j < 8; j++) FMA2(accP[p][j], a2[p], bd[j]);
        }
        if (c + 1 < nch) {
            int nb = buf ^ 1;
            #pragma unroll
            for (int t = 0; t < 4; t++) {
                As[nb][lkqA[t] + 0][lrowA[t]] = aReg[t].x; As[nb][lkqA[t] + 1][lrowA[t]] = aReg[t].y;
                As[nb][lkqA[t] + 2][lrowA[t]] = aReg[t].z; As[nb][lkqA[t] + 3][lrowA[t]] = aReg[t].w;
            }
            #pragma unroll
            for (int t = 0; t < 2; t++) {
                Bs[nb][lkqB[t] + 0][lrowB[t]] = bReg[t].x; Bs[nb][lkqB[t] + 1][lrowB[t]] = bReg[t].y;
                Bs[nb][lkqB[t] + 2][lrowB[t]] = bReg[t].z; Bs[nb][lkqB[t] + 3][lrowB[t]] = bReg[t].w;
            }
        }
        __syncthreads();
    }

    float acc[8][8];
    #pragma unroll
    for (int p = 0; p < 4; p++)
        #pragma unroll
        for (int j = 0; j < 8; j++) UNPACK2(acc[2 * p][j], acc[2 * p + 1][j], accP[p][j]);

    #pragma unroll
    for (int i = 0; i < 8; i++) {
        int gm = brow + tr * 8 + i;
        if (gm >= M) continue;
        *(float4*)&C[(size_t)gm * 64 + tc * 8] =
            make_float4(acc[i][0], acc[i][1], acc[i][2], acc[i][3]);
        *(float4*)&C[(size_t)gm * 64 + tc * 8 + 4] =
            make_float4(acc[i][4], acc[i][5], acc[i][6], acc[i][7]);
    }

    float asv[8], adv[8];
    #pragma unroll
    for (int j = 0; j < 8; j++) {
        asv[j] = as_[tc * 8 + j];
        adv[j] = ad_[tc * 8 + j];
    }
    #pragma unroll
    for (int i = 0; i < 8; i++) {
        float ss = 0.f, dd = 0.f;
        #pragma unroll
        for (int j = 0; j < 8; j++) {
            ss += acc[i][j] * asv[j];
            dd += acc[i][j] * adv[j];
        }
        #pragma unroll
        for (int o = 4; o >= 1; o >>= 1) {
            ss += __shfl_xor_sync(0xffffffffu, ss, o);
            dd += __shfl_xor_sync(0xffffffffu, dd, o);
        }
        int gm = brow + tr * 8 + i;
        if ((lane & 7) == 0 && gm < M) {
            s_[gm] = ss;
            d_[gm] = dd;
        }
    }
}

// ---------------- fused GAT layer, H=4 (optional bf16-split output) ----------
__global__ void gat_fused4(const int* __restrict__ rowptr, const int* __restrict__ ecol,
                           const float* __restrict__ s_, const float* __restrict__ d_,
                           const float* __restrict__ h, const float* __restrict__ bias,
                           const float* __restrict__ lw, const float* __restrict__ lb,
                           float* __restrict__ outp, unsigned* __restrict__ xhi,
                           unsigned* __restrict__ xlo, int n, int do_elu, int splitOut) {
    int warp = (blockIdx.x * blockDim.x + threadIdx.x) >> 5;
    int lane = threadIdx.x & 31;
    if (warp >= n) return;
    int node = warp;
    int start = rowptr[node], end = rowptr[node + 1];

    float4 dv4 = ((const float4*)d_)[node];
    float dsel[4] = {dv4.x, dv4.y, dv4.z, dv4.w};
    float4 sv4 = ((const float4*)s_)[node];
    float selfv[4] = {leaky(sv4.x + dsel[0]), leaky(sv4.y + dsel[1]),
                      leaky(sv4.z + dsel[2]), leaky(sv4.w + dsel[3])};

    float m[4], s[4];
    #pragma unroll
    for (int q = 0; q < 4; q++) {
        m[q] = (lane == 0) ? selfv[q] : -3e38f;
        s[q] = (lane == 0) ? 1.f : 0.f;
    }
    for (int e = start + lane; e < end; e += 32) {
        int src = ecol[e];
        float4 sv = ((const float4*)s_)[src];
        float v[4] = {leaky(sv.x + dsel[0]), leaky(sv.y + dsel[1]),
                      leaky(sv.z + dsel[2]), leaky(sv.w + dsel[3])};
        #pragma unroll
        for (int q = 0; q < 4; q++) {
            float nm = fmaxf(m[q], v[q]);
            s[q] = s[q] * expf(m[q] - nm) + expf(v[q] - nm);
            m[q] = nm;
        }
    }
    #pragma unroll
    for (int o = 16; o > 0; o >>= 1) {
        #pragma unroll
        for (int q = 0; q < 4; q++) {
            float om = __shfl_xor_sync(0xffffffffu, m[q], o);
            float os = __shfl_xor_sync(0xffffffffu, s[q], o);
            float nm = fmaxf(m[q], om);
            s[q] = s[q] * expf(m[q] - nm) + os * expf(om - nm);
            m[q] = nm;
        }
    }
    float inv[4], aself[4];
    #pragma unroll
    for (int q = 0; q < 4; q++) {
        inv[q] = 1.f / (s[q] + 1e-16f);
        aself[q] = expf(selfv[q] - m[q]) * inv[q];
    }

    int hl = lane & 3;
    float d_hl = (hl == 0) ? dsel[0] : (hl == 1) ? dsel[1] : (hl == 2) ? dsel[2] : dsel[3];
    float m_hl = (hl == 0) ? m[0]    : (hl == 1) ? m[1]    : (hl == 2) ? m[2]    : m[3];
    float i_hl = (hl == 0) ? inv[0]  : (hl == 1) ? inv[1]  : (hl == 2) ? inv[2]  : inv[3];
    int hA = lane >> 4;
    float asA = hA ? aself[1] : aself[0];
    float asB = hA ? aself[3] : aself[2];

    const float4* hps4 = (const float4*)(h + (size_t)node * 256);
    float4 acc0 = f4scale(hps4[lane], asA);
    float4 acc1 = f4scale(hps4[lane + 32], asB);

    for (int e0 = start; e0 < end; e0 += 8) {
        int me = e0 + (lane >> 2);
        float alpha = 0.f; int msrc = 0;
        if (me < end) {
            msrc = ecol[me];
            float v = leaky(s_[(size_t)msrc * 4 + hl] + d_hl);
            alpha = expf(v - m_hl) * i_hl;
        }
        int cnt = end - e0; if (cnt > 8) cnt = 8;
        for (int j0 = 0; j0 < cnt; j0 += 4) {
            int jn = cnt - j0; if (jn > 4) jn = 4;
            float4 pa[4], pb[4];
            float a0[4], a1[4];
            #pragma unroll
            for (int j = 0; j < 4; j++) {
                int src = __shfl_sync(0xffffffffu, msrc, (j0 + j) * 4);
                a0[j] = __shfl_sync(0xffffffffu, alpha, (j0 + j) * 4 + hA);
                a1[j] = __shfl_sync(0xffffffffu, alpha, (j0 + j) * 4 + 2 + hA);
                if (j < jn) {
                    const float4* hp4 = (const float4*)(h + (size_t)src * 256);
                    pa[j] = hp4[lane];
                    pb[j] = hp4[lane + 32];
                }
            }
            #pragma unroll
            for (int j = 0; j < 4; j++) {
                if (j < jn) {
                    acc0 = f4fma(pa[j], a0[j], acc0);
                    acc1 = f4fma(pb[j], a1[j], acc1);
                }
            }
        }
    }

    const float4* b4 = (const float4*)bias;
    const float4* lw4 = (const float4*)lw;
    const float4* lb4 = (const float4*)lb;
    float4 v0 = f4add(acc0, b4[lane]);
    float4 v1 = f4add(acc1, b4[lane + 32]);
    if (do_elu) {
        v0.x = v0.x > 0.f ? v0.x : expf(v0.x) - 1.f;
        v0.y = v0.y > 0.f ? v0.y : expf(v0.y) - 1.f;
        v0.z = v0.z > 0.f ? v0.z : expf(v0.z) - 1.f;
        v0.w = v0.w > 0.f ? v0.w : expf(v0.w) - 1.f;
        v1.x = v1.x > 0.f ? v1.x : expf(v1.x) - 1.f;
        v1.y = v1.y > 0.f ? v1.y : expf(v1.y) - 1.f;
        v1.z = v1.z > 0.f ? v1.z : expf(v1.z) - 1.f;
        v1.w = v1.w > 0.f ? v1.w : expf(v1.w) - 1.f;
    }
    float ssum = v0.x + v0.y + v0.z + v0.w + v1.x + v1.y + v1.z + v1.w;
    ssum = warpSum(ssum);
    float mu = ssum * (1.f / 256.f);
    float t, vs = 0.f;
    t = v0.x - mu; vs += t * t; t = v0.y - mu; vs += t * t;
    t = v0.z - mu; vs += t * t; t = v0.w - mu; vs += t * t;
    t = v1.x - mu; vs += t * t; t = v1.y - mu; vs += t * t;
    t = v1.z - mu; vs += t * t; t = v1.w - mu; vs += t * t;
    vs = warpSum(vs);
    float rs = rsqrtf(vs * (1.f / 256.f) + 1e-5f);
    float4 w0 = lw4[lane], w1 = lw4[lane + 32];
    float4 c0 = lb4[lane], c1 = lb4[lane + 32];
    float4 o0 = make_float4((v0.x - mu) * rs * w0.x + c0.x, (v0.y - mu) * rs * w0.y + c0.y,
                            (v0.z - mu) * rs * w0.z + c0.z, (v0.w - mu) * rs * w0.w + c0.w);
    float4 o1 = make_float4((v1.x - mu) * rs * w1.x + c1.x, (v1.y - mu) * rs * w1.y + c1.y,
                            (v1.z - mu) * rs * w1.z + c1.z, (v1.w - mu) * rs * w1.w + c1.w);
    float4* out4 = (float4*)(outp + (size_t)node * 256);
    out4[lane] = o0;
    out4[lane + 32] = o1;

    if (splitOut) {
        unsigned* xh = xhi + (size_t)node * 128;
        unsigned* xl = xlo + (size_t)node * 128;
        *(uint2*)&xh[lane * 2] = make_uint2(packbf(o0.x, o0.y), packbf(o0.z, o0.w));
        *(uint2*)&xh[64 + lane * 2] = make_uint2(packbf(o1.x, o1.y), packbf(o1.z, o1.w));
        *(uint2*)&xl[lane * 2] = make_uint2(
            packbf(o0.x - bfr(o0.x), o0.y - bfr(o0.y)),
            packbf(o0.z - bfr(o0.z), o0.w - bfr(o0.w)));
        *(uint2*)&xl[64 + lane * 2] = make_uint2(
            packbf(o1.x - bfr(o1.x), o1.y - bfr(o1.y)),
            packbf(o1.z - bfr(o1.z), o1.w - bfr(o1.w)));
    }
}

// ---------------- fused GAT layer, H=1 (D=64) ----------
__global__ void gat_fused1(const int* __restrict__ rowptr, const int* __restrict__ ecol,
                           const float* __restrict__ s_, const float* __restrict__ d_,
                           const float* __restrict__ h, const float* __restrict__ bias,
                           const float* __restrict__ lw, const float* __restrict__ lb,
                           float* __restrict__ outp, int n, int do_elu) {
    int warp = (blockIdx.x * blockDim.x + threadIdx.x) >> 5;
    int lane = threadIdx.x & 31;
    if (warp >= n) return;
    int node = warp;
    int start = rowptr[node], end = rowptr[node + 1];

    float dsel = d_[node];
    float selfv = leaky(s_[node] + dsel);
    float m = (lane == 0) ? selfv : -3e38f;
    float s = (lane == 0) ? 1.f : 0.f;
    for (int e = start + lane; e < end; e += 32) {
        float v = leaky(s_[ecol[e]] + dsel);
        float nm = fmaxf(m, v);
        s = s * expf(m - nm) + expf(v - nm);
        m = nm;
    }
    #pragma unroll
    for (int o = 16; o > 0; o >>= 1) {
        float om = __shfl_xor_sync(0xffffffffu, m, o);
        float os = __shfl_xor_sync(0xffffffffu, s, o);
        float nm = fmaxf(m, om);
        s = s * expf(m - nm) + os * expf(om - nm);
        m = nm;
    }
    float inv = 1.f / (s + 1e-16f);
    float aself = expf(selfv - m) * inv;

    int half = lane >> 4, f = lane & 15;
    const float4* hps4 = (const float4*)(h + (size_t)node * 64);
    float4 acc = (half == 0) ? f4scale(hps4[f], aself) : make_float4(0.f, 0.f, 0.f, 0.f);

    for (int e0 = start; e0 < end; e0 += 8) {
        int me = e0 + lane;
        float alpha = 0.f; int msrc = 0;
        if (lane < 8 && me < end) {
            msrc = ecol[me];
            alpha = expf(leaky(s_[msrc] + dsel) - m) * inv;
        }
        int cnt = end - e0; if (cnt > 8) cnt = 8;
        for (int j = 0; j < cnt; j += 2) {
            int eidx = j + half;
            int src = __shfl_sync(0xffffffffu, msrc, eidx);
            float al = __shfl_sync(0xffffffffu, alpha, eidx);
            if (eidx < cnt) {
                const float4* hp4 = (const float4*)(h + (size_t)src * 64);
                acc = f4fma(hp4[f], al, acc);
            }
        }
    }
    acc.x += __shfl_xor_sync(0xffffffffu, acc.x, 16);
    acc.y += __shfl_xor_sync(0xffffffffu, acc.y, 16);
    acc.z += __shfl_xor_sync(0xffffffffu, acc.z, 16);
    acc.w += __shfl_xor_sync(0xffffffffu, acc.w, 16);

    const float4* b4 = (const float4*)bias;
    const float4* lw4 = (const float4*)lw;
    const float4* lb4 = (const float4*)lb;
    float4 v = f4add(acc, b4[f]);
    if (do_elu) {
        v.x = v.x > 0.f ? v.x : expf(v.x) - 1.f;
        v.y = v.y > 0.f ? v.y : expf(v.y) - 1.f;
        v.z = v.z > 0.f ? v.z : expf(v.z) - 1.f;
        v.w = v.w > 0.f ? v.w : expf(v.w) - 1.f;
    }
    float ssum = warpSum(v.x + v.y + v.z + v.w);
    float mu = ssum * (1.f / 128.f);
    float t, vs = 0.f;
    t = v.x - mu; vs += t * t; t = v.y - mu; vs += t * t;
    t = v.z - mu; vs += t * t; t = v.w - mu; vs += t * t;
    vs = warpSum(vs);
    float rs = rsqrtf(vs * (1.f / 128.f) + 1e-5f);
    if (half == 0) {
        float4 w = lw4[f], c = lb4[f];
        float4* out4 = (float4*)(outp + (size_t)node * 64);
        out4[f] = make_float4((v.x - mu) * rs * w.x + c.x, (v.y - mu) * rs * w.y + c.y,
                              (v.z - mu) * rs * w.z + c.z, (v.w - mu) * rs * w.w + c.w);
    }
}

// ---------------- final MLP head ----------------
__global__ void head_kernel(const float* __restrict__ h3, const int* __restrict__ role,
                            const float* __restrict__ rc, const float* __restrict__ p1w,
                            const float* __restrict__ p2w, const float* __restrict__ p2b,
                            float* __restrict__ z, int n) {
    extern __shared__ float sm[];
    float* sp1 = sm;
    float* sp2 = sp1 + 64 * 64;
    float* sz  = sp2 + 64 * 64;
    float* sz1 = sz + 4 * 64;
    int tid = threadIdx.x;
    for (int i = tid; i < 64 * 64; i += 256) {
        int j = i >> 6, k = i & 63;
        sp1[k * 64 + j] = p1w[j * 128 + k];
        sp2[k * 64 + j] = p2w[i];
    }
    __syncthreads();
    int g = tid >> 6, j = tid & 63;
    float b2v = p2b[j];
    for (int it = 0; it < 16; it++) {
        int node = blockIdx.x * 64 + it * 4 + g;
        bool valid = node < n;
        float rcv = 0.f;
        if (valid) {
            sz[g * 64 + j] = h3[(size_t)node * 64 + j];
            rcv = rc[role[node] * 64 + j];
        }
        __syncthreads();
        float acc = rcv;
        #pragma unroll 8
        for (int k = 0; k < 64; k++) acc += sp1[k * 64 + j] * sz[g * 64 + k];
        sz1[g * 64 + j] = fmaxf(acc, 0.f);
        __syncthreads();
        float acc2 = b2v;
        #pragma unroll 8
        for (int k = 0; k < 64; k++) acc2 += sp2[k * 64 + j] * sz1[g * 64 + k];
        if (valid) z[(size_t)node * 64 + j] = acc2;
    }
}

// ---------------- host orchestration ----------------
extern "C" void kernel_launch(void* const* d_in, const int* in_sizes, int n_in,
                              void* d_out, int out_size) {
    const float* x   = (const float*)d_in[0];
    const void*  ei  = d_in[1];
    const void*  rid = d_in[2];
    const float* W1  = (const float*)d_in[3];
    const float* a1s = (const float*)d_in[4];
    const float* a1d = (const float*)d_in[5];
    const float* b1  = (const float*)d_in[6];
    const float* W2  = (const float*)d_in[7];
    const float* a2s = (const float*)d_in[8];
    const float* a2d = (const float*)d_in[9];
    const float* b2  = (const float*)d_in[10];
    const float* W3  = (const float*)d_in[11];
    const float* a3s = (const float*)d_in[12];
    const float* a3d = (const float*)d_in[13];
    const float* b3  = (const float*)d_in[14];
    const float* ln1w = (const float*)d_in[15];
    const float* ln1b = (const float*)d_in[16];
    const float* ln2w = (const float*)d_in[17];
    const float* ln2b = (const float*)d_in[18];
    const float* ln3w = (const float*)d_in[19];
    const float* ln3b = (const float*)d_in[20];
    const float* rt   = (const float*)d_in[21];
    const float* p1w  = (const float*)d_in[22];
    const float* p1b  = (const float*)d_in[23];
    const float* p2w  = (const float*)d_in[24];
    const float* p2b  = (const float*)d_in[25];
    float* z = (float*)d_out;

    float *hbuf, *xbuf, *ybuf, *sp, *dp, *rcp;
    unsigned *xhip, *xlop, *whip, *wlop;
    int *srcp, *dstp, *ecolp, *rowp, *degp, *curp, *bsump, *rolep, *flagp;
    cudaGetSymbolAddress((void**)&hbuf, g_h);
    cudaGetSymbolAddress((void**)&xbuf, g_x);
    cudaGetSymbolAddress((void**)&ybuf, g_y);
    cudaGetSymbolAddress((void**)&sp, g_s);
    cudaGetSymbolAddress((void**)&dp, g_d);
    cudaGetSymbolAddress((void**)&rcp, g_rc);
    cudaGetSymbolAddress((void**)&xhip, g_xhi);
    cudaGetSymbolAddress((void**)&xlop, g_xlo);
    cudaGetSymbolAddress((void**)&whip, g_whi);
    cudaGetSymbolAddress((void**)&wlop, g_wlo);
    cudaGetSymbolAddress((void**)&srcp, g_src);
    cudaGetSymbolAddress((void**)&dstp, g_dst);
    cudaGetSymbolAddress((void**)&ecolp, g_ecol);
    cudaGetSymbolAddress((void**)&rowp, g_rowptr);
    cudaGetSymbolAddress((void**)&degp, g_deg);
    cudaGetSymbolAddress((void**)&curp, g_cursor);
    cudaGetSymbolAddress((void**)&bsump, g_bsum);
    cudaGetSymbolAddress((void**)&rolep, g_role);
    cudaGetSymbolAddress((void**)&flagp, g_is64);

    const int n = NN, E = EE;
    const int nb = (n + 1023) / 1024;

    dim3 gg(2, (n + 127) / 128);
    int g3blocks = (n + 127) / 128;
    int fusedBlocks = (n * 32 + 255) / 256;

    cudaFuncSetAttribute(gemm_bf16, cudaFuncAttributeMaxDynamicSharedMemorySize,
                         GEMM_BF16_SMEM);

    // conversions first (no deps) so gemm1 stays in the ncu capture slot
    split_kernel<<<(n * 64 / 4 + 255) / 256, 256>>>(x, xhip, xlop, n * 64 / 4);
    split_kernel<<<16, 256>>>(W1, whip, wlop, 256 * 64 / 4);
    detect_kernel<<<1, 32>>>((const unsigned int*)ei, flagp);
    cudaMemsetAsync(degp, 0, n * sizeof(int));
    gemm_bf16<<<gg, 256, GEMM_BF16_SMEM>>>(xhip, xlop, whip, wlop, hbuf, n, 32,
                                           a1s, a1d, sp, dp, 4);
    prep_kernel<<<(E + 255) / 256, 256>>>(ei, rid, srcp, dstp, degp, rolep, flagp, E, n);
    scan_reduce_kernel<<<nb, 1024>>>(degp, bsump, n);
    scan_final_kernel<<<nb, 1024>>>(degp, bsump, rowp, curp, n);
    scatter_kernel<<<(E + 255) / 256, 256>>>(srcp, dstp, curp, ecolp, E);
    role_prep_kernel<<<1, 128>>>(rt, p1w, p1b, rcp);

    // layer 1 gather (emits bf16-split output for layer-2 GEMM A)
    gat_fused4<<<fusedBlocks, 256>>>(rowp, ecolp, sp, dp, hbuf, b1, ln1w, ln1b,
                                     xbuf, xhip, xlop, n, 1, 1);

    // layer 2
    split_kernel<<<64, 256>>>(W2, whip, wlop, 256 * 256 / 4);
    gemm_bf16<<<gg, 256, GEMM_BF16_SMEM>>>(xhip, xlop, whip, wlop, hbuf, n, 128,
                                           a2s, a2d, sp, dp, 4);
    gat_fused4<<<fusedBlocks, 256>>>(rowp, ecolp, sp, dp, hbuf, b2, ln2w, ln2b,
                                     xbuf, xhip, xlop, n, 1, 0);

    // layer 3 (fp32 FFMA2 path)
    gemm_nt64<<<g3blocks, 128>>>(xbuf, W3, hbuf, n, 256, a3s, a3d, sp, dp);
    gat_fused1<<<fusedBlocks, 256>>>(rowp, ecolp, sp, dp, hbuf, b3, ln3w, ln3b, ybuf, n, 0);

    // final MLP head
    size_t smem = (64 * 64 + 64 * 64 + 4 * 64 + 4 * 64) * sizeof(float);
    cudaFuncSetAttribute(head_kernel, cudaFuncAttributeMaxDynamicSharedMemorySize, (int)smem);
    head_kernel<<<(n + 63) / 64, 256, smem>>>(ybuf, rolep, rcp, p1w, p2w, p2b, z, n);
}

// round 15
// speedup vs baseline: 1.1676x; 1.0071x over previous
#include <cuda_runtime.h>
#include <cuda_bf16.h>
#include <math.h>

#define NN 50000
#define EE 400000
#define DMAX 256

// ---------------- scratch ----------------
__device__ float g_h[(size_t)NN * DMAX];
__device__ float g_x[(size_t)NN * DMAX];
__device__ float g_y[(size_t)NN * DMAX];
__device__ float g_s[NN * 4];
__device__ float g_d[NN * 4];
__device__ float g_rc[2 * 64];
__device__ unsigned g_xhi[(size_t)NN * 128];
__device__ unsigned g_xlo[(size_t)NN * 128];
__device__ unsigned g_whi[256 * 128];
__device__ unsigned g_wlo[256 * 128];
__device__ int g_src[EE];
__device__ int g_dst[EE];
__device__ int g_ecol[EE];
__device__ int g_rowptr[NN + 1];
__device__ int g_deg[NN];
__device__ int g_cursor[NN];
__device__ int g_bsum[64];
__device__ int g_role[NN];
__device__ int g_is64;

// ---------------- helpers ----------------
__device__ __forceinline__ float warpSum(float v) {
    #pragma unroll
    for (int o = 16; o > 0; o >>= 1) v += __shfl_xor_sync(0xffffffffu, v, o);
    return v;
}
__device__ __forceinline__ int warpSumI(int v) {
    #pragma unroll
    for (int o = 16; o > 0; o >>= 1) v += __shfl_xor_sync(0xffffffffu, v, o);
    return v;
}
__device__ __forceinline__ int warpInclScan(int v, int lane) {
    #pragma unroll
    for (int o = 1; o < 32; o <<= 1) {
        int t = __shfl_up_sync(0xffffffffu, v, o);
        if (lane >= o) v += t;
    }
    return v;
}
__device__ __forceinline__ float leaky(float v) { return fmaxf(v, 0.2f * v); }
__device__ __forceinline__ float4 f4fma(float4 a, float s, float4 c) {
    c.x += a.x * s; c.y += a.y * s; c.z += a.z * s; c.w += a.w * s; return c;
}
__device__ __forceinline__ float4 f4scale(float4 a, float s) {
    return make_float4(a.x * s, a.y * s, a.z * s, a.w * s);
}
__device__ __forceinline__ float4 f4add(float4 a, float4 b) {
    return make_float4(a.x + b.x, a.y + b.y, a.z + b.z, a.w + b.w);
}

// packed f32x2 ops (for FFMA2 gemm_nt64)
#define PACK2(d, x, y) asm("mov.b64 %0, {%1, %2};" : "=l"(d) : "f"(x), "f"(y))
#define DUP2(d, x)     asm("mov.b64 %0, {%1, %1};" : "=l"(d) : "f"(x))
#define FMA2(c, a, b)  asm("fma.rn.f32x2 %0, %1, %2, %0;" : "+l"(c) : "l"(a), "l"(b))
#define UNPACK2(x, y, d) asm("mov.b64 {%0, %1}, %2;" : "=f"(x), "=f"(y) : "l"(d))

// bf16 helpers
__device__ __forceinline__ unsigned packbf(float lo_elem, float hi_elem) {
    unsigned r;
    asm("cvt.rn.bf16x2.f32 %0, %1, %2;" : "=r"(r) : "f"(hi_elem), "f"(lo_elem));
    return r;
}
__device__ __forceinline__ float bfr(float f) {
    return __bfloat162float(__float2bfloat16(f));
}

#define MMA_BF16(c, a, b)                                                        \
    asm volatile("mma.sync.aligned.m16n8k16.row.col.f32.bf16.bf16.f32 "          \
                 "{%0,%1,%2,%3}, {%4,%5,%6,%7}, {%8,%9}, {%0,%1,%2,%3};"         \
                 : "+f"((c)[0]), "+f"((c)[1]), "+f"((c)[2]), "+f"((c)[3])        \
                 : "r"((a)[0]), "r"((a)[1]), "r"((a)[2]), "r"((a)[3]),           \
                   "r"((b)[0]), "r"((b)[1]))

#define LDM4(r, a)                                                               \
    asm volatile("ldmatrix.sync.aligned.m8n8.x4.shared.b16 {%0,%1,%2,%3}, [%4];" \
                 : "=r"((r)[0]), "=r"((r)[1]), "=r"((r)[2]), "=r"((r)[3])        \
                 : "r"(a))

__device__ __forceinline__ void cpasync16(unsigned dst, const void* src, bool valid) {
    int sz = valid ? 16 : 0;
    asm volatile("cp.async.cg.shared.global [%0], [%1], 16, %2;"
                 :: "r"(dst), "l"(src), "r"(sz));
}
#define CP_COMMIT() asm volatile("cp.async.commit_group;")

// ---------------- bf16 hi/lo split ----------------
__global__ void split_kernel(const float* __restrict__ in, unsigned* __restrict__ hi,
                             unsigned* __restrict__ lo, int n4) {
    int i = blockIdx.x * blockDim.x + threadIdx.x;
    if (i >= n4) return;
    float4 v = ((const float4*)in)[i];
    float h0 = bfr(v.x), h1 = bfr(v.y), h2 = bfr(v.z), h3 = bfr(v.w);
    uint2 hw = make_uint2(packbf(v.x, v.y), packbf(v.z, v.w));
    uint2 lw = make_uint2(packbf(v.x - h0, v.y - h1), packbf(v.z - h2, v.w - h3));
    ((uint2*)hi)[i] = hw;
    ((uint2*)lo)[i] = lw;
}

// ---------------- dtype detect + prep ----------------
__global__ void detect_kernel(const unsigned int* __restrict__ w, int* flag) {
    if (threadIdx.x == 0 && blockIdx.x == 0) {
        int is64 = 1;
        for (int i = 0; i < 64; i++)
            if (w[2 * i + 1] != 0u) { is64 = 0; break; }
        *flag = is64;
    }
}

__global__ void prep_kernel(const void* __restrict__ ei, const void* __restrict__ rid,
                            int* __restrict__ src, int* __restrict__ dst,
                            int* __restrict__ deg, int* __restrict__ role,
                            const int* __restrict__ flag, int E, int n) {
    int i = blockIdx.x * blockDim.x + threadIdx.x;
    int is64 = *flag;
    if (i < E) {
        int s, d;
        if (is64) {
            const long long* p = (const long long*)ei;
            s = (int)p[i];
            d = (int)p[(size_t)E + i];
        } else {
            const int* p = (const int*)ei;
            s = p[i];
            d = p[E + i];
        }
        src[i] = s;
        dst[i] = d;
        atomicAdd(&deg[d], 1);
    }
    if (i < n) {
        if (is64) role[i] = (int)((const long long*)rid)[i];
        else      role[i] = ((const int*)rid)[i];
    }
}

// ---------------- 2-phase scan ----------------
__global__ void scan_reduce_kernel(const int* __restrict__ deg, int* __restrict__ bsum, int n) {
    __shared__ int sw[32];
    int tid = threadIdx.x, lane = tid & 31, w = tid >> 5;
    int i = blockIdx.x * 1024 + tid;
    int v = (i < n) ? deg[i] : 0;
    v = warpSumI(v);
    if (lane == 0) sw[w] = v;
    __syncthreads();
    if (w == 0) {
        int t = sw[lane];
        t = warpSumI(t);
        if (lane == 0) bsum[blockIdx.x] = t;
    }
}

__global__ void scan_final_kernel(const int* __restrict__ deg, const int* __restrict__ bsum,
                                  int* __restrict__ rowptr, int* __restrict__ cursor, int n) {
    __shared__ int sw[32];
    __shared__ int partial[2];
    int tid = threadIdx.x, lane = tid & 31, w = tid >> 5;
    int bid = blockIdx.x;
    if (tid < 64) {
        int v = (tid < bid) ? bsum[tid] : 0;
        v = warpSumI(v);
        if ((tid & 31) == 0) partial[tid >> 5] = v;
    }
    int i = bid * 1024 + tid;
    int v = (i < n) ? deg[i] : 0;
    int iv = warpInclScan(v, lane);
    if (lane == 31) sw[w] = iv;
    __syncthreads();
    int base = partial[0] + partial[1];
    if (w == 0) {
        int t = sw[lane];
        t = warpInclScan(t, lane);
        sw[lane] = t;
    }
    __syncthreads();
    int offs = ((w > 0) ? sw[w - 1] : 0) + base;
    int incl = iv + offs;
    if (i < n) {
        rowptr[i + 1] = incl;
        cursor[i] = incl - v;
    }
    if (i == 0) rowptr[0] = 0;
}

__global__ void scatter_kernel(const int* __restrict__ src, const int* __restrict__ dst,
                               int* __restrict__ cursor, int* __restrict__ ecol, int E) {
    int i = blockIdx.x * blockDim.x + threadIdx.x;
    if (i >= E) return;
    int pos = atomicAdd(&cursor[dst[i]], 1);
    ecol[pos] = src[i];
}

// ---------------- role contribution precompute ----------------
__global__ void role_prep_kernel(const float* __restrict__ rt, const float* __restrict__ p1w,
                                 const float* __restrict__ p1b, float* __restrict__ rc) {
    int tid = threadIdx.x;
    int r = tid >> 6, j = tid & 63;
    float acc = p1b[j];
    #pragma unroll 8
    for (int k = 0; k < 64; k++)
        acc += rt[r * 64 + k] * p1w[j * 128 + 64 + k];
    rc[r * 64 + j] = acc;
}

// ---------------- BF16x3 tensor-core GEMM, cp.async + ldmatrix -------------------
#define CROW 20
#define CMAT (128 * CROW)
#define CBUF (4 * CMAT)
#define GEMM_BF16_SMEM (2 * CBUF * 4)
__global__ void __launch_bounds__(256, 2) gemm_bf16(
        const unsigned* __restrict__ Ahi, const unsigned* __restrict__ Alo,
        const unsigned* __restrict__ Bhi, const unsigned* __restrict__ Blo,
        float* __restrict__ C, int M, int KW,
        const float* __restrict__ as_, const float* __restrict__ ad_,
        float* __restrict__ s_, float* __restrict__ d_, int H) {
    extern __shared__ unsigned smemU[];
    unsigned sbase;
    asm("{ .reg .u64 t; cvta.to.shared.u64 t, %1; cvt.u32.u64 %0, t; }"
        : "=r"(sbase) : "l"(smemU));
    int tid = threadIdx.x, lane = tid & 31, warp = tid >> 5;
    int wm = warp & 3, wn = warp >> 2;
    int brow = blockIdx.y * 128, bcol = blockIdx.x * 128;
    float c[2][8][4];
    #pragma unroll
    for (int mt = 0; mt < 2; mt++)
        #pragma unroll
        for (int nt = 0; nt < 8; nt++)
            #pragma unroll
            for (int r = 0; r < 4; r++) c[mt][nt][r] = 0.f;

    const int nch = KW >> 4;

    // per-lane ldmatrix base word-offsets (within a matrix buffer)
    // A: matrices m0: rows r@klo, m1: r+8@klo, m2: r@khi, m3: r+8@khi
    unsigned aoffw = (unsigned)((wm * 32 + (lane & 7) + ((lane >> 3) & 1) * 8) * CROW
                                + ((lane >> 4) & 1) * 4);
    // B: m0: rows n0@klo, m1: n0@khi, m2: n0+8@klo, m3: n0+8@khi  (nt pair)
    unsigned boffw = (unsigned)((wn * 64 + (lane & 7) + ((lane >> 4) & 1) * 8) * CROW
                                + ((lane >> 3) & 1) * 4);

    // chunk copy: 2048 16B segments over 256 threads = 8 each
    auto issue = [&](int ch, int b) {
        #pragma unroll
        for (int t = 0; t < 8; t++) {
            int segid = tid + t * 256;
            int mtx = segid >> 9;
            int row = (segid >> 2) & 127;
            int seg = segid & 3;
            const unsigned* gp;
            bool valid = true;
            int grow;
            if (mtx == 0)      { gp = Ahi; grow = brow + row; valid = grow < M; }
            else if (mtx == 1) { gp = Alo; grow = brow + row; valid = grow < M; }
            else if (mtx == 2) { gp = Bhi; grow = bcol + row; }
            else               { gp = Blo; grow = bcol + row; }
            unsigned dst = sbase + (unsigned)(((b * 4 + mtx) * CMAT) + row * CROW + seg * 4) * 4u;
            cpasync16(dst, gp + (size_t)grow * KW + ch * 16 + seg * 4, valid);
        }
        CP_COMMIT();
    };

    issue(0, 0);

    for (int ch = 0; ch < nch; ch++) {
        int b = ch & 1;
        if (ch + 1 < nch) {
            issue(ch + 1, b ^ 1);
            asm volatile("cp.async.wait_group 1;");
        } else {
            asm volatile("cp.async.wait_group 0;");
        }
        __syncthreads();
        unsigned baseAhi = sbase + ((b * 4 + 0) * CMAT + aoffw) * 4u;
        unsigned baseAlo = sbase + ((b * 4 + 1) * CMAT + aoffw) * 4u;
        unsigned baseBhi = sbase + ((b * 4 + 2) * CMAT + boffw) * 4u;
        unsigned baseBlo = sbase + ((b * 4 + 3) * CMAT + boffw) * 4u;

        #pragma unroll
        for (int kg = 0; kg < 2; kg++) {
            unsigned kb = (unsigned)(kg * 8) * 4u;
            unsigned ah[2][4], al[2][4];
            LDM4(ah[0], baseAhi + kb);
            LDM4(ah[1], baseAhi + 16 * CROW * 4 + kb);
            LDM4(al[0], baseAlo + kb);
            LDM4(al[1], baseAlo + 16 * CROW * 4 + kb);
            #pragma unroll
            for (int pp = 0; pp < 4; pp++) {
                unsigned th[4], tl[4];
                LDM4(th, baseBhi + pp * 16 * CROW * 4 + kb);
                LDM4(tl, baseBlo + pp * 16 * CROW * 4 + kb);
                unsigned b0h[2] = {th[0], th[1]}, b1h[2] = {th[2], th[3]};
                unsigned b0l[2] = {tl[0], tl[1]}, b1l[2] = {tl[2], tl[3]};
                int n0 = pp * 2, n1 = pp * 2 + 1;
                MMA_BF16(c[0][n0], ah[0], b0h);
                MMA_BF16(c[1][n0], ah[1], b0h);
                MMA_BF16(c[0][n1], ah[0], b1h);
                MMA_BF16(c[1][n1], ah[1], b1h);
                MMA_BF16(c[0][n0], ah[0], b0l);
                MMA_BF16(c[1][n0], ah[1], b0l);
                MMA_BF16(c[0][n1], ah[0], b1l);
                MMA_BF16(c[1][n1], ah[1], b1l);
                MMA_BF16(c[0][n0], al[0], b0h);
                MMA_BF16(c[1][n0], al[1], b0h);
                MMA_BF16(c[0][n1], al[0], b1h);
                MMA_BF16(c[1][n1], al[1], b1h);
            }
        }
        __syncthreads();
    }

    // store C
    #pragma unroll
    for (int mt = 0; mt < 2; mt++) {
        #pragma unroll
        for (int nt = 0; nt < 8; nt++) {
            int row = brow + wm * 32 + mt * 16 + (lane >> 2);
            int col = bcol + wn * 64 + nt * 8 + 2 * (lane & 3);
            if (row < M)
                *(float2*)&C[(size_t)row * 256 + col] = make_float2(c[mt][nt][0], c[mt][nt][1]);
            if (row + 8 < M)
                *(float2*)&C[(size_t)(row + 8) * 256 + col] = make_float2(c[mt][nt][2], c[mt][nt][3]);
        }
    }

    // fused score epilogue
    int head = blockIdx.x * 2 + wn;
    #pragma unroll
    for (int mt = 0; mt < 2; mt++) {
        #pragma unroll
        for (int p = 0; p < 2; p++) {
            float ss = 0.f, dd = 0.f;
            #pragma unroll
            for (int nt = 0; nt < 8; nt++) {
                int cc = nt * 8 + 2 * (lane & 3);
                float c0 = c[mt][nt][p * 2], c1 = c[mt][nt][p * 2 + 1];
                ss += c0 * as_[head * 64 + cc] + c1 * as_[head * 64 + cc + 1];
                dd += c0 * ad_[head * 64 + cc] + c1 * ad_[head * 64 + cc + 1];
            }
            ss += __shfl_xor_sync(0xffffffffu, ss, 1);
            ss += __shfl_xor_sync(0xffffffffu, ss, 2);
            dd += __shfl_xor_sync(0xffffffffu, dd, 1);
            dd += __shfl_xor_sync(0xffffffffu, dd, 2);
            int row = brow + wm * 32 + mt * 16 + (lane >> 2) + p * 8;
            if ((lane & 3) == 0 && row < M) {
                s_[(size_t)row * H + head] = ss;
                d_[(size_t)row * H + head] = dd;
            }
        }
    }
}

// ---------------- FFMA2 GEMM 128x64 (layer 3), Nc=64, H=1 ----------------
__global__ void __launch_bounds__(128) gemm_nt64(
        const float* __restrict__ A, const float* __restrict__ B,
        float* __restrict__ C, int M, int K,
        const float* __restrict__ as_, const float* __restrict__ ad_,
        float* __restrict__ s_, float* __restrict__ d_) {
    __shared__ float As[2][16][132];
    __shared__ float Bs[2][16][68];
    int tid = threadIdx.x;
    int lane = tid & 31;
    int brow = blockIdx.x * 128;
    int tr = tid >> 3, tc = tid & 7;
    unsigned long long accP[4][8];
    #pragma unroll
    for (int p = 0; p < 4; p++)
        #pragma unroll
        for (int j = 0; j < 8; j++) accP[p][j] = 0ull;

    int lrowA[4], lkqA[4];
    #pragma unroll
    for (int t = 0; t < 4; t++) { int li = tid + t * 128; lrowA[t] = li >> 2; lkqA[t] = (li & 3) * 4; }
    int lrowB[2], lkqB[2];
    #pragma unroll
    for (int t = 0; t < 2; t++) { int li = tid + t * 128; lrowB[t] = li >> 2; lkqB[t] = (li & 3) * 4; }
    float4 aReg[4], bReg[2];
    const int nch = K / 16;

    #pragma unroll
    for (int t = 0; t < 4; t++) {
        int gm = brow + lrowA[t];
        aReg[t] = (gm < M) ? *(const float4*)&A[(size_t)gm * K + lkqA[t]]
                           : make_float4(0.f, 0.f, 0.f, 0.f);
    }
    #pragma unroll
    for (int t = 0; t < 2; t++)
        bReg[t] = *(const float4*)&B[(size_t)lrowB[t] * K + lkqB[t]];
    #pragma unroll
    for (int t = 0; t < 4; t++) {
        As[0][lkqA[t] + 0][lrowA[t]] = aReg[t].x; As[0][lkqA[t] + 1][lrowA[t]] = aReg[t].y;
        As[0][lkqA[t] + 2][lrowA[t]] = aReg[t].z; As[0][lkqA[t] + 3][lrowA[t]] = aReg[t].w;
    }
    #pragma unroll
    for (int t = 0; t < 2; t++) {
        Bs[0][lkqB[t] + 0][lrowB[t]] = bReg[t].x; Bs[0][lkqB[t] + 1][lrowB[t]] = bReg[t].y;
        Bs[0][lkqB[t] + 2][lrowB[t]] = bReg[t].z; Bs[0][lkqB[t] + 3][lrowB[t]] = bReg[t].w;
    }
    __syncthreads();

    for (int c = 0; c < nch; c++) {
        int buf = c & 1;
        if (c + 1 < nch) {
            int k0 = (c + 1) * 16;
            #pragma unroll
            for (int t = 0; t < 4; t++) {
                int gm = brow + lrowA[t];
                aReg[t] = (gm < M) ? *(const float4*)&A[(size_t)gm * K + k0 + lkqA[t]]
                                   : make_float4(0.f, 0.f, 0.f, 0.f);
            }
            #pragma unroll
            for (int t = 0; t < 2; t++)
                bReg[t] = *(const float4*)&B[(size_t)lrowB[t] * K + k0 + lkqB[t]];
        }
        #pragma unroll
        for (int kk = 0; kk < 16; kk++) {
            float4 va0 = *(float4*)&As[buf][kk][tr * 8];
            float4 va1 = *(float4*)&As[buf][kk][tr * 8 + 4];
            float4 vb0 = *(float4*)&Bs[buf][kk][tc * 8];
            float4 vb1 = *(float4*)&Bs[buf][kk][tc * 8 + 4];
            unsigned long long a2[4], bd[8];
            PACK2(a2[0], va0.x, va0.y); PACK2(a2[1], va0.z, va0.w);
            PACK2(a2[2], va1.x, va1.y); PACK2(a2[3], va1.z, va1.w);
            DUP2(bd[0], vb0.x); DUP2(bd[1], vb0.y); DUP2(bd[2], vb0.z); DUP2(bd[3], vb0.w);
            DUP2(bd[4], vb1.x); DUP2(bd[5], vb1.y); DUP2(bd[6], vb1.z); DUP2(bd[7], vb1.w);
            #pragma unroll
            for (int p = 0; p < 4; p++)
                #pragma unroll
                for (int j = 0; j < 8; j++) FMA2(accP[p][j], a2[p], bd[j]);
        }
        if (c + 1 < nch) {
            int nb = buf ^ 1;
            #pragma unroll
            for (int t = 0; t < 4; t++) {
                As[nb][lkqA[t] + 0][lrowA[t]] = aReg[t].x; As[nb][lkqA[t] + 1][lrowA[t]] = aReg[t].y;
                As[nb][lkqA[t] + 2][lrowA[t]] = aReg[t].z; As[nb][lkqA[t] + 3][lrowA[t]] = aReg[t].w;
            }
            #pragma unroll
            for (int t = 0; t < 2; t++) {
                Bs[nb][lkqB[t] + 0][lrowB[t]] = bReg[t].x; Bs[nb][lkqB[t] + 1][lrowB[t]] = bReg[t].y;
                Bs[nb][lkqB[t] + 2][lrowB[t]] = bReg[t].z; Bs[nb][lkqB[t] + 3][lrowB[t]] = bReg[t].w;
            }
        }
        __syncthreads();
    }

    float acc[8][8];
    #pragma unroll
    for (int p = 0; p < 4; p++)
        #pragma unroll
        for (int j = 0; j < 8; j++) UNPACK2(acc[2 * p][j], acc[2 * p + 1][j], accP[p][j]);

    #pragma unroll
    for (int i = 0; i < 8; i++) {
        int gm = brow + tr * 8 + i;
        if (gm >= M) continue;
        *(float4*)&C[(size_t)gm * 64 + tc * 8] =
            make_float4(acc[i][0], acc[i][1], acc[i][2], acc[i][3]);
        *(float4*)&C[(size_t)gm * 64 + tc * 8 + 4] =
            make_float4(acc[i][4], acc[i][5], acc[i][6], acc[i][7]);
    }

    float asv[8], adv[8];
    #pragma unroll
    for (int j = 0; j < 8; j++) {
        asv[j] = as_[tc * 8 + j];
        adv[j] = ad_[tc * 8 + j];
    }
    #pragma unroll
    for (int i = 0; i < 8; i++) {
        float ss = 0.f, dd = 0.f;
        #pragma unroll
        for (int j = 0; j < 8; j++) {
            ss += acc[i][j] * asv[j];
            dd += acc[i][j] * adv[j];
        }
        #pragma unroll
        for (int o = 4; o >= 1; o >>= 1) {
            ss += __shfl_xor_sync(0xffffffffu, ss, o);
            dd += __shfl_xor_sync(0xffffffffu, dd, o);
        }
        int gm = brow + tr * 8 + i;
        if ((lane & 7) == 0 && gm < M) {
            s_[gm] = ss;
            d_[gm] = dd;
        }
    }
}

// ---------------- fused GAT layer, H=4 (optional bf16-split output) ----------
__global__ void gat_fused4(const int* __restrict__ rowptr, const int* __restrict__ ecol,
                           const float* __restrict__ s_, const float* __restrict__ d_,
                           const float* __restrict__ h, const float* __restrict__ bias,
                           const float* __restrict__ lw, const float* __restrict__ lb,
                           float* __restrict__ outp, unsigned* __restrict__ xhi,
                           unsigned* __restrict__ xlo, int n, int do_elu, int splitOut) {
    int warp = (blockIdx.x * blockDim.x + threadIdx.x) >> 5;
    int lane = threadIdx.x & 31;
    if (warp >= n) return;
    int node = warp;
    int start = rowptr[node], end = rowptr[node + 1];

    float4 dv4 = ((const float4*)d_)[node];
    float dsel[4] = {dv4.x, dv4.y, dv4.z, dv4.w};
    float4 sv4 = ((const float4*)s_)[node];
    float selfv[4] = {leaky(sv4.x + dsel[0]), leaky(sv4.y + dsel[1]),
                      leaky(sv4.z + dsel[2]), leaky(sv4.w + dsel[3])};

    float m[4], s[4];
    #pragma unroll
    for (int q = 0; q < 4; q++) {
        m[q] = (lane == 0) ? selfv[q] : -3e38f;
        s[q] = (lane == 0) ? 1.f : 0.f;
    }
    for (int e = start + lane; e < end; e += 32) {
        int src = ecol[e];
        float4 sv = ((const float4*)s_)[src];
        float v[4] = {leaky(sv.x + dsel[0]), leaky(sv.y + dsel[1]),
                      leaky(sv.z + dsel[2]), leaky(sv.w + dsel[3])};
        #pragma unroll
        for (int q = 0; q < 4; q++) {
            float nm = fmaxf(m[q], v[q]);
            s[q] = s[q] * expf(m[q] - nm) + expf(v[q] - nm);
            m[q] = nm;
        }
    }
    #pragma unroll
    for (int o = 16; o > 0; o >>= 1) {
        #pragma unroll
        for (int q = 0; q < 4; q++) {
            float om = __shfl_xor_sync(0xffffffffu, m[q], o);
            float os = __shfl_xor_sync(0xffffffffu, s[q], o);
            float nm = fmaxf(m[q], om);
            s[q] = s[q] * expf(m[q] - nm) + os * expf(om - nm);
            m[q] = nm;
        }
    }
    float inv[4], aself[4];
    #pragma unroll
    for (int q = 0; q < 4; q++) {
        inv[q] = 1.f / (s[q] + 1e-16f);
        aself[q] = expf(selfv[q] - m[q]) * inv[q];
    }

    int hl = lane & 3;
    float d_hl = (hl == 0) ? dsel[0] : (hl == 1) ? dsel[1] : (hl == 2) ? dsel[2] : dsel[3];
    float m_hl = (hl == 0) ? m[0]    : (hl == 1) ? m[1]    : (hl == 2) ? m[2]    : m[3];
    float i_hl = (hl == 0) ? inv[0]  : (hl == 1) ? inv[1]  : (hl == 2) ? inv[2]  : inv[3];
    int hA = lane >> 4;
    float asA = hA ? aself[1] : aself[0];
    float asB = hA ? aself[3] : aself[2];

    const float4* hps4 = (const float4*)(h + (size_t)node * 256);
    float4 acc0 = f4scale(hps4[lane], asA);
    float4 acc1 = f4scale(hps4[lane + 32], asB);

    for (int e0 = start; e0 < end; e0 += 8) {
        int me = e0 + (lane >> 2);
        float alpha = 0.f; int msrc = 0;
        if (me < end) {
            msrc = ecol[me];
            float v = leaky(s_[(size_t)msrc * 4 + hl] + d_hl);
            alpha = expf(v - m_hl) * i_hl;
        }
        int cnt = end - e0; if (cnt > 8) cnt = 8;
        for (int j0 = 0; j0 < cnt; j0 += 4) {
            int jn = cnt - j0; if (jn > 4) jn = 4;
            float4 pa[4], pb[4];
            float a0[4], a1[4];
            #pragma unroll
            for (int j = 0; j < 4; j++) {
                int src = __shfl_sync(0xffffffffu, msrc, (j0 + j) * 4);
                a0[j] = __shfl_sync(0xffffffffu, alpha, (j0 + j) * 4 + hA);
                a1[j] = __shfl_sync(0xffffffffu, alpha, (j0 + j) * 4 + 2 + hA);
                if (j < jn) {
                    const float4* hp4 = (const float4*)(h + (size_t)src * 256);
                    pa[j] = hp4[lane];
                    pb[j] = hp4[lane + 32];
                }
            }
            #pragma unroll
            for (int j = 0; j < 4; j++) {
                if (j < jn) {
                    acc0 = f4fma(pa[j], a0[j], acc0);
                    acc1 = f4fma(pb[j], a1[j], acc1);
                }
            }
        }
    }

    const float4* b4 = (const float4*)bias;
    const float4* lw4 = (const float4*)lw;
    const float4* lb4 = (const float4*)lb;
    float4 v0 = f4add(acc0, b4[lane]);
    float4 v1 = f4add(acc1, b4[lane + 32]);
    if (do_elu) {
        v0.x = v0.x > 0.f ? v0.x : expf(v0.x) - 1.f;
        v0.y = v0.y > 0.f ? v0.y : expf(v0.y) - 1.f;
        v0.z = v0.z > 0.f ? v0.z : expf(v0.z) - 1.f;
        v0.w = v0.w > 0.f ? v0.w : expf(v0.w) - 1.f;
        v1.x = v1.x > 0.f ? v1.x : expf(v1.x) - 1.f;
        v1.y = v1.y > 0.f ? v1.y : expf(v1.y) - 1.f;
        v1.z = v1.z > 0.f ? v1.z : expf(v1.z) - 1.f;
        v1.w = v1.w > 0.f ? v1.w : expf(v1.w) - 1.f;
    }
    float ssum = v0.x + v0.y + v0.z + v0.w + v1.x + v1.y + v1.z + v1.w;
    ssum = warpSum(ssum);
    float mu = ssum * (1.f / 256.f);
    float t, vs = 0.f;
    t = v0.x - mu; vs += t * t; t = v0.y - mu; vs += t * t;
    t = v0.z - mu; vs += t * t; t = v0.w - mu; vs += t * t;
    t = v1.x - mu; vs += t * t; t = v1.y - mu; vs += t * t;
    t = v1.z - mu; vs += t * t; t = v1.w - mu; vs += t * t;
    vs = warpSum(vs);
    float rs = rsqrtf(vs * (1.f / 256.f) + 1e-5f);
    float4 w0 = lw4[lane], w1 = lw4[lane + 32];
    float4 c0 = lb4[lane], c1 = lb4[lane + 32];
    float4 o0 = make_float4((v0.x - mu) * rs * w0.x + c0.x, (v0.y - mu) * rs * w0.y + c0.y,
                            (v0.z - mu) * rs * w0.z + c0.z, (v0.w - mu) * rs * w0.w + c0.w);
    float4 o1 = make_float4((v1.x - mu) * rs * w1.x + c1.x, (v1.y - mu) * rs * w1.y + c1.y,
                            (v1.z - mu) * rs * w1.z + c1.z, (v1.w - mu) * rs * w1.w + c1.w);
    float4* out4 = (float4*)(outp + (size_t)node * 256);
    out4[lane] = o0;
    out4[lane + 32] = o1;

    if (splitOut) {
        unsigned* xh = xhi + (size_t)node * 128;
        unsigned* xl = xlo + (size_t)node * 128;
        *(uint2*)&xh[lane * 2] = make_uint2(packbf(o0.x, o0.y), packbf(o0.z, o0.w));
        *(uint2*)&xh[64 + lane * 2] = make_uint2(packbf(o1.x, o1.y), packbf(o1.z, o1.w));
        *(uint2*)&xl[lane * 2] = make_uint2(
            packbf(o0.x - bfr(o0.x), o0.y - bfr(o0.y)),
            packbf(o0.z - bfr(o0.z), o0.w - bfr(o0.w)));
        *(uint2*)&xl[64 + lane * 2] = make_uint2(
            packbf(o1.x - bfr(o1.x), o1.y - bfr(o1.y)),
            packbf(o1.z - bfr(o1.z), o1.w - bfr(o1.w)));
    }
}

// ---------------- fused GAT layer, H=1 (D=64) ----------
__global__ void gat_fused1(const int* __restrict__ rowptr, const int* __restrict__ ecol,
                           const float* __restrict__ s_, const float* __restrict__ d_,
                           const float* __restrict__ h, const float* __restrict__ bias,
                           const float* __restrict__ lw, const float* __restrict__ lb,
                           float* __restrict__ outp, int n, int do_elu) {
    int warp = (blockIdx.x * blockDim.x + threadIdx.x) >> 5;
    int lane = threadIdx.x & 31;
    if (warp >= n) return;
    int node = warp;
    int start = rowptr[node], end = rowptr[node + 1];

    float dsel = d_[node];
    float selfv = leaky(s_[node] + dsel);
    float m = (lane == 0) ? selfv : -3e38f;
    float s = (lane == 0) ? 1.f : 0.f;
    for (int e = start + lane; e < end; e += 32) {
        float v = leaky(s_[ecol[e]] + dsel);
        float nm = fmaxf(m, v);
        s = s * expf(m - nm) + expf(v - nm);
        m = nm;
    }
    #pragma unroll
    for (int o = 16; o > 0; o >>= 1) {
        float om = __shfl_xor_sync(0xffffffffu, m, o);
        float os = __shfl_xor_sync(0xffffffffu, s, o);
        float nm = fmaxf(m, om);
        s = s * expf(m - nm) + os * expf(om - nm);
        m = nm;
    }
    float inv = 1.f / (s + 1e-16f);
    float aself = expf(selfv - m) * inv;

    int half = lane >> 4, f = lane & 15;
    const float4* hps4 = (const float4*)(h + (size_t)node * 64);
    float4 acc = (half == 0) ? f4scale(hps4[f], aself) : make_float4(0.f, 0.f, 0.f, 0.f);

    for (int e0 = start; e0 < end; e0 += 8) {
        int me = e0 + lane;
        float alpha = 0.f; int msrc = 0;
        if (lane < 8 && me < end) {
            msrc = ecol[me];
            alpha = expf(leaky(s_[msrc] + dsel) - m) * inv;
        }
        int cnt = end - e0; if (cnt > 8) cnt = 8;
        for (int j = 0; j < cnt; j += 2) {
            int eidx = j + half;
            int src = __shfl_sync(0xffffffffu, msrc, eidx);
            float al = __shfl_sync(0xffffffffu, alpha, eidx);
            if (eidx < cnt) {
                const float4* hp4 = (const float4*)(h + (size_t)src * 64);
                acc = f4fma(hp4[f], al, acc);
            }
        }
    }
    acc.x += __shfl_xor_sync(0xffffffffu, acc.x, 16);
    acc.y += __shfl_xor_sync(0xffffffffu, acc.y, 16);
    acc.z += __shfl_xor_sync(0xffffffffu, acc.z, 16);
    acc.w += __shfl_xor_sync(0xffffffffu, acc.w, 16);

    const float4* b4 = (const float4*)bias;
    const float4* lw4 = (const float4*)lw;
    const float4* lb4 = (const float4*)lb;
    float4 v = f4add(acc, b4[f]);
    if (do_elu) {
        v.x = v.x > 0.f ? v.x : expf(v.x) - 1.f;
        v.y = v.y > 0.f ? v.y : expf(v.y) - 1.f;
        v.z = v.z > 0.f ? v.z : expf(v.z) - 1.f;
        v.w = v.w > 0.f ? v.w : expf(v.w) - 1.f;
    }
    float ssum = warpSum(v.x + v.y + v.z + v.w);
    float mu = ssum * (1.f / 128.f);
    float t, vs = 0.f;
    t = v.x - mu; vs += t * t; t = v.y - mu; vs += t * t;
    t = v.z - mu; vs += t * t; t = v.w - mu; vs += t * t;
    vs = warpSum(vs);
    float rs = rsqrtf(vs * (1.f / 128.f) + 1e-5f);
    if (half == 0) {
        float4 w = lw4[f], c = lb4[f];
        float4* out4 = (float4*)(outp + (size_t)node * 64);
        out4[f] = make_float4((v.x - mu) * rs * w.x + c.x, (v.y - mu) * rs * w.y + c.y,
                              (v.z - mu) * rs * w.z + c.z, (v.w - mu) * rs * w.w + c.w);
    }
}

// ---------------- final MLP head ----------------
__global__ void head_kernel(const float* __restrict__ h3, const int* __restrict__ role,
                            const float* __restrict__ rc, const float* __restrict__ p1w,
                            const float* __restrict__ p2w, const float* __restrict__ p2b,
                            float* __restrict__ z, int n) {
    extern __shared__ float sm[];
    float* sp1 = sm;
    float* sp2 = sp1 + 64 * 64;
    float* sz  = sp2 + 64 * 64;
    float* sz1 = sz + 4 * 64;
    int tid = threadIdx.x;
    for (int i = tid; i < 64 * 64; i += 256) {
        int j = i >> 6, k = i & 63;
        sp1[k * 64 + j] = p1w[j * 128 + k];
        sp2[k * 64 + j] = p2w[i];
    }
    __syncthreads();
    int g = tid >> 6, j = tid & 63;
    float b2v = p2b[j];
    for (int it = 0; it < 16; it++) {
        int node = blockIdx.x * 64 + it * 4 + g;
        bool valid = node < n;
        float rcv = 0.f;
        if (valid) {
            sz[g * 64 + j] = h3[(size_t)node * 64 + j];
            rcv = rc[role[node] * 64 + j];
        }
        __syncthreads();
        float acc = rcv;
        #pragma unroll 8
        for (int k = 0; k < 64; k++) acc += sp1[k * 64 + j] * sz[g * 64 + k];
        sz1[g * 64 + j] = fmaxf(acc, 0.f);
        __syncthreads();
        float acc2 = b2v;
        #pragma unroll 8
        for (int k = 0; k < 64; k++) acc2 += sp2[k * 64 + j] * sz1[g * 64 + k];
        if (valid) z[(size_t)node * 64 + j] = acc2;
    }
}

// ---------------- host orchestration ----------------
extern "C" void kernel_launch(void* const* d_in, const int* in_sizes, int n_in,
                              void* d_out, int out_size) {
    const float* x   = (const float*)d_in[0];
    const void*  ei  = d_in[1];
    const void*  rid = d_in[2];
    const float* W1  = (const float*)d_in[3];
    const float* a1s = (const float*)d_in[4];
    const float* a1d = (const float*)d_in[5];
    const float* b1  = (const float*)d_in[6];
    const float* W2  = (const float*)d_in[7];
    const float* a2s = (const float*)d_in[8];
    const float* a2d = (const float*)d_in[9];
    const float* b2  = (const float*)d_in[10];
    const float* W3  = (const float*)d_in[11];
    const float* a3s = (const float*)d_in[12];
    const float* a3d = (const float*)d_in[13];
    const float* b3  = (const float*)d_in[14];
    const float* ln1w = (const float*)d_in[15];
    const float* ln1b = (const float*)d_in[16];
    const float* ln2w = (const float*)d_in[17];
    const float* ln2b = (const float*)d_in[18];
    const float* ln3w = (const float*)d_in[19];
    const float* ln3b = (const float*)d_in[20];
    const float* rt   = (const float*)d_in[21];
    const float* p1w  = (const float*)d_in[22];
    const float* p1b  = (const float*)d_in[23];
    const float* p2w  = (const float*)d_in[24];
    const float* p2b  = (const float*)d_in[25];
    float* z = (float*)d_out;

    float *hbuf, *xbuf, *ybuf, *sp, *dp, *rcp;
    unsigned *xhip, *xlop, *whip, *wlop;
    int *srcp, *dstp, *ecolp, *rowp, *degp, *curp, *bsump, *rolep, *flagp;
    cudaGetSymbolAddress((void**)&hbuf, g_h);
    cudaGetSymbolAddress((void**)&xbuf, g_x);
    cudaGetSymbolAddress((void**)&ybuf, g_y);
    cudaGetSymbolAddress((void**)&sp, g_s);
    cudaGetSymbolAddress((void**)&dp, g_d);
    cudaGetSymbolAddress((void**)&rcp, g_rc);
    cudaGetSymbolAddress((void**)&xhip, g_xhi);
    cudaGetSymbolAddress((void**)&xlop, g_xlo);
    cudaGetSymbolAddress((void**)&whip, g_whi);
    cudaGetSymbolAddress((void**)&wlop, g_wlo);
    cudaGetSymbolAddress((void**)&srcp, g_src);
    cudaGetSymbolAddress((void**)&dstp, g_dst);
    cudaGetSymbolAddress((void**)&ecolp, g_ecol);
    cudaGetSymbolAddress((void**)&rowp, g_rowptr);
    cudaGetSymbolAddress((void**)&degp, g_deg);
    cudaGetSymbolAddress((void**)&curp, g_cursor);
    cudaGetSymbolAddress((void**)&bsump, g_bsum);
    cudaGetSymbolAddress((void**)&rolep, g_role);
    cudaGetSymbolAddress((void**)&flagp, g_is64);

    const int n = NN, E = EE;
    const int nb = (n + 1023) / 1024;

    dim3 gg(2, (n + 127) / 128);
    int g3blocks = (n + 127) / 128;
    int fusedBlocks = (n * 32 + 255) / 256;

    cudaFuncSetAttribute(gemm_bf16, cudaFuncAttributeMaxDynamicSharedMemorySize,
                         GEMM_BF16_SMEM);

    // conversions first (no deps) so gemm1 stays in the ncu capture slot
    split_kernel<<<(n * 64 / 4 + 255) / 256, 256>>>(x, xhip, xlop, n * 64 / 4);
    split_kernel<<<16, 256>>>(W1, whip, wlop, 256 * 64 / 4);
    detect_kernel<<<1, 32>>>((const unsigned int*)ei, flagp);
    cudaMemsetAsync(degp, 0, n * sizeof(int));
    gemm_bf16<<<gg, 256, GEMM_BF16_SMEM>>>(xhip, xlop, whip, wlop, hbuf, n, 32,
                                           a1s, a1d, sp, dp, 4);
    prep_kernel<<<(E + 255) / 256, 256>>>(ei, rid, srcp, dstp, degp, rolep, flagp, E, n);
    scan_reduce_kernel<<<nb, 1024>>>(degp, bsump, n);
    scan_final_kernel<<<nb, 1024>>>(degp, bsump, rowp, curp, n);
    scatter_kernel<<<(E + 255) / 256, 256>>>(srcp, dstp, curp, ecolp, E);
    role_prep_kernel<<<1, 128>>>(rt, p1w, p1b, rcp);

    // layer 1 gather (emits bf16-split output for layer-2 GEMM A)
    gat_fused4<<<fusedBlocks, 256>>>(rowp, ecolp, sp, dp, hbuf, b1, ln1w, ln1b,
                                     xbuf, xhip, xlop, n, 1, 1);

    // layer 2
    split_kernel<<<64, 256>>>(W2, whip, wlop, 256 * 256 / 4);
    gemm_bf16<<<gg, 256, GEMM_BF16_SMEM>>>(xhip, xlop, whip, wlop, hbuf, n, 128,
                                           a2s, a2d, sp, dp, 4);
    gat_fused4<<<fusedBlocks, 256>>>(rowp, ecolp, sp, dp, hbuf, b2, ln2w, ln2b,
                                     xbuf, xhip, xlop, n, 1, 0);

    // layer 3 (fp32 FFMA2 path)
    gemm_nt64<<<g3blocks, 128>>>(xbuf, W3, hbuf, n, 256, a3s, a3d, sp, dp);
    gat_fused1<<<fusedBlocks, 256>>>(rowp, ecolp, sp, dp, hbuf, b3, ln3w, ln3b, ybuf, n, 0);

    // final MLP head
    size_t smem = (64 * 64 + 64 * 64 + 4 * 64 + 4 * 64) * sizeof(float);
    cudaFuncSetAttribute(head_kernel, cudaFuncAttributeMaxDynamicSharedMemorySize, (int)smem);
    head_kernel<<<(n + 63) / 64, 256, smem>>>(ybuf, rolep, rcp, p1w, p2w, p2b, z, n);
}

// round 17
// speedup vs baseline: 1.2395x; 1.0616x over previous
#include <cuda_runtime.h>
#include <cuda_bf16.h>
#include <math.h>

#define NN 50000
#define EE 400000
#define DMAX 256

// ---------------- scratch ----------------
__device__ float g_h[(size_t)NN * DMAX];
__device__ float g_x[(size_t)NN * DMAX];
__device__ float g_y[(size_t)NN * DMAX];
__device__ float g_s[NN * 4];
__device__ float g_d[NN * 4];
__device__ float g_rc[2 * 64];
__device__ unsigned g_xhi[(size_t)NN * 128];
__device__ unsigned g_xlo[(size_t)NN * 128];
__device__ unsigned g_whi[256 * 128];
__device__ unsigned g_wlo[256 * 128];
__device__ int g_src[EE];
__device__ int g_dst[EE];
__device__ int g_ecol[EE];
__device__ int g_rowptr[NN + 1];
__device__ int g_deg[NN];
__device__ int g_cursor[NN];
__device__ int g_bsum[64];
__device__ int g_role[NN];
__device__ int g_is64;

// ---------------- helpers ----------------
__device__ __forceinline__ float warpSum(float v) {
    #pragma unroll
    for (int o = 16; o > 0; o >>= 1) v += __shfl_xor_sync(0xffffffffu, v, o);
    return v;
}
__device__ __forceinline__ int warpSumI(int v) {
    #pragma unroll
    for (int o = 16; o > 0; o >>= 1) v += __shfl_xor_sync(0xffffffffu, v, o);
    return v;
}
__device__ __forceinline__ int warpInclScan(int v, int lane) {
    #pragma unroll
    for (int o = 1; o < 32; o <<= 1) {
        int t = __shfl_up_sync(0xffffffffu, v, o);
        if (lane >= o) v += t;
    }
    return v;
}
__device__ __forceinline__ float leaky(float v) { return fmaxf(v, 0.2f * v); }
__device__ __forceinline__ float4 f4fma(float4 a, float s, float4 c) {
    c.x += a.x * s; c.y += a.y * s; c.z += a.z * s; c.w += a.w * s; return c;
}
__device__ __forceinline__ float4 f4scale(float4 a, float s) {
    return make_float4(a.x * s, a.y * s, a.z * s, a.w * s);
}
__device__ __forceinline__ float4 f4add(float4 a, float4 b) {
    return make_float4(a.x + b.x, a.y + b.y, a.z + b.z, a.w + b.w);
}

// packed f32x2 ops
#define PACK2(d, x, y) asm("mov.b64 %0, {%1, %2};" : "=l"(d) : "f"(x), "f"(y))
#define DUP2(d, x)     asm("mov.b64 %0, {%1, %1};" : "=l"(d) : "f"(x))
#define FMA2(c, a, b)  asm("fma.rn.f32x2 %0, %1, %2, %0;" : "+l"(c) : "l"(a), "l"(b))
#define UNPACK2(x, y, d) asm("mov.b64 {%0, %1}, %2;" : "=f"(x), "=f"(y) : "l"(d))

// bf16 helpers
__device__ __forceinline__ unsigned packbf(float lo_elem, float hi_elem) {
    unsigned r;
    asm("cvt.rn.bf16x2.f32 %0, %1, %2;" : "=r"(r) : "f"(hi_elem), "f"(lo_elem));
    return r;
}
__device__ __forceinline__ float bfr(float f) {
    return __bfloat162float(__float2bfloat16(f));
}

#define MMA_BF16(c, a, b)                                                        \
    asm volatile("mma.sync.aligned.m16n8k16.row.col.f32.bf16.bf16.f32 "          \
                 "{%0,%1,%2,%3}, {%4,%5,%6,%7}, {%8,%9}, {%0,%1,%2,%3};"         \
                 : "+f"((c)[0]), "+f"((c)[1]), "+f"((c)[2]), "+f"((c)[3])        \
                 : "r"((a)[0]), "r"((a)[1]), "r"((a)[2]), "r"((a)[3]),           \
                   "r"((b)[0]), "r"((b)[1]))

#define LDM4(r, a)                                                               \
    asm volatile("ldmatrix.sync.aligned.m8n8.x4.shared.b16 {%0,%1,%2,%3}, [%4];" \
                 : "=r"((r)[0]), "=r"((r)[1]), "=r"((r)[2]), "=r"((r)[3])        \
                 : "r"(a))

__device__ __forceinline__ void cpasync16(unsigned dst, const void* src, bool valid) {
    int sz = valid ? 16 : 0;
    asm volatile("cp.async.cg.shared.global [%0], [%1], 16, %2;"
                 :: "r"(dst), "l"(src), "r"(sz));
}
#define CP_COMMIT() asm volatile("cp.async.commit_group;")

// ---------------- bf16 hi/lo split ----------------
__global__ void split_kernel(const float* __restrict__ in, unsigned* __restrict__ hi,
                             unsigned* __restrict__ lo, int n4) {
    int i = blockIdx.x * blockDim.x + threadIdx.x;
    if (i >= n4) return;
    float4 v = ((const float4*)in)[i];
    float h0 = bfr(v.x), h1 = bfr(v.y), h2 = bfr(v.z), h3 = bfr(v.w);
    uint2 hw = make_uint2(packbf(v.x, v.y), packbf(v.z, v.w));
    uint2 lw = make_uint2(packbf(v.x - h0, v.y - h1), packbf(v.z - h2, v.w - h3));
    ((uint2*)hi)[i] = hw;
    ((uint2*)lo)[i] = lw;
}

// ---------------- dtype detect + prep ----------------
__global__ void detect_kernel(const unsigned int* __restrict__ w, int* flag) {
    if (threadIdx.x == 0 && blockIdx.x == 0) {
        int is64 = 1;
        for (int i = 0; i < 64; i++)
            if (w[2 * i + 1] != 0u) { is64 = 0; break; }
        *flag = is64;
    }
}

__global__ void prep_kernel(const void* __restrict__ ei, const void* __restrict__ rid,
                            int* __restrict__ src, int* __restrict__ dst,
                            int* __restrict__ deg, int* __restrict__ role,
                            const int* __restrict__ flag, int E, int n) {
    int i = blockIdx.x * blockDim.x + threadIdx.x;
    int is64 = *flag;
    if (i < E) {
        int s, d;
        if (is64) {
            const long long* p = (const long long*)ei;
            s = (int)p[i];
            d = (int)p[(size_t)E + i];
        } else {
            const int* p = (const int*)ei;
            s = p[i];
            d = p[E + i];
        }
        src[i] = s;
        dst[i] = d;
        atomicAdd(&deg[d], 1);
    }
    if (i < n) {
        if (is64) role[i] = (int)((const long long*)rid)[i];
        else      role[i] = ((const int*)rid)[i];
    }
}

// ---------------- 2-phase scan ----------------
__global__ void scan_reduce_kernel(const int* __restrict__ deg, int* __restrict__ bsum, int n) {
    __shared__ int sw[32];
    int tid = threadIdx.x, lane = tid & 31, w = tid >> 5;
    int i = blockIdx.x * 1024 + tid;
    int v = (i < n) ? deg[i] : 0;
    v = warpSumI(v);
    if (lane == 0) sw[w] = v;
    __syncthreads();
    if (w == 0) {
        int t = sw[lane];
        t = warpSumI(t);
        if (lane == 0) bsum[blockIdx.x] = t;
    }
}

__global__ void scan_final_kernel(const int* __restrict__ deg, const int* __restrict__ bsum,
                                  int* __restrict__ rowptr, int* __restrict__ cursor, int n) {
    __shared__ int sw[32];
    __shared__ int partial[2];
    int tid = threadIdx.x, lane = tid & 31, w = tid >> 5;
    int bid = blockIdx.x;
    if (tid < 64) {
        int v = (tid < bid) ? bsum[tid] : 0;
        v = warpSumI(v);
        if ((tid & 31) == 0) partial[tid >> 5] = v;
    }
    int i = bid * 1024 + tid;
    int v = (i < n) ? deg[i] : 0;
    int iv = warpInclScan(v, lane);
    if (lane == 31) sw[w] = iv;
    __syncthreads();
    int base = partial[0] + partial[1];
    if (w == 0) {
        int t = sw[lane];
        t = warpInclScan(t, lane);
        sw[lane] = t;
    }
    __syncthreads();
    int offs = ((w > 0) ? sw[w - 1] : 0) + base;
    int incl = iv + offs;
    if (i < n) {
        rowptr[i + 1] = incl;
        cursor[i] = incl - v;
    }
    if (i == 0) rowptr[0] = 0;
}

__global__ void scatter_kernel(const int* __restrict__ src, const int* __restrict__ dst,
                               int* __restrict__ cursor, int* __restrict__ ecol, int E) {
    int i = blockIdx.x * blockDim.x + threadIdx.x;
    if (i >= E) return;
    int pos = atomicAdd(&cursor[dst[i]], 1);
    ecol[pos] = src[i];
}

// ---------------- role contribution precompute ----------------
__global__ void role_prep_kernel(const float* __restrict__ rt, const float* __restrict__ p1w,
                                 const float* __restrict__ p1b, float* __restrict__ rc) {
    int tid = threadIdx.x;
    int r = tid >> 6, j = tid & 63;
    float acc = p1b[j];
    #pragma unroll 8
    for (int k = 0; k < 64; k++)
        acc += rt[r * 64 + k] * p1w[j * 128 + 64 + k];
    rc[r * 64 + j] = acc;
}

// ---------------- BF16x3 tensor-core GEMM 128x128, cp.async + ldmatrix ----------------
#define CROW 20
#define CMAT (128 * CROW)
#define CBUF (4 * CMAT)
#define GEMM_BF16_SMEM (2 * CBUF * 4)
__global__ void __launch_bounds__(256, 2) gemm_bf16(
        const unsigned* __restrict__ Ahi, const unsigned* __restrict__ Alo,
        const unsigned* __restrict__ Bhi, const unsigned* __restrict__ Blo,
        float* __restrict__ C, int M, int KW,
        const float* __restrict__ as_, const float* __restrict__ ad_,
        float* __restrict__ s_, float* __restrict__ d_, int H) {
    extern __shared__ unsigned smemU[];
    unsigned sbase;
    asm("{ .reg .u64 t; cvta.to.shared.u64 t, %1; cvt.u32.u64 %0, t; }"
        : "=r"(sbase) : "l"(smemU));
    int tid = threadIdx.x, lane = tid & 31, warp = tid >> 5;
    int wm = warp & 3, wn = warp >> 2;
    int brow = blockIdx.y * 128, bcol = blockIdx.x * 128;
    float c[2][8][4];
    #pragma unroll
    for (int mt = 0; mt < 2; mt++)
        #pragma unroll
        for (int nt = 0; nt < 8; nt++)
            #pragma unroll
            for (int r = 0; r < 4; r++) c[mt][nt][r] = 0.f;

    const int nch = KW >> 4;

    unsigned aoffw = (unsigned)((wm * 32 + (lane & 7) + ((lane >> 3) & 1) * 8) * CROW
                                + ((lane >> 4) & 1) * 4);
    unsigned boffw = (unsigned)((wn * 64 + (lane & 7) + ((lane >> 4) & 1) * 8) * CROW
                                + ((lane >> 3) & 1) * 4);

    auto issue = [&](int ch, int b) {
        #pragma unroll
        for (int t = 0; t < 8; t++) {
            int segid = tid + t * 256;
            int mtx = segid >> 9;
            int row = (segid >> 2) & 127;
            int seg = segid & 3;
            const unsigned* gp;
            bool valid = true;
            int grow;
            if (mtx == 0)      { gp = Ahi; grow = brow + row; valid = grow < M; }
            else if (mtx == 1) { gp = Alo; grow = brow + row; valid = grow < M; }
            else if (mtx == 2) { gp = Bhi; grow = bcol + row; }
            else               { gp = Blo; grow = bcol + row; }
            unsigned dst = sbase + (unsigned)(((b * 4 + mtx) * CMAT) + row * CROW + seg * 4) * 4u;
            cpasync16(dst, gp + (size_t)grow * KW + ch * 16 + seg * 4, valid);
        }
        CP_COMMIT();
    };

    issue(0, 0);

    for (int ch = 0; ch < nch; ch++) {
        int b = ch & 1;
        if (ch + 1 < nch) {
            issue(ch + 1, b ^ 1);
            asm volatile("cp.async.wait_group 1;");
        } else {
            asm volatile("cp.async.wait_group 0;");
        }
        __syncthreads();
        unsigned baseAhi = sbase + ((b * 4 + 0) * CMAT + aoffw) * 4u;
        unsigned baseAlo = sbase + ((b * 4 + 1) * CMAT + aoffw) * 4u;
        unsigned baseBhi = sbase + ((b * 4 + 2) * CMAT + boffw) * 4u;
        unsigned baseBlo = sbase + ((b * 4 + 3) * CMAT + boffw) * 4u;

        #pragma unroll
        for (int kg = 0; kg < 2; kg++) {
            unsigned kb = (unsigned)(kg * 8) * 4u;
            unsigned ah[2][4], al[2][4];
            LDM4(ah[0], baseAhi + kb);
            LDM4(ah[1], baseAhi + 16 * CROW * 4 + kb);
            LDM4(al[0], baseAlo + kb);
            LDM4(al[1], baseAlo + 16 * CROW * 4 + kb);
            #pragma unroll
            for (int pp = 0; pp < 4; pp++) {
                unsigned th[4], tl[4];
                LDM4(th, baseBhi + pp * 16 * CROW * 4 + kb);
                LDM4(tl, baseBlo + pp * 16 * CROW * 4 + kb);
                unsigned b0h[2] = {th[0], th[1]}, b1h[2] = {th[2], th[3]};
                unsigned b0l[2] = {tl[0], tl[1]}, b1l[2] = {tl[2], tl[3]};
                int n0 = pp * 2, n1 = pp * 2 + 1;
                MMA_BF16(c[0][n0], ah[0], b0h);
                MMA_BF16(c[1][n0], ah[1], b0h);
                MMA_BF16(c[0][n1], ah[0], b1h);
                MMA_BF16(c[1][n1], ah[1], b1h);
                MMA_BF16(c[0][n0], ah[0], b0l);
                MMA_BF16(c[1][n0], ah[1], b0l);
                MMA_BF16(c[0][n1], ah[0], b1l);
                MMA_BF16(c[1][n1], ah[1], b1l);
                MMA_BF16(c[0][n0], al[0], b0h);
                MMA_BF16(c[1][n0], al[1], b0h);
                MMA_BF16(c[0][n1], al[0], b1h);
                MMA_BF16(c[1][n1], al[1], b1h);
            }
        }
        __syncthreads();
    }

    #pragma unroll
    for (int mt = 0; mt < 2; mt++) {
        #pragma unroll
        for (int nt = 0; nt < 8; nt++) {
            int row = brow + wm * 32 + mt * 16 + (lane >> 2);
            int col = bcol + wn * 64 + nt * 8 + 2 * (lane & 3);
            if (row < M)
                *(float2*)&C[(size_t)row * 256 + col] = make_float2(c[mt][nt][0], c[mt][nt][1]);
            if (row + 8 < M)
                *(float2*)&C[(size_t)(row + 8) * 256 + col] = make_float2(c[mt][nt][2], c[mt][nt][3]);
        }
    }

    int head = blockIdx.x * 2 + wn;
    #pragma unroll
    for (int mt = 0; mt < 2; mt++) {
        #pragma unroll
        for (int p = 0; p < 2; p++) {
            float ss = 0.f, dd = 0.f;
            #pragma unroll
            for (int nt = 0; nt < 8; nt++) {
                int cc = nt * 8 + 2 * (lane & 3);
                float c0 = c[mt][nt][p * 2], c1 = c[mt][nt][p * 2 + 1];
                ss += c0 * as_[head * 64 + cc] + c1 * as_[head * 64 + cc + 1];
                dd += c0 * ad_[head * 64 + cc] + c1 * ad_[head * 64 + cc + 1];
            }
            ss += __shfl_xor_sync(0xffffffffu, ss, 1);
            ss += __shfl_xor_sync(0xffffffffu, ss, 2);
            dd += __shfl_xor_sync(0xffffffffu, dd, 1);
            dd += __shfl_xor_sync(0xffffffffu, dd, 2);
            int row = brow + wm * 32 + mt * 16 + (lane >> 2) + p * 8;
            if ((lane & 3) == 0 && row < M) {
                s_[(size_t)row * H + head] = ss;
                d_[(size_t)row * H + head] = dd;
            }
        }
    }
}

// ---------------- BF16x3 tensor GEMM 128x64 (layer 3, H=1) ----------------
#define N64_BUF 7680
#define N64_SMEM ((2 * N64_BUF + 256) * 4)
__global__ void __launch_bounds__(256) gemm_bf16n64(
        const unsigned* __restrict__ Ahi, const unsigned* __restrict__ Alo,
        const unsigned* __restrict__ Bhi, const unsigned* __restrict__ Blo,
        float* __restrict__ C, int M, int KW,
        const float* __restrict__ as_, const float* __restrict__ ad_,
        float* __restrict__ s_, float* __restrict__ d_) {
    extern __shared__ unsigned smemU[];
    unsigned sbase;
    asm("{ .reg .u64 t; cvta.to.shared.u64 t, %1; cvt.u32.u64 %0, t; }"
        : "=r"(sbase) : "l"(smemU));
    int tid = threadIdx.x, lane = tid & 31, warp = tid >> 5;
    int wm = warp & 3, wn = warp >> 2;
    int brow = blockIdx.x * 128;
    float c[2][4][4];
    #pragma unroll
    for (int mt = 0; mt < 2; mt++)
        #pragma unroll
        for (int nt = 0; nt < 4; nt++)
            #pragma unroll
            for (int r = 0; r < 4; r++) c[mt][nt][r] = 0.f;

    const int nch = KW >> 4;
    unsigned aoffw = (unsigned)((wm * 32 + (lane & 7) + ((lane >> 3) & 1) * 8) * CROW
                                + ((lane >> 4) & 1) * 4);
    unsigned boffw = (unsigned)((wn * 32 + (lane & 7) + ((lane >> 4) & 1) * 8) * CROW
                                + ((lane >> 3) & 1) * 4);

    auto issue = [&](int ch, int b) {
        #pragma unroll
        for (int t = 0; t < 6; t++) {
            int segid = tid + t * 256;
            int mtx, row, seg;
            if (segid < 1024) { mtx = segid >> 9; row = (segid >> 2) & 127; seg = segid & 3; }
            else { int bi = segid - 1024; mtx = 2 + (bi >> 8); row = (bi >> 2) & 63; seg = bi & 3; }
            const unsigned* gp;
            bool valid = true;
            int grow;
            unsigned dstoff;
            if (mtx == 0)      { gp = Ahi; grow = brow + row; valid = grow < M; dstoff = row * CROW + seg * 4; }
            else if (mtx == 1) { gp = Alo; grow = brow + row; valid = grow < M; dstoff = 2560 + row * CROW + seg * 4; }
            else if (mtx == 2) { gp = Bhi; grow = row; dstoff = 5120 + row * CROW + seg * 4; }
            else               { gp = Blo; grow = row; dstoff = 6400 + row * CROW + seg * 4; }
            unsigned dst = sbase + (unsigned)(b * N64_BUF + dstoff) * 4u;
            cpasync16(dst, gp + (size_t)grow * KW + ch * 16 + seg * 4, valid);
        }
        CP_COMMIT();
    };

    issue(0, 0);

    for (int ch = 0; ch < nch; ch++) {
        int b = ch & 1;
        if (ch + 1 < nch) {
            issue(ch + 1, b ^ 1);
            asm volatile("cp.async.wait_group 1;");
        } else {
            asm volatile("cp.async.wait_group 0;");
        }
        __syncthreads();
        unsigned bufb = sbase + (unsigned)(b * N64_BUF) * 4u;
        unsigned baseAhi = bufb + aoffw * 4u;
        unsigned baseAlo = bufb + (2560u + aoffw) * 4u;
        unsigned baseBhi = bufb + (5120u + boffw) * 4u;
        unsigned baseBlo = bufb + (6400u + boffw) * 4u;

        #pragma unroll
        for (int kg = 0; kg < 2; kg++) {
            unsigned kb = (unsigned)(kg * 8) * 4u;
            unsigned ah[2][4], al[2][4];
            LDM4(ah[0], baseAhi + kb);
            LDM4(ah[1], baseAhi + 16 * CROW * 4 + kb);
            LDM4(al[0], baseAlo + kb);
            LDM4(al[1], baseAlo + 16 * CROW * 4 + kb);
            #pragma unroll
            for (int pp = 0; pp < 2; pp++) {
                unsigned th[4], tl[4];
                LDM4(th, baseBhi + pp * 16 * CROW * 4 + kb);
                LDM4(tl, baseBlo + pp * 16 * CROW * 4 + kb);
                unsigned b0h[2] = {th[0], th[1]}, b1h[2] = {th[2], th[3]};
                unsigned b0l[2] = {tl[0], tl[1]}, b1l[2] = {tl[2], tl[3]};
                int n0 = pp * 2, n1 = pp * 2 + 1;
                MMA_BF16(c[0][n0], ah[0], b0h);
                MMA_BF16(c[1][n0], ah[1], b0h);
                MMA_BF16(c[0][n1], ah[0], b1h);
                MMA_BF16(c[1][n1], ah[1], b1h);
                MMA_BF16(c[0][n0], ah[0], b0l);
                MMA_BF16(c[1][n0], ah[1], b0l);
                MMA_BF16(c[0][n1], ah[0], b1l);
                MMA_BF16(c[1][n1], ah[1], b1l);
                MMA_BF16(c[0][n0], al[0], b0h);
                MMA_BF16(c[1][n0], al[1], b0h);
                MMA_BF16(c[0][n1], al[0], b1h);
                MMA_BF16(c[1][n1], al[1], b1h);
            }
        }
        __syncthreads();
    }

    #pragma unroll
    for (int mt = 0; mt < 2; mt++) {
        #pragma unroll
        for (int nt = 0; nt < 4; nt++) {
            int row = brow + wm * 32 + mt * 16 + (lane >> 2);
            int col = wn * 32 + nt * 8 + 2 * (lane & 3);
            if (row < M)
                *(float2*)&C[(size_t)row * 64 + col] = make_float2(c[mt][nt][0], c[mt][nt][1]);
            if (row + 8 < M)
                *(float2*)&C[(size_t)(row + 8) * 64 + col] = make_float2(c[mt][nt][2], c[mt][nt][3]);
        }
    }

    float* sred = (float*)(smemU + 2 * N64_BUF);
    float* dred = sred + 128;
    if (tid < 128) { sred[tid] = 0.f; dred[tid] = 0.f; }
    __syncthreads();
    #pragma unroll
    for (int mt = 0; mt < 2; mt++) {
        #pragma unroll
        for (int p = 0; p < 2; p++) {
            float ss = 0.f, dd = 0.f;
            #pragma unroll
            for (int nt = 0; nt < 4; nt++) {
                int cc = wn * 32 + nt * 8 + 2 * (lane & 3);
                float c0 = c[mt][nt][p * 2], c1 = c[mt][nt][p * 2 + 1];
                ss += c0 * as_[cc] + c1 * as_[cc + 1];
                dd += c0 * ad_[cc] + c1 * ad_[cc + 1];
            }
            ss += __shfl_xor_sync(0xffffffffu, ss, 1);
            ss += __shfl_xor_sync(0xffffffffu, ss, 2);
            dd += __shfl_xor_sync(0xffffffffu, dd, 1);
            dd += __shfl_xor_sync(0xffffffffu, dd, 2);
            if ((lane & 3) == 0) {
                int rl = wm * 32 + mt * 16 + (lane >> 2) + p * 8;
                atomicAdd(&sred[rl], ss);
                atomicAdd(&dred[rl], dd);
            }
        }
    }
    __syncthreads();
    if (tid < 128) {
        int gm = brow + tid;
        if (gm < M) {
            s_[gm] = sred[tid];
            d_[gm] = dred[tid];
        }
    }
}

// ---------------- fused GAT layer, H=4 (optional bf16-split output) ----------
__global__ void gat_fused4(const int* __restrict__ rowptr, const int* __restrict__ ecol,
                           const float* __restrict__ s_, const float* __restrict__ d_,
                           const float* __restrict__ h, const float* __restrict__ bias,
                           const float* __restrict__ lw, const float* __restrict__ lb,
                           float* __restrict__ outp, unsigned* __restrict__ xhi,
                           unsigned* __restrict__ xlo, int n, int do_elu, int splitOut) {
    int warp = (blockIdx.x * blockDim.x + threadIdx.x) >> 5;
    int lane = threadIdx.x & 31;
    if (warp >= n) return;
    int node = warp;
    int start = rowptr[node], end = rowptr[node + 1];

    float4 dv4 = ((const float4*)d_)[node];
    float dsel[4] = {dv4.x, dv4.y, dv4.z, dv4.w};
    float4 sv4 = ((const float4*)s_)[node];
    float selfv[4] = {leaky(sv4.x + dsel[0]), leaky(sv4.y + dsel[1]),
                      leaky(sv4.z + dsel[2]), leaky(sv4.w + dsel[3])};

    float m[4], s[4];
    #pragma unroll
    for (int q = 0; q < 4; q++) {
        m[q] = (lane == 0) ? selfv[q] : -3e38f;
        s[q] = (lane == 0) ? 1.f : 0.f;
    }
    for (int e = start + lane; e < end; e += 32) {
        int src = ecol[e];
        float4 sv = ((const float4*)s_)[src];
        float v[4] = {leaky(sv.x + dsel[0]), leaky(sv.y + dsel[1]),
                      leaky(sv.z + dsel[2]), leaky(sv.w + dsel[3])};
        #pragma unroll
        for (int q = 0; q < 4; q++) {
            float nm = fmaxf(m[q], v[q]);
            s[q] = s[q] * expf(m[q] - nm) + expf(v[q] - nm);
            m[q] = nm;
        }
    }
    #pragma unroll
    for (int o = 16; o > 0; o >>= 1) {
        #pragma unroll
        for (int q = 0; q < 4; q++) {
            float om = __shfl_xor_sync(0xffffffffu, m[q], o);
            float os = __shfl_xor_sync(0xffffffffu, s[q], o);
            float nm = fmaxf(m[q], om);
            s[q] = s[q] * expf(m[q] - nm) + os * expf(om - nm);
            m[q] = nm;
        }
    }
    float inv[4], aself[4];
    #pragma unroll
    for (int q = 0; q < 4; q++) {
        inv[q] = 1.f / (s[q] + 1e-16f);
        aself[q] = expf(selfv[q] - m[q]) * inv[q];
    }

    int hl = lane & 3;
    float d_hl = (hl == 0) ? dsel[0] : (hl == 1) ? dsel[1] : (hl == 2) ? dsel[2] : dsel[3];
    float m_hl = (hl == 0) ? m[0]    : (hl == 1) ? m[1]    : (hl == 2) ? m[2]    : m[3];
    float i_hl = (hl == 0) ? inv[0]  : (hl == 1) ? inv[1]  : (hl == 2) ? inv[2]  : inv[3];
    int hA = lane >> 4;
    float asA = hA ? aself[1] : aself[0];
    float asB = hA ? aself[3] : aself[2];

    const float4* hps4 = (const float4*)(h + (size_t)node * 256);
    float4 acc0 = f4scale(hps4[lane], asA);
    float4 acc1 = f4scale(hps4[lane + 32], asB);

    for (int e0 = start; e0 < end; e0 += 8) {
        int me = e0 + (lane >> 2);
        float alpha = 0.f; int msrc = 0;
        if (me < end) {
            msrc = ecol[me];
            float v = leaky(s_[(size_t)msrc * 4 + hl] + d_hl);
            alpha = expf(v - m_hl) * i_hl;
        }
        int cnt = end - e0; if (cnt > 8) cnt = 8;
        for (int j0 = 0; j0 < cnt; j0 += 4) {
            int jn = cnt - j0; if (jn > 4) jn = 4;
            float4 pa[4], pb[4];
            float a0[4], a1[4];
            #pragma unroll
            for (int j = 0; j < 4; j++) {
                int src = __shfl_sync(0xffffffffu, msrc, (j0 + j) * 4);
                a0[j] = __shfl_sync(0xffffffffu, alpha, (j0 + j) * 4 + hA);
                a1[j] = __shfl_sync(0xffffffffu, alpha, (j0 + j) * 4 + 2 + hA);
                if (j < jn) {
                    const float4* hp4 = (const float4*)(h + (size_t)src * 256);
                    pa[j] = hp4[lane];
                    pb[j] = hp4[lane + 32];
                }
            }
            #pragma unroll
            for (int j = 0; j < 4; j++) {
                if (j < jn) {
                    acc0 = f4fma(pa[j], a0[j], acc0);
                    acc1 = f4fma(pb[j], a1[j], acc1);
                }
            }
        }
    }

    const float4* b4 = (const float4*)bias;
    const float4* lw4 = (const float4*)lw;
    const float4* lb4 = (const float4*)lb;
    float4 v0 = f4add(acc0, b4[lane]);
    float4 v1 = f4add(acc1, b4[lane + 32]);
    if (do_elu) {
        v0.x = v0.x > 0.f ? v0.x : expf(v0.x) - 1.f;
        v0.y = v0.y > 0.f ? v0.y : expf(v0.y) - 1.f;
        v0.z = v0.z > 0.f ? v0.z : expf(v0.z) - 1.f;
        v0.w = v0.w > 0.f ? v0.w : expf(v0.w) - 1.f;
        v1.x = v1.x > 0.f ? v1.x : expf(v1.x) - 1.f;
        v1.y = v1.y > 0.f ? v1.y : expf(v1.y) - 1.f;
        v1.z = v1.z > 0.f ? v1.z : expf(v1.z) - 1.f;
        v1.w = v1.w > 0.f ? v1.w : expf(v1.w) - 1.f;
    }
    float ssum = v0.x + v0.y + v0.z + v0.w + v1.x + v1.y + v1.z + v1.w;
    ssum = warpSum(ssum);
    float mu = ssum * (1.f / 256.f);
    float t, vs = 0.f;
    t = v0.x - mu; vs += t * t; t = v0.y - mu; vs += t * t;
    t = v0.z - mu; vs += t * t; t = v0.w - mu; vs += t * t;
    t = v1.x - mu; vs += t * t; t = v1.y - mu; vs += t * t;
    t = v1.z - mu; vs += t * t; t = v1.w - mu; vs += t * t;
    vs = warpSum(vs);
    float rs = rsqrtf(vs * (1.f / 256.f) + 1e-5f);
    float4 w0 = lw4[lane], w1 = lw4[lane + 32];
    float4 c0 = lb4[lane], c1 = lb4[lane + 32];
    float4 o0 = make_float4((v0.x - mu) * rs * w0.x + c0.x, (v0.y - mu) * rs * w0.y + c0.y,
                            (v0.z - mu) * rs * w0.z + c0.z, (v0.w - mu) * rs * w0.w + c0.w);
    float4 o1 = make_float4((v1.x - mu) * rs * w1.x + c1.x, (v1.y - mu) * rs * w1.y + c1.y,
                            (v1.z - mu) * rs * w1.z + c1.z, (v1.w - mu) * rs * w1.w + c1.w);
    float4* out4 = (float4*)(outp + (size_t)node * 256);
    out4[lane] = o0;
    out4[lane + 32] = o1;

    if (splitOut) {
        unsigned* xh = xhi + (size_t)node * 128;
        unsigned* xl = xlo + (size_t)node * 128;
        *(uint2*)&xh[lane * 2] = make_uint2(packbf(o0.x, o0.y), packbf(o0.z, o0.w));
        *(uint2*)&xh[64 + lane * 2] = make_uint2(packbf(o1.x, o1.y), packbf(o1.z, o1.w));
        *(uint2*)&xl[lane * 2] = make_uint2(
            packbf(o0.x - bfr(o0.x), o0.y - bfr(o0.y)),
            packbf(o0.z - bfr(o0.z), o0.w - bfr(o0.w)));
        *(uint2*)&xl[64 + lane * 2] = make_uint2(
            packbf(o1.x - bfr(o1.x), o1.y - bfr(o1.y)),
            packbf(o1.z - bfr(o1.z), o1.w - bfr(o1.w)));
    }
}

// ---------------- fused GAT layer, H=1 (D=64) ----------
__global__ void gat_fused1(const int* __restrict__ rowptr, const int* __restrict__ ecol,
                           const float* __restrict__ s_, const float* __restrict__ d_,
                           const float* __restrict__ h, const float* __restrict__ bias,
                           const float* __restrict__ lw, const float* __restrict__ lb,
                           float* __restrict__ outp, int n, int do_elu) {
    int warp = (blockIdx.x * blockDim.x + threadIdx.x) >> 5;
    int lane = threadIdx.x & 31;
    if (warp >= n) return;
    int node = warp;
    int start = rowptr[node], end = rowptr[node + 1];

    float dsel = d_[node];
    float selfv = leaky(s_[node] + dsel);
    float m = (lane == 0) ? selfv : -3e38f;
    float s = (lane == 0) ? 1.f : 0.f;
    for (int e = start + lane; e < end; e += 32) {
        float v = leaky(s_[ecol[e]] + dsel);
        float nm = fmaxf(m, v);
        s = s * expf(m - nm) + expf(v - nm);
        m = nm;
    }
    #pragma unroll
    for (int o = 16; o > 0; o >>= 1) {
        float om = __shfl_xor_sync(0xffffffffu, m, o);
        float os = __shfl_xor_sync(0xffffffffu, s, o);
        float nm = fmaxf(m, om);
        s = s * expf(m - nm) + os * expf(om - nm);
        m = nm;
    }
    float inv = 1.f / (s + 1e-16f);
    float aself = expf(selfv - m) * inv;

    int half = lane >> 4, f = lane & 15;
    const float4* hps4 = (const float4*)(h + (size_t)node * 64);
    float4 acc = (half == 0) ? f4scale(hps4[f], aself) : make_float4(0.f, 0.f, 0.f, 0.f);

    for (int e0 = start; e0 < end; e0 += 8) {
        int me = e0 + lane;
        float alpha = 0.f; int msrc = 0;
        if (lane < 8 && me < end) {
            msrc = ecol[me];
            alpha = expf(leaky(s_[msrc] + dsel) - m) * inv;
        }
        int cnt = end - e0; if (cnt > 8) cnt = 8;
        for (int j = 0; j < cnt; j += 2) {
            int eidx = j + half;
            int src = __shfl_sync(0xffffffffu, msrc, eidx);
            float al = __shfl_sync(0xffffffffu, alpha, eidx);
            if (eidx < cnt) {
                const float4* hp4 = (const float4*)(h + (size_t)src * 64);
                acc = f4fma(hp4[f], al, acc);
            }
        }
    }
    acc.x += __shfl_xor_sync(0xffffffffu, acc.x, 16);
    acc.y += __shfl_xor_sync(0xffffffffu, acc.y, 16);
    acc.z += __shfl_xor_sync(0xffffffffu, acc.z, 16);
    acc.w += __shfl_xor_sync(0xffffffffu, acc.w, 16);

    const float4* b4 = (const float4*)bias;
    const float4* lw4 = (const float4*)lw;
    const float4* lb4 = (const float4*)lb;
    float4 v = f4add(acc, b4[f]);
    if (do_elu) {
        v.x = v.x > 0.f ? v.x : expf(v.x) - 1.f;
        v.y = v.y > 0.f ? v.y : expf(v.y) - 1.f;
        v.z = v.z > 0.f ? v.z : expf(v.z) - 1.f;
        v.w = v.w > 0.f ? v.w : expf(v.w) - 1.f;
    }
    float ssum = warpSum(v.x + v.y + v.z + v.w);
    float mu = ssum * (1.f / 128.f);
    float t, vs = 0.f;
    t = v.x - mu; vs += t * t; t = v.y - mu; vs += t * t;
    t = v.z - mu; vs += t * t; t = v.w - mu; vs += t * t;
    vs = warpSum(vs);
    float rs = rsqrtf(vs * (1.f / 128.f) + 1e-5f);
    if (half == 0) {
        float4 w = lw4[f], c = lb4[f];
        float4* out4 = (float4*)(outp + (size_t)node * 64);
        out4[f] = make_float4((v.x - mu) * rs * w.x + c.x, (v.y - mu) * rs * w.y + c.y,
                              (v.z - mu) * rs * w.z + c.z, (v.w - mu) * rs * w.w + c.w);
    }
}

// ---------------- final MLP head (FFMA2, paired outputs j and j+32) ----------------
__global__ void head_kernel(const float* __restrict__ h3, const int* __restrict__ role,
                            const float* __restrict__ rc, const float* __restrict__ p1w,
                            const float* __restrict__ p2w, const float* __restrict__ p2b,
                            float* __restrict__ z, int n) {
    extern __shared__ float sm[];
    float* sp1p = sm;
    float* sp2p = sp1p + 4096;
    float* sz   = sp2p + 4096;
    float* sz1  = sz + 512;
    int tid = threadIdx.x;
    for (int i = tid; i < 4096; i += 256) {
        int k = i >> 6, q = i & 63;
        int j = (q >> 1) + (q & 1) * 32;
        sp1p[k * 64 + q] = p1w[j * 128 + k];
        sp2p[k * 64 + q] = p2w[j * 64 + k];
    }
    __syncthreads();
    int g = tid >> 5, jj = tid & 31;
    float b2a = p2b[jj], b2b = p2b[jj + 32];
    for (int it = 0; it < 8; it++) {
        int node = blockIdx.x * 64 + it * 8 + g;
        bool valid = node < n;
        float rca = 0.f, rcb = 0.f;
        if (valid) {
            sz[g * 64 + jj] = h3[(size_t)node * 64 + jj];
            sz[g * 64 + jj + 32] = h3[(size_t)node * 64 + jj + 32];
            int r = role[node];
            rca = rc[r * 64 + jj];
            rcb = rc[r * 64 + jj + 32];
        }
        __syncthreads();
        unsigned long long acc2;
        PACK2(acc2, rca, rcb);
        #pragma unroll 8
        for (int k = 0; k < 64; k++) {
            unsigned long long a2 = *(unsigned long long*)&sp1p[k * 64 + jj * 2];
            unsigned long long bb; DUP2(bb, sz[g * 64 + k]);
            FMA2(acc2, a2, bb);
        }
        float oa, ob;
        UNPACK2(oa, ob, acc2);
        sz1[g * 64 + jj] = fmaxf(oa, 0.f);
        sz1[g * 64 + jj + 32] = fmaxf(ob, 0.f);
        __syncthreads();
        PACK2(acc2, b2a, b2b);
        #pragma unroll 8
        for (int k = 0; k < 64; k++) {
            unsigned long long a2 = *(unsigned long long*)&sp2p[k * 64 + jj * 2];
            unsigned long long bb; DUP2(bb, sz1[g * 64 + k]);
            FMA2(acc2, a2, bb);
        }
        UNPACK2(oa, ob, acc2);
        if (valid) {
            z[(size_t)node * 64 + jj] = oa;
            z[(size_t)node * 64 + jj + 32] = ob;
        }
    }
}

// ---------------- host orchestration ----------------
extern "C" void kernel_launch(void* const* d_in, const int* in_sizes, int n_in,
                              void* d_out, int out_size) {
    const float* x   = (const float*)d_in[0];
    const void*  ei  = d_in[1];
    const void*  rid = d_in[2];
    const float* W1  = (const float*)d_in[3];
    const float* a1s = (const float*)d_in[4];
    const float* a1d = (const float*)d_in[5];
    const float* b1  = (const float*)d_in[6];
    const float* W2  = (const float*)d_in[7];
    const float* a2s = (const float*)d_in[8];
    const float* a2d = (const float*)d_in[9];
    const float* b2  = (const float*)d_in[10];
    const float* W3  = (const float*)d_in[11];
    const float* a3s = (const float*)d_in[12];
    const float* a3d = (const float*)d_in[13];
    const float* b3  = (const float*)d_in[14];
    const float* ln1w = (const float*)d_in[15];
    const float* ln1b = (const float*)d_in[16];
    const float* ln2w = (const float*)d_in[17];
    const float* ln2b = (const float*)d_in[18];
    const float* ln3w = (const float*)d_in[19];
    const float* ln3b = (const float*)d_in[20];
    const float* rt   = (const float*)d_in[21];
    const float* p1w  = (const float*)d_in[22];
    const float* p1b  = (const float*)d_in[23];
    const float* p2w  = (const float*)d_in[24];
    const float* p2b  = (const float*)d_in[25];
    float* z = (float*)d_out;

    float *hbuf, *xbuf, *ybuf, *sp, *dp, *rcp;
    unsigned *xhip, *xlop, *whip, *wlop;
    int *srcp, *dstp, *ecolp, *rowp, *degp, *curp, *bsump, *rolep, *flagp;
    cudaGetSymbolAddress((void**)&hbuf, g_h);
    cudaGetSymbolAddress((void**)&xbuf, g_x);
    cudaGetSymbolAddress((void**)&ybuf, g_y);
    cudaGetSymbolAddress((void**)&sp, g_s);
    cudaGetSymbolAddress((void**)&dp, g_d);
    cudaGetSymbolAddress((void**)&rcp, g_rc);
    cudaGetSymbolAddress((void**)&xhip, g_xhi);
    cudaGetSymbolAddress((void**)&xlop, g_xlo);
    cudaGetSymbolAddress((void**)&whip, g_whi);
    cudaGetSymbolAddress((void**)&wlop, g_wlo);
    cudaGetSymbolAddress((void**)&srcp, g_src);
    cudaGetSymbolAddress((void**)&dstp, g_dst);
    cudaGetSymbolAddress((void**)&ecolp, g_ecol);
    cudaGetSymbolAddress((void**)&rowp, g_rowptr);
    cudaGetSymbolAddress((void**)&degp, g_deg);
    cudaGetSymbolAddress((void**)&curp, g_cursor);
    cudaGetSymbolAddress((void**)&bsump, g_bsum);
    cudaGetSymbolAddress((void**)&rolep, g_role);
    cudaGetSymbolAddress((void**)&flagp, g_is64);

    const int n = NN, E = EE;
    const int nb = (n + 1023) / 1024;

    dim3 gg(2, (n + 127) / 128);
    int g3blocks = (n + 127) / 128;
    int fusedBlocks = (n * 32 + 255) / 256;

    cudaFuncSetAttribute(gemm_bf16, cudaFuncAttributeMaxDynamicSharedMemorySize,
                         GEMM_BF16_SMEM);
    cudaFuncSetAttribute(gemm_bf16n64, cudaFuncAttributeMaxDynamicSharedMemorySize,
                         N64_SMEM);

    // conversions first (no deps) so gemm1 stays in the ncu capture slot
    split_kernel<<<(n * 64 / 4 + 255) / 256, 256>>>(x, xhip, xlop, n * 64 / 4);
    split_kernel<<<16, 256>>>(W1, whip, wlop, 256 * 64 / 4);
    detect_kernel<<<1, 32>>>((const unsigned int*)ei, flagp);
    cudaMemsetAsync(degp, 0, n * sizeof(int));
    gemm_bf16<<<gg, 256, GEMM_BF16_SMEM>>>(xhip, xlop, whip, wlop, hbuf, n, 32,
                                           a1s, a1d, sp, dp, 4);
    prep_kernel<<<(E + 255) / 256, 256>>>(ei, rid, srcp, dstp, degp, rolep, flagp, E, n);
    scan_reduce_kernel<<<nb, 1024>>>(degp, bsump, n);
    scan_final_kernel<<<nb, 1024>>>(degp, bsump, rowp, curp, n);
    scatter_kernel<<<(E + 255) / 256, 256>>>(srcp, dstp, curp, ecolp, E);
    role_prep_kernel<<<1, 128>>>(rt, p1w, p1b, rcp);

    // layer 1 gather (emits bf16-split output for layer-2 GEMM A)
    gat_fused4<<<fusedBlocks, 256>>>(rowp, ecolp, sp, dp, hbuf, b1, ln1w, ln1b,
                                     xbuf, xhip, xlop, n, 1, 1);

    // layer 2 (gather also emits bf16-split for layer-3 GEMM A)
    split_kernel<<<64, 256>>>(W2, whip, wlop, 256 * 256 / 4);
    gemm_bf16<<<gg, 256, GEMM_BF16_SMEM>>>(xhip, xlop, whip, wlop, hbuf, n, 128,
                                           a2s, a2d, sp, dp, 4);
    gat_fused4<<<fusedBlocks, 256>>>(rowp, ecolp, sp, dp, hbuf, b2, ln2w, ln2b,
                                     xbuf, xhip, xlop, n, 1, 1);

    // layer 3 (bf16 tensor path; W buffers reused after gemm2 completes)
    split_kernel<<<16, 256>>>(W3, whip, wlop, 64 * 256 / 4);
    gemm_bf16n64<<<g3blocks, 256, N64_SMEM>>>(xhip, xlop, whip, wlop, hbuf, n, 128,
                                              a3s, a3d, sp, dp);
    gat_fused1<<<fusedBlocks, 256>>>(rowp, ecolp, sp, dp, hbuf, b3, ln3w, ln3b, ybuf, n, 0);

    // final MLP head
    size_t smem = (4096 + 4096 + 512 + 512) * sizeof(float);
    cudaFuncSetAttribute(head_kernel, cudaFuncAttributeMaxDynamicSharedMemorySize, (int)smem);
    head_kernel<<<(n + 63) / 64, 256, smem>>>(ybuf, rolep, rcp, p1w, p2w, p2b, z, n);
}